// round 4
// baseline (speedup 1.0000x reference)
#include <cuda_runtime.h>
#include <cuda_fp16.h>
#include <cstdint>
#include <cstddef>

#define B_ 2
#define T_ 4096
#define C_ 768
#define H_ 12
#define D_ 64
#define M_ (B_*T_)          // 8192
#define N_QKV (3*C_)        // 2304
// softmax scale folded with log2(e) so we can use ex2
#define QSCALE (0.125f * 1.4426950408889634f)

// Scratch (allocation-free requirement -> __device__ globals)
__device__ float g_qkv[(size_t)M_ * N_QKV];   // [B*T, 3C]
__device__ float g_attn[(size_t)M_ * C_];     // [B*T, C]

// ---------------------------------------------------------------------------
// Helpers
// ---------------------------------------------------------------------------
__device__ __forceinline__ float to_tf32(float x) {
    uint32_t u;
    asm("cvt.rna.tf32.f32 %0, %1;" : "=r"(u) : "f"(x));
    return __uint_as_float(u);
}
__device__ __forceinline__ uint32_t tf32bits(float x) {
    uint32_t u;
    asm("cvt.rna.tf32.f32 %0, %1;" : "=r"(u) : "f"(x));
    return u;
}

__device__ __forceinline__ void mma_tf32(float* c, const uint32_t* a,
                                         uint32_t b0, uint32_t b1) {
    asm volatile(
        "mma.sync.aligned.m16n8k8.row.col.f32.tf32.tf32.f32 "
        "{%0,%1,%2,%3},{%4,%5,%6,%7},{%8,%9},{%0,%1,%2,%3};"
        : "+f"(c[0]), "+f"(c[1]), "+f"(c[2]), "+f"(c[3])
        : "r"(a[0]), "r"(a[1]), "r"(a[2]), "r"(a[3]), "r"(b0), "r"(b1));
}

__device__ __forceinline__ void mma_f16(float* c, const uint32_t* a,
                                        uint32_t b0, uint32_t b1) {
    asm volatile(
        "mma.sync.aligned.m16n8k16.row.col.f32.f16.f16.f32 "
        "{%0,%1,%2,%3},{%4,%5,%6,%7},{%8,%9},{%0,%1,%2,%3};"
        : "+f"(c[0]), "+f"(c[1]), "+f"(c[2]), "+f"(c[3])
        : "r"(a[0]), "r"(a[1]), "r"(a[2]), "r"(a[3]), "r"(b0), "r"(b1));
}

__device__ __forceinline__ uint32_t pack_h2(float lo, float hi) {
    __half2 h = __floats2half2_rn(lo, hi);
    return *reinterpret_cast<uint32_t*>(&h);
}

__device__ __forceinline__ float fast_exp2(float x) {
    float r;
    asm("ex2.approx.ftz.f32 %0, %1;" : "=f"(r) : "f"(x));
    return r;
}

__device__ __forceinline__ uint32_t smem_u32(const void* p) {
    return (uint32_t)__cvta_generic_to_shared(p);
}
__device__ __forceinline__ void cp_async16(uint32_t dst, const void* src) {
    asm volatile("cp.async.cg.shared.global [%0], [%1], 16;" :: "r"(dst), "l"(src));
}
__device__ __forceinline__ void cp_commit() {
    asm volatile("cp.async.commit_group;");
}

// ---------------------------------------------------------------------------
// tf32 tensor-core GEMM with bias: C[M,N] = A[M,K] @ B[K,N] + bias[N]
// BM=BN=128, BK=16, 256 threads (8 warps), warp tile 64x32 (m16n8k8).
// 3-stage cp.async pipeline; tf32 conversion at fragment load.
// Dynamic smem: 3 * (128*20 + 16*136) * 4 = 56832 bytes.
// ---------------------------------------------------------------------------
#define GA_ST 2560          // 128*20 floats per A stage
#define GB_ST 2176          // 16*136 floats per B stage
#define GEMM_SMEM ((3*(GA_ST+GB_ST))*4)

__global__ void __launch_bounds__(256)
gemm_tf32_kernel(const float* __restrict__ A, const float* __restrict__ B,
                 const float* __restrict__ bias, float* __restrict__ C,
                 int M, int N, int K)
{
    extern __shared__ float sm[];
    float* As = sm;                 // [3][128][20]
    float* Bs = sm + 3 * GA_ST;     // [3][16][136]

    const int tid = threadIdx.x;
    const int wid = tid >> 5;
    const int lane = tid & 31;
    const int g = lane >> 2;
    const int t4 = lane & 3;
    const int wm = wid >> 2;
    const int wn = wid & 3;
    const int bx = blockIdx.x, by = blockIdx.y;

    const int arow = tid >> 1;            // 0..127
    const int acol = (tid & 1) * 8;       // 0 or 8
    const int brow = tid >> 4;            // 0..15
    const int bcol = (tid & 15) * 8;      // 0..120

    const float* aG = A + (size_t)(by * 128 + arow) * K + acol;
    const float* bG = B + (size_t)brow * N + bx * 128 + bcol;

    const int steps = K >> 4;

    auto load_stage = [&](int s) {
        const int st = s % 3;
        const int k0 = s << 4;
        uint32_t ad = smem_u32(&As[st * GA_ST + arow * 20 + acol]);
        cp_async16(ad,      aG + k0);
        cp_async16(ad + 16, aG + k0 + 4);
        uint32_t bd = smem_u32(&Bs[st * GB_ST + brow * 136 + bcol]);
        cp_async16(bd,      bG + (size_t)k0 * N);
        cp_async16(bd + 16, bG + (size_t)k0 * N + 4);
        cp_commit();
    };

    load_stage(0);
    load_stage(1);

    float acc[4][4][4];
    #pragma unroll
    for (int mt = 0; mt < 4; mt++)
        #pragma unroll
        for (int nt = 0; nt < 4; nt++)
            #pragma unroll
            for (int i = 0; i < 4; i++) acc[mt][nt][i] = 0.f;

    for (int s = 0; s < steps; s++) {
        if (s + 1 < steps) { asm volatile("cp.async.wait_group 1;"); }
        else               { asm volatile("cp.async.wait_group 0;"); }
        __syncthreads();
        if (s + 2 < steps) load_stage(s + 2);

        const float* Ast = As + (s % 3) * GA_ST;
        const float* Bst = Bs + (s % 3) * GB_ST;

        #pragma unroll
        for (int kk = 0; kk < 16; kk += 8) {
            uint32_t afr[4][4], bfr[4][2];
            #pragma unroll
            for (int mt = 0; mt < 4; mt++) {
                const int row = wm * 64 + mt * 16;
                afr[mt][0] = tf32bits(Ast[(row + g) * 20 + kk + t4]);
                afr[mt][1] = tf32bits(Ast[(row + g + 8) * 20 + kk + t4]);
                afr[mt][2] = tf32bits(Ast[(row + g) * 20 + kk + t4 + 4]);
                afr[mt][3] = tf32bits(Ast[(row + g + 8) * 20 + kk + t4 + 4]);
            }
            #pragma unroll
            for (int nt = 0; nt < 4; nt++) {
                const int col = wn * 32 + nt * 8 + g;
                bfr[nt][0] = tf32bits(Bst[(kk + t4) * 136 + col]);
                bfr[nt][1] = tf32bits(Bst[(kk + t4 + 4) * 136 + col]);
            }
            #pragma unroll
            for (int mt = 0; mt < 4; mt++)
                #pragma unroll
                for (int nt = 0; nt < 4; nt++)
                    mma_tf32(acc[mt][nt], afr[mt], bfr[nt][0], bfr[nt][1]);
        }
    }

    // Epilogue: bias + store (float2 pairs, C-layout)
    #pragma unroll
    for (int nt = 0; nt < 4; nt++) {
        const int col = bx * 128 + wn * 32 + nt * 8 + 2 * t4;
        const float b0 = bias[col], b1 = bias[col + 1];
        #pragma unroll
        for (int mt = 0; mt < 4; mt++) {
            const int row = by * 128 + wm * 64 + mt * 16 + g;
            float2 o0 = make_float2(acc[mt][nt][0] + b0, acc[mt][nt][1] + b1);
            float2 o1 = make_float2(acc[mt][nt][2] + b0, acc[mt][nt][3] + b1);
            *reinterpret_cast<float2*>(C + (size_t)row * N + col) = o0;
            *reinterpret_cast<float2*>(C + (size_t)(row + 8) * N + col) = o1;
        }
    }
}

// ---------------------------------------------------------------------------
// Flash attention (causal), tensor cores, cp.async double-buffered K/V.
// grid = (T/128, B*H), 256 threads (8 warps). Br=128, Bc=64, D=64.
// Warp w owns query rows [w*16, w*16+16). K,V staged raw fp32 in smem;
// K frags: LDS + cvt.rna.tf32; V frags: 2x LDS + half2 pack.
// Dynamic smem: 2 stages * 2 tensors * 64*68 floats = 69632 bytes.
// ---------------------------------------------------------------------------
#define AT_STAGE (2 * 64 * 68)        // floats per stage (K then V)
#define ATTN_SMEM (2 * AT_STAGE * 4)

__global__ void __launch_bounds__(256)
attn_mma_kernel(const float* __restrict__ qkv, float* __restrict__ out)
{
    extern __shared__ float sm[];

    const int bh = blockIdx.y;
    const int b = bh / H_;
    const int h = bh % H_;
    const int qtile = gridDim.x - 1 - blockIdx.x;   // big tiles first
    const int tid = threadIdx.x;
    const int w = tid >> 5;
    const int lane = tid & 31;
    const int g = lane >> 2;
    const int t4 = lane & 3;

    // ---- stage Q tile (pre-scaled tf32) through stage-1 buffer ----
    float* Qs = sm + AT_STAGE;     // [128][68], exactly fills stage 1
    #pragma unroll
    for (int i = 0; i < 8; i++) {
        const int c = tid + i * 256;          // 0..2047
        const int r = c >> 4;
        const int col = (c & 15) * 4;
        float4 v = *reinterpret_cast<const float4*>(
            qkv + (size_t)(b * T_ + qtile * 128 + r) * N_QKV + h * D_ + col);
        Qs[r * 68 + col + 0] = to_tf32(v.x * QSCALE);
        Qs[r * 68 + col + 1] = to_tf32(v.y * QSCALE);
        Qs[r * 68 + col + 2] = to_tf32(v.z * QSCALE);
        Qs[r * 68 + col + 3] = to_tf32(v.w * QSCALE);
    }
    __syncthreads();

    uint32_t Qa[8][4];
    #pragma unroll
    for (int kc = 0; kc < 8; kc++) {
        const int row = w * 16;
        Qa[kc][0] = __float_as_uint(Qs[(row + g) * 68 + kc * 8 + t4]);
        Qa[kc][1] = __float_as_uint(Qs[(row + g + 8) * 68 + kc * 8 + t4]);
        Qa[kc][2] = __float_as_uint(Qs[(row + g) * 68 + kc * 8 + t4 + 4]);
        Qa[kc][3] = __float_as_uint(Qs[(row + g + 8) * 68 + kc * 8 + t4 + 4]);
    }

    const int ntiles = 2 * qtile + 2;

    auto load_kv = [&](int s) {
        const int st = s & 1;
        const int kbase = s * 64;
        float* Kst = sm + st * AT_STAGE;
        float* Vst = Kst + 64 * 68;
        #pragma unroll
        for (int i = 0; i < 4; i++) {
            const int c = tid + i * 256;      // 0..1023
            const int r = c >> 4;
            const int col = (c & 15) * 4;
            const float* src =
                qkv + (size_t)(b * T_ + kbase + r) * N_QKV + h * D_ + col;
            cp_async16(smem_u32(&Kst[r * 68 + col]), src + C_);
            cp_async16(smem_u32(&Vst[r * 68 + col]), src + 2 * C_);
        }
        cp_commit();
    };
    load_kv(0);   // stage 0 untouched by Q staging

    float o[8][4];
    #pragma unroll
    for (int nt = 0; nt < 8; nt++)
        #pragma unroll
        for (int i = 0; i < 4; i++) o[nt][i] = 0.f;
    float m0 = -1e30f, m1 = -1e30f, l0 = 0.f, l1 = 0.f;

    const int q0 = qtile * 128 + w * 16 + g;   // first own query row (second is +8)

    for (int kt = 0; kt < ntiles; kt++) {
        asm volatile("cp.async.wait_group 0;");
        __syncthreads();
        if (kt + 1 < ntiles) load_kv(kt + 1);

        const float* Kr = sm + (kt & 1) * AT_STAGE;
        const float* Vr = Kr + 64 * 68;
        const int kbase = kt * 64;

        // ---- S = Q @ K^T (16x64 per warp) ----
        float s_[8][4];
        #pragma unroll
        for (int nt = 0; nt < 8; nt++)
            #pragma unroll
            for (int i = 0; i < 4; i++) s_[nt][i] = 0.f;
        #pragma unroll
        for (int kc = 0; kc < 8; kc++) {
            #pragma unroll
            for (int nt = 0; nt < 8; nt++) {
                uint32_t kb0 = tf32bits(Kr[(nt * 8 + g) * 68 + kc * 8 + t4]);
                uint32_t kb1 = tf32bits(Kr[(nt * 8 + g) * 68 + kc * 8 + t4 + 4]);
                mma_tf32(s_[nt], Qa[kc], kb0, kb1);
            }
        }

        // ---- causal mask (only tiles overlapping the diagonal) ----
        if (kbase + 63 > q0) {
            #pragma unroll
            for (int nt = 0; nt < 8; nt++) {
                const int c0 = kbase + nt * 8 + 2 * t4;
                if (c0 > q0)         s_[nt][0] = -1e30f;
                if (c0 + 1 > q0)     s_[nt][1] = -1e30f;
                if (c0 > q0 + 8)     s_[nt][2] = -1e30f;
                if (c0 + 1 > q0 + 8) s_[nt][3] = -1e30f;
            }
        }

        // ---- online softmax (base-2) ----
        float mx0 = -1e30f, mx1 = -1e30f;
        #pragma unroll
        for (int nt = 0; nt < 8; nt++) {
            mx0 = fmaxf(mx0, fmaxf(s_[nt][0], s_[nt][1]));
            mx1 = fmaxf(mx1, fmaxf(s_[nt][2], s_[nt][3]));
        }
        mx0 = fmaxf(mx0, __shfl_xor_sync(0xffffffff, mx0, 1));
        mx0 = fmaxf(mx0, __shfl_xor_sync(0xffffffff, mx0, 2));
        mx1 = fmaxf(mx1, __shfl_xor_sync(0xffffffff, mx1, 1));
        mx1 = fmaxf(mx1, __shfl_xor_sync(0xffffffff, mx1, 2));
        const float nm0 = fmaxf(m0, mx0), nm1 = fmaxf(m1, mx1);
        const float sc0 = fast_exp2(m0 - nm0), sc1 = fast_exp2(m1 - nm1);
        m0 = nm0; m1 = nm1;

        float rs0 = 0.f, rs1 = 0.f;
        #pragma unroll
        for (int nt = 0; nt < 8; nt++) {
            s_[nt][0] = fast_exp2(s_[nt][0] - m0); rs0 += s_[nt][0];
            s_[nt][1] = fast_exp2(s_[nt][1] - m0); rs0 += s_[nt][1];
            s_[nt][2] = fast_exp2(s_[nt][2] - m1); rs1 += s_[nt][2];
            s_[nt][3] = fast_exp2(s_[nt][3] - m1); rs1 += s_[nt][3];
        }
        rs0 += __shfl_xor_sync(0xffffffff, rs0, 1);
        rs0 += __shfl_xor_sync(0xffffffff, rs0, 2);
        rs1 += __shfl_xor_sync(0xffffffff, rs1, 1);
        rs1 += __shfl_xor_sync(0xffffffff, rs1, 2);
        l0 = l0 * sc0 + rs0;
        l1 = l1 * sc1 + rs1;

        #pragma unroll
        for (int nt = 0; nt < 8; nt++) {
            o[nt][0] *= sc0; o[nt][1] *= sc0;
            o[nt][2] *= sc1; o[nt][3] *= sc1;
        }

        // ---- O += P @ V  (fp16 mma; V frags packed from raw fp32) ----
        #pragma unroll
        for (int kc = 0; kc < 4; kc++) {
            uint32_t pa[4];
            pa[0] = pack_h2(s_[2 * kc][0], s_[2 * kc][1]);
            pa[1] = pack_h2(s_[2 * kc][2], s_[2 * kc][3]);
            pa[2] = pack_h2(s_[2 * kc + 1][0], s_[2 * kc + 1][1]);
            pa[3] = pack_h2(s_[2 * kc + 1][2], s_[2 * kc + 1][3]);
            const int k0 = kc * 16 + 2 * t4;
            #pragma unroll
            for (int nt = 0; nt < 8; nt++) {
                const int d = nt * 8 + g;
                uint32_t vb0 = pack_h2(Vr[k0 * 68 + d],       Vr[(k0 + 1) * 68 + d]);
                uint32_t vb1 = pack_h2(Vr[(k0 + 8) * 68 + d], Vr[(k0 + 9) * 68 + d]);
                mma_f16(o[nt], pa, vb0, vb1);
            }
        }
    }

    // ---- normalize + store ----
    const float inv0 = 1.f / l0, inv1 = 1.f / l1;
    const size_t row0 = (size_t)(b * T_ + qtile * 128 + w * 16 + g);
    const size_t row1 = row0 + 8;
    #pragma unroll
    for (int nt = 0; nt < 8; nt++) {
        const int col = h * D_ + nt * 8 + 2 * t4;
        float2 v0 = make_float2(o[nt][0] * inv0, o[nt][1] * inv0);
        float2 v1 = make_float2(o[nt][2] * inv1, o[nt][3] * inv1);
        *reinterpret_cast<float2*>(out + row0 * C_ + col) = v0;
        *reinterpret_cast<float2*>(out + row1 * C_ + col) = v1;
    }
}

// ---------------------------------------------------------------------------
// Launch
// ---------------------------------------------------------------------------
extern "C" void kernel_launch(void* const* d_in, const int* in_sizes, int n_in,
                              void* d_out, int out_size)
{
    const float* x    = (const float*)d_in[0];
    const float* Wqkv = (const float*)d_in[1];
    const float* bqkv = (const float*)d_in[2];
    const float* Wout = (const float*)d_in[3];
    const float* bout = (const float*)d_in[4];
    float* out = (float*)d_out;

    float* qkv;  cudaGetSymbolAddress((void**)&qkv,  g_qkv);
    float* attn; cudaGetSymbolAddress((void**)&attn, g_attn);

    cudaFuncSetAttribute(gemm_tf32_kernel,
                         cudaFuncAttributeMaxDynamicSharedMemorySize, GEMM_SMEM);
    cudaFuncSetAttribute(attn_mma_kernel,
                         cudaFuncAttributeMaxDynamicSharedMemorySize, ATTN_SMEM);

    // 1) QKV projection: [8192,768] @ [768,2304] + bias
    {
        dim3 grid(N_QKV / 128, M_ / 128);
        gemm_tf32_kernel<<<grid, 256, GEMM_SMEM>>>(x, Wqkv, bqkv, qkv, M_, N_QKV, C_);
    }
    // 2) Causal attention (flash, tensor cores)
    {
        dim3 grid(T_ / 128, B_ * H_);
        attn_mma_kernel<<<grid, 256, ATTN_SMEM>>>(qkv, attn);
    }
    // 3) Output projection: [8192,768] @ [768,768] + bias
    {
        dim3 grid(C_ / 128, M_ / 128);
        gemm_tf32_kernel<<<grid, 256, GEMM_SMEM>>>(attn, Wout, bout, out, M_, C_, C_);
    }
}

// round 5
// speedup vs baseline: 1.7455x; 1.7455x over previous
#include <cuda_runtime.h>
#include <cuda_fp16.h>
#include <cstdint>
#include <cstddef>

#define B_ 2
#define T_ 4096
#define C_ 768
#define H_ 12
#define D_ 64
#define M_ (B_*T_)          // 8192
#define N_QKV (3*C_)        // 2304
// softmax scale folded with log2(e) so we can use ex2
#define QSCALE (0.125f * 1.4426950408889634f)

// Scratch (allocation-free requirement -> __device__ globals)
__device__ float g_qkv[(size_t)M_ * N_QKV];   // [B*T, 3C]
__device__ float g_attn[(size_t)M_ * C_];     // [B*T, C]

// ---------------------------------------------------------------------------
// Helpers
// ---------------------------------------------------------------------------
__device__ __forceinline__ float to_tf32(float x) {
    uint32_t u;
    asm("cvt.rna.tf32.f32 %0, %1;" : "=r"(u) : "f"(x));
    return __uint_as_float(u);
}

__device__ __forceinline__ void mma_tf32(float* c, const uint32_t* a,
                                         uint32_t b0, uint32_t b1) {
    asm volatile(
        "mma.sync.aligned.m16n8k8.row.col.f32.tf32.tf32.f32 "
        "{%0,%1,%2,%3},{%4,%5,%6,%7},{%8,%9},{%0,%1,%2,%3};"
        : "+f"(c[0]), "+f"(c[1]), "+f"(c[2]), "+f"(c[3])
        : "r"(a[0]), "r"(a[1]), "r"(a[2]), "r"(a[3]), "r"(b0), "r"(b1));
}

__device__ __forceinline__ void mma_f16(float* c, const uint32_t* a,
                                        uint32_t b0, uint32_t b1) {
    asm volatile(
        "mma.sync.aligned.m16n8k16.row.col.f32.f16.f16.f32 "
        "{%0,%1,%2,%3},{%4,%5,%6,%7},{%8,%9},{%0,%1,%2,%3};"
        : "+f"(c[0]), "+f"(c[1]), "+f"(c[2]), "+f"(c[3])
        : "r"(a[0]), "r"(a[1]), "r"(a[2]), "r"(a[3]), "r"(b0), "r"(b1));
}

__device__ __forceinline__ uint32_t pack_h2(float lo, float hi) {
    __half2 h = __floats2half2_rn(lo, hi);
    return *reinterpret_cast<uint32_t*>(&h);
}

__device__ __forceinline__ float fast_exp2(float x) {
    float r;
    asm("ex2.approx.ftz.f32 %0, %1;" : "=f"(r) : "f"(x));
    return r;
}

// ---------------------------------------------------------------------------
// tf32 tensor-core GEMM with bias (round-3 proven version):
// C[M,N] = A[M,K] @ B[K,N] + bias[N]
// BM=BN=128, BK=16, 256 threads (8 warps), warp tile 64x32 (m16n8k8).
// ---------------------------------------------------------------------------
__global__ void __launch_bounds__(256)
gemm_tf32_kernel(const float* __restrict__ A, const float* __restrict__ B,
                 const float* __restrict__ bias, float* __restrict__ C,
                 int M, int N, int K)
{
    __shared__ float As[128][20];   // [m][k], pitch 20 -> conflict-free frags
    __shared__ float Bs[16][136];   // [k][n], pitch 136 (==8 mod 32) -> conflict-free

    const int tid = threadIdx.x;
    const int wid = tid >> 5;
    const int lane = tid & 31;
    const int g = lane >> 2;       // 0..7
    const int t4 = lane & 3;       // 0..3
    const int wm = wid >> 2;       // 0..1 -> m offset wm*64
    const int wn = wid & 3;        // 0..3 -> n offset wn*32
    const int bx = blockIdx.x, by = blockIdx.y;

    float acc[4][4][4];
    #pragma unroll
    for (int mt = 0; mt < 4; mt++)
        #pragma unroll
        for (int nt = 0; nt < 4; nt++)
            #pragma unroll
            for (int i = 0; i < 4; i++) acc[mt][nt][i] = 0.f;

    const int ar = tid >> 2;            // 0..63 (rows ar, ar+64)
    const int ac = (tid & 3) * 4;
    const int br = tid >> 5;            // 0..7 (rows br, br+8)
    const int bc = (lane) * 4;

    for (int k0 = 0; k0 < K; k0 += 16) {
        #pragma unroll
        for (int h = 0; h < 2; h++) {
            const int row = ar + h * 64;
            float4 v = *reinterpret_cast<const float4*>(
                A + (size_t)(by * 128 + row) * K + k0 + ac);
            As[row][ac + 0] = to_tf32(v.x);
            As[row][ac + 1] = to_tf32(v.y);
            As[row][ac + 2] = to_tf32(v.z);
            As[row][ac + 3] = to_tf32(v.w);
        }
        #pragma unroll
        for (int h = 0; h < 2; h++) {
            const int row = br + h * 8;
            float4 v = *reinterpret_cast<const float4*>(
                B + (size_t)(k0 + row) * N + bx * 128 + bc);
            Bs[row][bc + 0] = to_tf32(v.x);
            Bs[row][bc + 1] = to_tf32(v.y);
            Bs[row][bc + 2] = to_tf32(v.z);
            Bs[row][bc + 3] = to_tf32(v.w);
        }
        __syncthreads();

        #pragma unroll
        for (int kk = 0; kk < 16; kk += 8) {
            uint32_t afr[4][4], bfr[4][2];
            #pragma unroll
            for (int mt = 0; mt < 4; mt++) {
                const int row = wm * 64 + mt * 16;
                afr[mt][0] = __float_as_uint(As[row + g][kk + t4]);
                afr[mt][1] = __float_as_uint(As[row + g + 8][kk + t4]);
                afr[mt][2] = __float_as_uint(As[row + g][kk + t4 + 4]);
                afr[mt][3] = __float_as_uint(As[row + g + 8][kk + t4 + 4]);
            }
            #pragma unroll
            for (int nt = 0; nt < 4; nt++) {
                const int col = wn * 32 + nt * 8 + g;
                bfr[nt][0] = __float_as_uint(Bs[kk + t4][col]);
                bfr[nt][1] = __float_as_uint(Bs[kk + t4 + 4][col]);
            }
            #pragma unroll
            for (int mt = 0; mt < 4; mt++)
                #pragma unroll
                for (int nt = 0; nt < 4; nt++)
                    mma_tf32(acc[mt][nt], afr[mt], bfr[nt][0], bfr[nt][1]);
        }
        __syncthreads();
    }

    #pragma unroll
    for (int nt = 0; nt < 4; nt++) {
        const int col = bx * 128 + wn * 32 + nt * 8 + 2 * t4;
        const float b0 = bias[col], b1 = bias[col + 1];
        #pragma unroll
        for (int mt = 0; mt < 4; mt++) {
            const int row = by * 128 + wm * 64 + mt * 16 + g;
            float2 o0 = make_float2(acc[mt][nt][0] + b0, acc[mt][nt][1] + b1);
            float2 o1 = make_float2(acc[mt][nt][2] + b0, acc[mt][nt][3] + b1);
            *reinterpret_cast<float2*>(C + (size_t)row * N + col) = o0;
            *reinterpret_cast<float2*>(C + (size_t)(row + 8) * N + col) = o1;
        }
    }
}

// ---------------------------------------------------------------------------
// Flash attention (causal), fp16 tensor cores throughout.
// grid = (T/64, B*H), 128 threads (4 warps). Br=Bc=64, D=64.
// Warp w owns query rows [w*16, w*16+16).
//  - Q: staged fp32 (pre-scaled) through Vs buffer, frags packed to fp16 regs.
//  - K: stored half2 [k][72] (convert at STS), frags are direct half2 LDS.
//  - V: stored raw fp32 [k][68] (conflict-free float4 STS), frags packed
//    half2 at use time (conflict-free LDS.32).
//  - QK^T and P@V both m16n8k16.f16 with fp32 accumulation.
// ---------------------------------------------------------------------------
__global__ void __launch_bounds__(128)
attn_mma_kernel(const float* __restrict__ qkv, float* __restrict__ out)
{
    __shared__ __half Ksh[64][72];   // 9216 B
    __shared__ float  Vs[64][68];    // 17408 B (also Q staging buffer)

    const int bh = blockIdx.y;
    const int b = bh / H_;
    const int h = bh % H_;
    const int qtile = gridDim.x - 1 - blockIdx.x;   // big tiles first
    const int tid = threadIdx.x;
    const int w = tid >> 5;
    const int lane = tid & 31;
    const int g = lane >> 2;
    const int t4 = lane & 3;

    // ---- stage Q tile (pre-scaled fp32) through Vs ----
    #pragma unroll
    for (int i = 0; i < 8; i++) {
        const int c = tid + i * 128;          // 0..1023
        const int r = c >> 4;
        const int col = (c & 15) * 4;
        float4 v = *reinterpret_cast<const float4*>(
            qkv + (size_t)(b * T_ + qtile * 64 + r) * N_QKV + h * D_ + col);
        Vs[r][col + 0] = v.x * QSCALE;
        Vs[r][col + 1] = v.y * QSCALE;
        Vs[r][col + 2] = v.z * QSCALE;
        Vs[r][col + 3] = v.w * QSCALE;
    }
    __syncthreads();

    // ---- Q fragments (fp16): 4 k16-chunks x 4 half2 regs ----
    uint32_t Qa[4][4];
    {
        const int row = w * 16;
        #pragma unroll
        for (int kc = 0; kc < 4; kc++) {
            const int k0 = kc * 16 + 2 * t4;
            Qa[kc][0] = pack_h2(Vs[row + g][k0],         Vs[row + g][k0 + 1]);
            Qa[kc][1] = pack_h2(Vs[row + g + 8][k0],     Vs[row + g + 8][k0 + 1]);
            Qa[kc][2] = pack_h2(Vs[row + g][k0 + 8],     Vs[row + g][k0 + 9]);
            Qa[kc][3] = pack_h2(Vs[row + g + 8][k0 + 8], Vs[row + g + 8][k0 + 9]);
        }
    }

    float o[8][4];
    #pragma unroll
    for (int nt = 0; nt < 8; nt++)
        #pragma unroll
        for (int i = 0; i < 4; i++) o[nt][i] = 0.f;
    float m0 = -1e30f, m1 = -1e30f, l0 = 0.f, l1 = 0.f;

    const int ntiles = qtile + 1;
    for (int kt = 0; kt < ntiles; kt++) {
        const int kbase = kt * 64;
        __syncthreads();    // previous consumers done (and Q frags extracted)
        // ---- load K (->half) and V (raw fp32) tiles ----
        #pragma unroll
        for (int i = 0; i < 8; i++) {
            const int c = tid + i * 128;
            const int r = c >> 4;
            const int col = (c & 15) * 4;
            const float* src =
                qkv + (size_t)(b * T_ + kbase + r) * N_QKV + h * D_ + col;
            float4 kv = *reinterpret_cast<const float4*>(src + C_);
            *reinterpret_cast<__half2*>(&Ksh[r][col])     = __floats2half2_rn(kv.x, kv.y);
            *reinterpret_cast<__half2*>(&Ksh[r][col + 2]) = __floats2half2_rn(kv.z, kv.w);
            float4 vv = *reinterpret_cast<const float4*>(src + 2 * C_);
            *reinterpret_cast<float4*>(&Vs[r][col]) = vv;
        }
        __syncthreads();

        // ---- S = Q @ K^T (16x64 per warp), fp16 mma ----
        float s_[8][4];
        #pragma unroll
        for (int nt = 0; nt < 8; nt++)
            #pragma unroll
            for (int i = 0; i < 4; i++) s_[nt][i] = 0.f;
        #pragma unroll
        for (int kc = 0; kc < 4; kc++) {
            const int k0 = kc * 16 + 2 * t4;
            #pragma unroll
            for (int nt = 0; nt < 8; nt++) {
                uint32_t kb0 = *reinterpret_cast<const uint32_t*>(&Ksh[nt * 8 + g][k0]);
                uint32_t kb1 = *reinterpret_cast<const uint32_t*>(&Ksh[nt * 8 + g][k0 + 8]);
                mma_f16(s_[nt], Qa[kc], kb0, kb1);
            }
        }

        // ---- causal mask on diagonal tile ----
        if (kt == qtile) {
            const int q0 = w * 16 + g;
            const int q1 = q0 + 8;
            #pragma unroll
            for (int nt = 0; nt < 8; nt++) {
                const int c0 = nt * 8 + 2 * t4;
                if (c0 > q0)     s_[nt][0] = -1e30f;
                if (c0 + 1 > q0) s_[nt][1] = -1e30f;
                if (c0 > q1)     s_[nt][2] = -1e30f;
                if (c0 + 1 > q1) s_[nt][3] = -1e30f;
            }
        }

        // ---- online softmax (base-2) ----
        float mx0 = -1e30f, mx1 = -1e30f;
        #pragma unroll
        for (int nt = 0; nt < 8; nt++) {
            mx0 = fmaxf(mx0, fmaxf(s_[nt][0], s_[nt][1]));
            mx1 = fmaxf(mx1, fmaxf(s_[nt][2], s_[nt][3]));
        }
        mx0 = fmaxf(mx0, __shfl_xor_sync(0xffffffff, mx0, 1));
        mx0 = fmaxf(mx0, __shfl_xor_sync(0xffffffff, mx0, 2));
        mx1 = fmaxf(mx1, __shfl_xor_sync(0xffffffff, mx1, 1));
        mx1 = fmaxf(mx1, __shfl_xor_sync(0xffffffff, mx1, 2));
        const float nm0 = fmaxf(m0, mx0), nm1 = fmaxf(m1, mx1);
        const float sc0 = fast_exp2(m0 - nm0), sc1 = fast_exp2(m1 - nm1);
        m0 = nm0; m1 = nm1;

        float rs0 = 0.f, rs1 = 0.f;
        #pragma unroll
        for (int nt = 0; nt < 8; nt++) {
            s_[nt][0] = fast_exp2(s_[nt][0] - m0); rs0 += s_[nt][0];
            s_[nt][1] = fast_exp2(s_[nt][1] - m0); rs0 += s_[nt][1];
            s_[nt][2] = fast_exp2(s_[nt][2] - m1); rs1 += s_[nt][2];
            s_[nt][3] = fast_exp2(s_[nt][3] - m1); rs1 += s_[nt][3];
        }
        rs0 += __shfl_xor_sync(0xffffffff, rs0, 1);
        rs0 += __shfl_xor_sync(0xffffffff, rs0, 2);
        rs1 += __shfl_xor_sync(0xffffffff, rs1, 1);
        rs1 += __shfl_xor_sync(0xffffffff, rs1, 2);
        l0 = l0 * sc0 + rs0;
        l1 = l1 * sc1 + rs1;

        #pragma unroll
        for (int nt = 0; nt < 8; nt++) {
            o[nt][0] *= sc0; o[nt][1] *= sc0;
            o[nt][2] *= sc1; o[nt][3] *= sc1;
        }

        // ---- O += P @ V (fp16 mma; V frags packed from raw fp32) ----
        #pragma unroll
        for (int kc = 0; kc < 4; kc++) {
            uint32_t pa[4];
            pa[0] = pack_h2(s_[2 * kc][0], s_[2 * kc][1]);
            pa[1] = pack_h2(s_[2 * kc][2], s_[2 * kc][3]);
            pa[2] = pack_h2(s_[2 * kc + 1][0], s_[2 * kc + 1][1]);
            pa[3] = pack_h2(s_[2 * kc + 1][2], s_[2 * kc + 1][3]);
            const int k0 = kc * 16 + 2 * t4;
            #pragma unroll
            for (int nt = 0; nt < 8; nt++) {
                const int d = nt * 8 + g;
                uint32_t vb0 = pack_h2(Vs[k0][d],     Vs[k0 + 1][d]);
                uint32_t vb1 = pack_h2(Vs[k0 + 8][d], Vs[k0 + 9][d]);
                mma_f16(o[nt], pa, vb0, vb1);
            }
        }
    }

    // ---- normalize + store ----
    const float inv0 = 1.f / l0, inv1 = 1.f / l1;
    const size_t row0 = (size_t)(b * T_ + qtile * 64 + w * 16 + g);
    const size_t row1 = row0 + 8;
    #pragma unroll
    for (int nt = 0; nt < 8; nt++) {
        const int col = h * D_ + nt * 8 + 2 * t4;
        float2 v0 = make_float2(o[nt][0] * inv0, o[nt][1] * inv0);
        float2 v1 = make_float2(o[nt][2] * inv1, o[nt][3] * inv1);
        *reinterpret_cast<float2*>(out + row0 * C_ + col) = v0;
        *reinterpret_cast<float2*>(out + row1 * C_ + col) = v1;
    }
}

// ---------------------------------------------------------------------------
// Launch
// ---------------------------------------------------------------------------
extern "C" void kernel_launch(void* const* d_in, const int* in_sizes, int n_in,
                              void* d_out, int out_size)
{
    const float* x    = (const float*)d_in[0];
    const float* Wqkv = (const float*)d_in[1];
    const float* bqkv = (const float*)d_in[2];
    const float* Wout = (const float*)d_in[3];
    const float* bout = (const float*)d_in[4];
    float* out = (float*)d_out;

    float* qkv;  cudaGetSymbolAddress((void**)&qkv,  g_qkv);
    float* attn; cudaGetSymbolAddress((void**)&attn, g_attn);

    // 1) QKV projection: [8192,768] @ [768,2304] + bias
    {
        dim3 grid(N_QKV / 128, M_ / 128);
        gemm_tf32_kernel<<<grid, 256>>>(x, Wqkv, bqkv, qkv, M_, N_QKV, C_);
    }
    // 2) Causal attention (flash, fp16 tensor cores)
    {
        dim3 grid(T_ / 64, B_ * H_);
        attn_mma_kernel<<<grid, 128>>>(qkv, attn);
    }
    // 3) Output projection: [8192,768] @ [768,768] + bias
    {
        dim3 grid(C_ / 128, M_ / 128);
        gemm_tf32_kernel<<<grid, 256>>>(attn, Wout, bout, out, M_, C_, C_);
    }
}

// round 6
// speedup vs baseline: 2.0781x; 1.1906x over previous
#include <cuda_runtime.h>
#include <cuda_fp16.h>
#include <cstdint>
#include <cstddef>

#define B_ 2
#define T_ 4096
#define C_ 768
#define H_ 12
#define D_ 64
#define M_ (B_*T_)          // 8192
#define N_QKV (3*C_)        // 2304
// softmax scale folded with log2(e) so we can use ex2
#define QSCALE (0.125f * 1.4426950408889634f)

// Scratch (allocation-free requirement -> __device__ globals)
__device__ float g_qkv[(size_t)M_ * N_QKV];   // [B*T, 3C]
__device__ float g_attn[(size_t)M_ * C_];     // [B*T, C]

// ---------------------------------------------------------------------------
// Helpers
// ---------------------------------------------------------------------------
__device__ __forceinline__ void mma_f16(float* c, const uint32_t* a,
                                        uint32_t b0, uint32_t b1) {
    asm volatile(
        "mma.sync.aligned.m16n8k16.row.col.f32.f16.f16.f32 "
        "{%0,%1,%2,%3},{%4,%5,%6,%7},{%8,%9},{%0,%1,%2,%3};"
        : "+f"(c[0]), "+f"(c[1]), "+f"(c[2]), "+f"(c[3])
        : "r"(a[0]), "r"(a[1]), "r"(a[2]), "r"(a[3]), "r"(b0), "r"(b1));
}

__device__ __forceinline__ void ldsm_x4_trans(uint32_t& r0, uint32_t& r1,
                                              uint32_t& r2, uint32_t& r3,
                                              uint32_t addr) {
    asm volatile(
        "ldmatrix.sync.aligned.m8n8.x4.trans.shared.b16 {%0,%1,%2,%3}, [%4];"
        : "=r"(r0), "=r"(r1), "=r"(r2), "=r"(r3) : "r"(addr));
}

__device__ __forceinline__ uint32_t pack_h2(float lo, float hi) {
    __half2 h = __floats2half2_rn(lo, hi);
    return *reinterpret_cast<uint32_t*>(&h);
}

__device__ __forceinline__ float fast_exp2(float x) {
    float r;
    asm("ex2.approx.ftz.f32 %0, %1;" : "=f"(r) : "f"(x));
    return r;
}

__device__ __forceinline__ uint32_t smem_u32(const void* p) {
    return (uint32_t)__cvta_generic_to_shared(p);
}

// ---------------------------------------------------------------------------
// fp16 tensor-core GEMM with bias: C[M,N] = A[M,K] @ B[K,N] + bias[N]
// BM=BN=128, BK=32, 256 threads (8 warps), warp tile 64x32 (m16n8k16).
// A: half [128][40] (pitch 40 -> conflict-free scalar frag LDS).
// B: half [32][136] (row bank stride 4 -> conflict-free ldmatrix.x4.trans).
// fp32 accumulate, bias added in fp32 epilogue.
// ---------------------------------------------------------------------------
__global__ void __launch_bounds__(256)
gemm_f16_kernel(const float* __restrict__ A, const float* __restrict__ B,
                const float* __restrict__ bias, float* __restrict__ C,
                int M, int N, int K)
{
    __shared__ __half As[128][40];   // 10240 B
    __shared__ __half Bs[32][136];   // 8704 B

    const int tid = threadIdx.x;
    const int wid = tid >> 5;
    const int lane = tid & 31;
    const int g = lane >> 2;       // 0..7
    const int t4 = lane & 3;       // 0..3
    const int wm = wid >> 2;       // 0..1 -> m offset wm*64
    const int wn = wid & 3;        // 0..3 -> n offset wn*32
    const int bx = blockIdx.x, by = blockIdx.y;

    // ldmatrix lane addressing (4 matrices: klo/khi x nlo/nhi)
    const int mrow = lane & 7;
    const int mid  = lane >> 3;
    const uint32_t bbase = smem_u32(
        &Bs[(mid & 1) * 8 + mrow][wn * 32 + (mid >> 1) * 8]);

    float acc[4][4][4];
    #pragma unroll
    for (int mt = 0; mt < 4; mt++)
        #pragma unroll
        for (int nt = 0; nt < 4; nt++)
            #pragma unroll
            for (int i = 0; i < 4; i++) acc[mt][nt][i] = 0.f;

    // staging coordinates
    const int ar = tid >> 1;             // 0..127
    const int ac = (tid & 1) * 16;       // 0 or 16
    const int br = tid >> 3;             // 0..31
    const int bc = (tid & 7) * 16;       // 0..112

    for (int k0 = 0; k0 < K; k0 += 32) {
        // ---- stage A tile 128x32 (fp32 -> fp16) ----
        #pragma unroll
        for (int j = 0; j < 4; j++) {
            float4 v = *reinterpret_cast<const float4*>(
                A + (size_t)(by * 128 + ar) * K + k0 + ac + 4 * j);
            __half2 h0 = __floats2half2_rn(v.x, v.y);
            __half2 h1 = __floats2half2_rn(v.z, v.w);
            *reinterpret_cast<__half2*>(&As[ar][ac + 4 * j])     = h0;
            *reinterpret_cast<__half2*>(&As[ar][ac + 4 * j + 2]) = h1;
        }
        // ---- stage B tile 32x128 (fp32 -> fp16) ----
        #pragma unroll
        for (int j = 0; j < 4; j++) {
            float4 v = *reinterpret_cast<const float4*>(
                B + (size_t)(k0 + br) * N + bx * 128 + bc + 4 * j);
            __half2 h0 = __floats2half2_rn(v.x, v.y);
            __half2 h1 = __floats2half2_rn(v.z, v.w);
            *reinterpret_cast<__half2*>(&Bs[br][bc + 4 * j])     = h0;
            *reinterpret_cast<__half2*>(&Bs[br][bc + 4 * j + 2]) = h1;
        }
        __syncthreads();

        #pragma unroll
        for (int kk = 0; kk < 32; kk += 16) {
            uint32_t afr[4][4], bfr[4][2];
            #pragma unroll
            for (int mt = 0; mt < 4; mt++) {
                const int row = wm * 64 + mt * 16;
                const int kc = kk + 2 * t4;
                afr[mt][0] = *reinterpret_cast<const uint32_t*>(&As[row + g][kc]);
                afr[mt][1] = *reinterpret_cast<const uint32_t*>(&As[row + g + 8][kc]);
                afr[mt][2] = *reinterpret_cast<const uint32_t*>(&As[row + g][kc + 8]);
                afr[mt][3] = *reinterpret_cast<const uint32_t*>(&As[row + g + 8][kc + 8]);
            }
            #pragma unroll
            for (int p = 0; p < 2; p++) {
                uint32_t r0, r1, r2, r3;
                ldsm_x4_trans(r0, r1, r2, r3,
                              bbase + (uint32_t)(kk * 136 + p * 16) * 2);
                bfr[2 * p][0] = r0; bfr[2 * p][1] = r1;
                bfr[2 * p + 1][0] = r2; bfr[2 * p + 1][1] = r3;
            }
            #pragma unroll
            for (int mt = 0; mt < 4; mt++)
                #pragma unroll
                for (int nt = 0; nt < 4; nt++)
                    mma_f16(acc[mt][nt], afr[mt], bfr[nt][0], bfr[nt][1]);
        }
        __syncthreads();
    }

    // ---- epilogue: bias + store ----
    #pragma unroll
    for (int nt = 0; nt < 4; nt++) {
        const int col = bx * 128 + wn * 32 + nt * 8 + 2 * t4;
        const float b0 = bias[col], b1 = bias[col + 1];
        #pragma unroll
        for (int mt = 0; mt < 4; mt++) {
            const int row = by * 128 + wm * 64 + mt * 16 + g;
            float2 o0 = make_float2(acc[mt][nt][0] + b0, acc[mt][nt][1] + b1);
            float2 o1 = make_float2(acc[mt][nt][2] + b0, acc[mt][nt][3] + b1);
            *reinterpret_cast<float2*>(C + (size_t)row * N + col) = o0;
            *reinterpret_cast<float2*>(C + (size_t)(row + 8) * N + col) = o1;
        }
    }
}

// ---------------------------------------------------------------------------
// Flash attention (causal), fp16 tensor cores.
// grid = (T/64, B*H), 128 threads (4 warps). Br=Bc=64, D=64.
// Q/K/V all staged fp16 [64][72]. Q,K frags: scalar half2 LDS (conflict-free:
// bank = 4*row + t4). V frags: ldmatrix.x4.trans (row bank stride 4).
// ---------------------------------------------------------------------------
__global__ void __launch_bounds__(128)
attn_mma_kernel(const float* __restrict__ qkv, float* __restrict__ out)
{
    __shared__ __half Qh[64][72];    // 9216 B each
    __shared__ __half Kh[64][72];
    __shared__ __half Vh[64][72];

    const int bh = blockIdx.y;
    const int b = bh / H_;
    const int h = bh % H_;
    const int qtile = gridDim.x - 1 - blockIdx.x;   // big tiles first
    const int tid = threadIdx.x;
    const int w = tid >> 5;
    const int lane = tid & 31;
    const int g = lane >> 2;
    const int t4 = lane & 3;

    // ldmatrix lane addressing for V (4 matrices: klo/khi x dlo/dhi)
    const int mrow = lane & 7;
    const int mid  = lane >> 3;
    const uint32_t vbase = smem_u32(
        &Vh[(mid & 1) * 8 + mrow][(mid >> 1) * 8]);

    // ---- stage Q tile (pre-scaled fp16) ----
    #pragma unroll
    for (int i = 0; i < 8; i++) {
        const int c = tid + i * 128;          // 0..1023
        const int r = c >> 4;
        const int col = (c & 15) * 4;
        float4 v = *reinterpret_cast<const float4*>(
            qkv + (size_t)(b * T_ + qtile * 64 + r) * N_QKV + h * D_ + col);
        *reinterpret_cast<__half2*>(&Qh[r][col]) =
            __floats2half2_rn(v.x * QSCALE, v.y * QSCALE);
        *reinterpret_cast<__half2*>(&Qh[r][col + 2]) =
            __floats2half2_rn(v.z * QSCALE, v.w * QSCALE);
    }
    __syncthreads();

    // ---- Q fragments: 4 k16-chunks x 4 half2 regs ----
    uint32_t Qa[4][4];
    {
        const int row = w * 16;
        #pragma unroll
        for (int kc = 0; kc < 4; kc++) {
            const int k0 = kc * 16 + 2 * t4;
            Qa[kc][0] = *reinterpret_cast<const uint32_t*>(&Qh[row + g][k0]);
            Qa[kc][1] = *reinterpret_cast<const uint32_t*>(&Qh[row + g + 8][k0]);
            Qa[kc][2] = *reinterpret_cast<const uint32_t*>(&Qh[row + g][k0 + 8]);
            Qa[kc][3] = *reinterpret_cast<const uint32_t*>(&Qh[row + g + 8][k0 + 8]);
        }
    }

    float o[8][4];
    #pragma unroll
    for (int nt = 0; nt < 8; nt++)
        #pragma unroll
        for (int i = 0; i < 4; i++) o[nt][i] = 0.f;
    float m0 = -1e30f, m1 = -1e30f, l0 = 0.f, l1 = 0.f;

    const int ntiles = qtile + 1;
    for (int kt = 0; kt < ntiles; kt++) {
        const int kbase = kt * 64;
        __syncthreads();    // previous tile's consumers done
        // ---- stage K and V tiles (fp32 -> fp16) ----
        #pragma unroll
        for (int i = 0; i < 8; i++) {
            const int c = tid + i * 128;
            const int r = c >> 4;
            const int col = (c & 15) * 4;
            const float* src =
                qkv + (size_t)(b * T_ + kbase + r) * N_QKV + h * D_ + col;
            float4 kv = *reinterpret_cast<const float4*>(src + C_);
            *reinterpret_cast<__half2*>(&Kh[r][col])     = __floats2half2_rn(kv.x, kv.y);
            *reinterpret_cast<__half2*>(&Kh[r][col + 2]) = __floats2half2_rn(kv.z, kv.w);
            float4 vv = *reinterpret_cast<const float4*>(src + 2 * C_);
            *reinterpret_cast<__half2*>(&Vh[r][col])     = __floats2half2_rn(vv.x, vv.y);
            *reinterpret_cast<__half2*>(&Vh[r][col + 2]) = __floats2half2_rn(vv.z, vv.w);
        }
        __syncthreads();

        // ---- S = Q @ K^T (16x64 per warp) ----
        float s_[8][4];
        #pragma unroll
        for (int nt = 0; nt < 8; nt++)
            #pragma unroll
            for (int i = 0; i < 4; i++) s_[nt][i] = 0.f;
        #pragma unroll
        for (int kc = 0; kc < 4; kc++) {
            const int k0 = kc * 16 + 2 * t4;
            #pragma unroll
            for (int nt = 0; nt < 8; nt++) {
                uint32_t kb0 = *reinterpret_cast<const uint32_t*>(&Kh[nt * 8 + g][k0]);
                uint32_t kb1 = *reinterpret_cast<const uint32_t*>(&Kh[nt * 8 + g][k0 + 8]);
                mma_f16(s_[nt], Qa[kc], kb0, kb1);
            }
        }

        // ---- causal mask on diagonal tile ----
        if (kt == qtile) {
            const int q0 = w * 16 + g;
            const int q1 = q0 + 8;
            #pragma unroll
            for (int nt = 0; nt < 8; nt++) {
                const int c0 = nt * 8 + 2 * t4;
                if (c0 > q0)     s_[nt][0] = -1e30f;
                if (c0 + 1 > q0) s_[nt][1] = -1e30f;
                if (c0 > q1)     s_[nt][2] = -1e30f;
                if (c0 + 1 > q1) s_[nt][3] = -1e30f;
            }
        }

        // ---- online softmax (base-2) ----
        float mx0 = -1e30f, mx1 = -1e30f;
        #pragma unroll
        for (int nt = 0; nt < 8; nt++) {
            mx0 = fmaxf(mx0, fmaxf(s_[nt][0], s_[nt][1]));
            mx1 = fmaxf(mx1, fmaxf(s_[nt][2], s_[nt][3]));
        }
        mx0 = fmaxf(mx0, __shfl_xor_sync(0xffffffff, mx0, 1));
        mx0 = fmaxf(mx0, __shfl_xor_sync(0xffffffff, mx0, 2));
        mx1 = fmaxf(mx1, __shfl_xor_sync(0xffffffff, mx1, 1));
        mx1 = fmaxf(mx1, __shfl_xor_sync(0xffffffff, mx1, 2));
        const float nm0 = fmaxf(m0, mx0), nm1 = fmaxf(m1, mx1);
        const float sc0 = fast_exp2(m0 - nm0), sc1 = fast_exp2(m1 - nm1);
        m0 = nm0; m1 = nm1;

        float rs0 = 0.f, rs1 = 0.f;
        #pragma unroll
        for (int nt = 0; nt < 8; nt++) {
            s_[nt][0] = fast_exp2(s_[nt][0] - m0); rs0 += s_[nt][0];
            s_[nt][1] = fast_exp2(s_[nt][1] - m0); rs0 += s_[nt][1];
            s_[nt][2] = fast_exp2(s_[nt][2] - m1); rs1 += s_[nt][2];
            s_[nt][3] = fast_exp2(s_[nt][3] - m1); rs1 += s_[nt][3];
        }
        rs0 += __shfl_xor_sync(0xffffffff, rs0, 1);
        rs0 += __shfl_xor_sync(0xffffffff, rs0, 2);
        rs1 += __shfl_xor_sync(0xffffffff, rs1, 1);
        rs1 += __shfl_xor_sync(0xffffffff, rs1, 2);
        l0 = l0 * sc0 + rs0;
        l1 = l1 * sc1 + rs1;

        #pragma unroll
        for (int nt = 0; nt < 8; nt++) {
            o[nt][0] *= sc0; o[nt][1] *= sc0;
            o[nt][2] *= sc1; o[nt][3] *= sc1;
        }

        // ---- O += P @ V (V frags via ldmatrix.x4.trans) ----
        #pragma unroll
        for (int kc = 0; kc < 4; kc++) {
            uint32_t pa[4];
            pa[0] = pack_h2(s_[2 * kc][0], s_[2 * kc][1]);
            pa[1] = pack_h2(s_[2 * kc][2], s_[2 * kc][3]);
            pa[2] = pack_h2(s_[2 * kc + 1][0], s_[2 * kc + 1][1]);
            pa[3] = pack_h2(s_[2 * kc + 1][2], s_[2 * kc + 1][3]);
            #pragma unroll
            for (int p = 0; p < 4; p++) {
                uint32_t v0, v1, v2, v3;
                ldsm_x4_trans(v0, v1, v2, v3,
                              vbase + (uint32_t)(kc * 16 * 72 + p * 16) * 2);
                mma_f16(o[2 * p],     pa, v0, v1);
                mma_f16(o[2 * p + 1], pa, v2, v3);
            }
        }
    }

    // ---- normalize + store ----
    const float inv0 = 1.f / l0, inv1 = 1.f / l1;
    const size_t row0 = (size_t)(b * T_ + qtile * 64 + w * 16 + g);
    const size_t row1 = row0 + 8;
    #pragma unroll
    for (int nt = 0; nt < 8; nt++) {
        const int col = h * D_ + nt * 8 + 2 * t4;
        float2 v0 = make_float2(o[nt][0] * inv0, o[nt][1] * inv0);
        float2 v1 = make_float2(o[nt][2] * inv1, o[nt][3] * inv1);
        *reinterpret_cast<float2*>(out + row0 * C_ + col) = v0;
        *reinterpret_cast<float2*>(out + row1 * C_ + col) = v1;
    }
}

// ---------------------------------------------------------------------------
// Launch
// ---------------------------------------------------------------------------
extern "C" void kernel_launch(void* const* d_in, const int* in_sizes, int n_in,
                              void* d_out, int out_size)
{
    const float* x    = (const float*)d_in[0];
    const float* Wqkv = (const float*)d_in[1];
    const float* bqkv = (const float*)d_in[2];
    const float* Wout = (const float*)d_in[3];
    const float* bout = (const float*)d_in[4];
    float* out = (float*)d_out;

    float* qkv;  cudaGetSymbolAddress((void**)&qkv,  g_qkv);
    float* attn; cudaGetSymbolAddress((void**)&attn, g_attn);

    // 1) QKV projection: [8192,768] @ [768,2304] + bias
    {
        dim3 grid(N_QKV / 128, M_ / 128);
        gemm_f16_kernel<<<grid, 256>>>(x, Wqkv, bqkv, qkv, M_, N_QKV, C_);
    }
    // 2) Causal attention (flash, fp16 tensor cores)
    {
        dim3 grid(T_ / 64, B_ * H_);
        attn_mma_kernel<<<grid, 128>>>(qkv, attn);
    }
    // 3) Output projection: [8192,768] @ [768,768] + bias
    {
        dim3 grid(C_ / 128, M_ / 128);
        gemm_f16_kernel<<<grid, 256>>>(attn, Wout, bout, out, M_, C_, C_);
    }
}

// round 8
// speedup vs baseline: 2.9803x; 1.4341x over previous
#include <cuda_runtime.h>
#include <cuda_fp16.h>
#include <cstdint>
#include <cstddef>

#define B_ 2
#define T_ 4096
#define C_ 768
#define H_ 12
#define D_ 64
#define M_ (B_*T_)          // 8192
#define N_QKV (3*C_)        // 2304
// softmax scale folded with log2(e) so we can use ex2
#define QSCALE (0.125f * 1.4426950408889634f)

// fp16 scratch (allocation-free requirement -> __device__ globals)
__device__ __half g_xh[(size_t)M_ * C_];
__device__ __half g_wqkvh[(size_t)C_ * N_QKV];
__device__ __half g_wouth[(size_t)C_ * C_];
__device__ __half g_qkvh[(size_t)M_ * N_QKV];   // Q part pre-scaled by QSCALE
__device__ __half g_attnh[(size_t)M_ * C_];

// ---------------------------------------------------------------------------
// Helpers
// ---------------------------------------------------------------------------
__device__ __forceinline__ void mma_f16(float* c, const uint32_t* a,
                                        uint32_t b0, uint32_t b1) {
    asm volatile(
        "mma.sync.aligned.m16n8k16.row.col.f32.f16.f16.f32 "
        "{%0,%1,%2,%3},{%4,%5,%6,%7},{%8,%9},{%0,%1,%2,%3};"
        : "+f"(c[0]), "+f"(c[1]), "+f"(c[2]), "+f"(c[3])
        : "r"(a[0]), "r"(a[1]), "r"(a[2]), "r"(a[3]), "r"(b0), "r"(b1));
}

__device__ __forceinline__ void ldsm_x4(uint32_t& r0, uint32_t& r1,
                                        uint32_t& r2, uint32_t& r3,
                                        uint32_t addr) {
    asm volatile(
        "ldmatrix.sync.aligned.m8n8.x4.shared.b16 {%0,%1,%2,%3}, [%4];"
        : "=r"(r0), "=r"(r1), "=r"(r2), "=r"(r3) : "r"(addr));
}

__device__ __forceinline__ void ldsm_x4_trans(uint32_t& r0, uint32_t& r1,
                                              uint32_t& r2, uint32_t& r3,
                                              uint32_t addr) {
    asm volatile(
        "ldmatrix.sync.aligned.m8n8.x4.trans.shared.b16 {%0,%1,%2,%3}, [%4];"
        : "=r"(r0), "=r"(r1), "=r"(r2), "=r"(r3) : "r"(addr));
}

__device__ __forceinline__ uint32_t pack_h2(float lo, float hi) {
    __half2 h = __floats2half2_rn(lo, hi);
    return *reinterpret_cast<uint32_t*>(&h);
}

__device__ __forceinline__ float fast_exp2(float x) {
    float r;
    asm("ex2.approx.ftz.f32 %0, %1;" : "=f"(r) : "f"(x));
    return r;
}

__device__ __forceinline__ uint32_t smem_u32(const void* p) {
    return (uint32_t)__cvta_generic_to_shared(p);
}

// ---------------------------------------------------------------------------
// fp32 -> fp16 conversion (elementwise), n4 = numel/4
// ---------------------------------------------------------------------------
__global__ void __launch_bounds__(256)
cvt_f32_f16(const float* __restrict__ in, __half* __restrict__ out, int n4)
{
    int i = blockIdx.x * blockDim.x + threadIdx.x;
    if (i < n4) {
        float4 v = reinterpret_cast<const float4*>(in)[i];
        __half2 h0 = __floats2half2_rn(v.x, v.y);
        __half2 h1 = __floats2half2_rn(v.z, v.w);
        uint2 u;
        u.x = *reinterpret_cast<uint32_t*>(&h0);
        u.y = *reinterpret_cast<uint32_t*>(&h1);
        reinterpret_cast<uint2*>(out)[i] = u;
    }
}

// ---------------------------------------------------------------------------
// fp16-in tensor-core GEMM with bias: C[M,N] = A[M,K] @ B[K,N] + bias[N]
// BM=BN=128, BK=32, 256 threads (8 warps), warp tile 64x32 (m16n8k16).
// A: half [128][40]  -> A-frags via ldmatrix.x4      (row stride 20 banks)
// B: half [32][136]  -> B-frags via ldmatrix.x4.trans (row stride 4 banks)
// HALF_OUT: write fp16, scaling columns < qcols by qsc (Q pre-scale).
// ---------------------------------------------------------------------------
template<bool HALF_OUT>
__global__ void __launch_bounds__(256)
gemm_h_kernel(const __half* __restrict__ A, const __half* __restrict__ B,
              const float* __restrict__ bias, void* __restrict__ Cout,
              int M, int N, int K, int qcols, float qsc)
{
    __shared__ __half As[128][40];   // 10240 B
    __shared__ __half Bs[32][136];   // 8704 B

    const int tid = threadIdx.x;
    const int wid = tid >> 5;
    const int lane = tid & 31;
    const int g = lane >> 2;
    const int t4 = lane & 3;
    const int wm = wid >> 2;
    const int wn = wid & 3;
    const int bx = blockIdx.x, by = blockIdx.y;
    const int mrow = lane & 7;
    const int mid  = lane >> 3;

    const uint32_t abase = smem_u32(
        &As[wm * 64 + (mid & 1) * 8 + mrow][(mid >> 1) * 8]);
    const uint32_t bbase = smem_u32(
        &Bs[(mid & 1) * 8 + mrow][wn * 32 + (mid >> 1) * 8]);

    float acc[4][4][4];
    #pragma unroll
    for (int mt = 0; mt < 4; mt++)
        #pragma unroll
        for (int nt = 0; nt < 4; nt++)
            #pragma unroll
            for (int i = 0; i < 4; i++) acc[mt][nt][i] = 0.f;

    for (int k0 = 0; k0 < K; k0 += 32) {
        // ---- stage A tile 128x32 halves (pure copy) ----
        #pragma unroll
        for (int i = 0; i < 2; i++) {
            const int c = tid + i * 256;       // 0..511
            const int r = c >> 2;              // 0..127
            const int ch = c & 3;              // uint4 chunk
            *reinterpret_cast<uint4*>(&As[r][ch * 8]) =
                *reinterpret_cast<const uint4*>(
                    A + (size_t)(by * 128 + r) * K + k0 + ch * 8);
        }
        // ---- stage B tile 32x128 halves (pure copy) ----
        #pragma unroll
        for (int i = 0; i < 2; i++) {
            const int c = tid + i * 256;       // 0..511
            const int r = c >> 4;              // 0..31
            const int ch = c & 15;
            *reinterpret_cast<uint4*>(&Bs[r][ch * 8]) =
                *reinterpret_cast<const uint4*>(
                    B + (size_t)(k0 + r) * N + bx * 128 + ch * 8);
        }
        __syncthreads();

        #pragma unroll
        for (int kk = 0; kk < 32; kk += 16) {
            uint32_t afr[4][4], bfr[4][2];
            #pragma unroll
            for (int mt = 0; mt < 4; mt++)
                ldsm_x4(afr[mt][0], afr[mt][1], afr[mt][2], afr[mt][3],
                        abase + (uint32_t)(mt * 16 * 40 + kk) * 2);
            #pragma unroll
            for (int p = 0; p < 2; p++) {
                uint32_t r0, r1, r2, r3;
                ldsm_x4_trans(r0, r1, r2, r3,
                              bbase + (uint32_t)(kk * 136 + p * 16) * 2);
                bfr[2 * p][0] = r0; bfr[2 * p][1] = r1;
                bfr[2 * p + 1][0] = r2; bfr[2 * p + 1][1] = r3;
            }
            #pragma unroll
            for (int mt = 0; mt < 4; mt++)
                #pragma unroll
                for (int nt = 0; nt < 4; nt++)
                    mma_f16(acc[mt][nt], afr[mt], bfr[nt][0], bfr[nt][1]);
        }
        __syncthreads();
    }

    // ---- epilogue ----
    float osc = 1.f;
    if (HALF_OUT) osc = (bx * 128 < qcols) ? qsc : 1.f;

    #pragma unroll
    for (int nt = 0; nt < 4; nt++) {
        const int col = bx * 128 + wn * 32 + nt * 8 + 2 * t4;
        const float b0 = bias[col], b1 = bias[col + 1];
        #pragma unroll
        for (int mt = 0; mt < 4; mt++) {
            const int row = by * 128 + wm * 64 + mt * 16 + g;
            if (HALF_OUT) {
                __half* Ch = (__half*)Cout;
                uint32_t v0 = pack_h2((acc[mt][nt][0] + b0) * osc,
                                      (acc[mt][nt][1] + b1) * osc);
                uint32_t v1 = pack_h2((acc[mt][nt][2] + b0) * osc,
                                      (acc[mt][nt][3] + b1) * osc);
                *reinterpret_cast<uint32_t*>(&Ch[(size_t)row * N + col]) = v0;
                *reinterpret_cast<uint32_t*>(&Ch[(size_t)(row + 8) * N + col]) = v1;
            } else {
                float* Cf = (float*)Cout;
                float2 o0 = make_float2(acc[mt][nt][0] + b0, acc[mt][nt][1] + b1);
                float2 o1 = make_float2(acc[mt][nt][2] + b0, acc[mt][nt][3] + b1);
                *reinterpret_cast<float2*>(Cf + (size_t)row * N + col) = o0;
                *reinterpret_cast<float2*>(Cf + (size_t)(row + 8) * N + col) = o1;
            }
        }
    }
}

// ---------------------------------------------------------------------------
// Flash attention (causal), fp16 end-to-end.
// grid = (T/128, B*H), 256 threads (8 warps). Br=128, Bc=64, D=64.
// qkvh already fp16 with Q pre-scaled. Staging = pure uint4 copies.
// K frags: ldmatrix.x4 (non-trans), V frags: ldmatrix.x4.trans.
// Output written fp16 to g_attnh.
// ---------------------------------------------------------------------------
__global__ void __launch_bounds__(256)
attn_mma_kernel(const __half* __restrict__ qkvh, __half* __restrict__ outh)
{
    __shared__ __half Qh[128][72];   // 18432 B
    __shared__ __half Kh[64][72];    //  9216 B
    __shared__ __half Vh[64][72];    //  9216 B

    const int bh = blockIdx.y;
    const int b = bh / H_;
    const int h = bh % H_;
    const int qtile = gridDim.x - 1 - blockIdx.x;   // big tiles first
    const int tid = threadIdx.x;
    const int w = tid >> 5;
    const int lane = tid & 31;
    const int g = lane >> 2;
    const int t4 = lane & 3;
    const int mrow = lane & 7;
    const int mid  = lane >> 3;

    // ldmatrix bases
    const uint32_t kfb = smem_u32(&Kh[(mid >> 1) * 8 + mrow][(mid & 1) * 8]);
    const uint32_t vfb = smem_u32(&Vh[(mid & 1) * 8 + mrow][(mid >> 1) * 8]);

    // ---- stage Q tile (pure copy; already fp16 + pre-scaled) ----
    #pragma unroll
    for (int i = 0; i < 4; i++) {
        const int c = tid + i * 256;          // 0..1023
        const int r = c >> 3;                 // 0..127
        const int ch = c & 7;
        *reinterpret_cast<uint4*>(&Qh[r][ch * 8]) =
            *reinterpret_cast<const uint4*>(
                qkvh + (size_t)(b * T_ + qtile * 128 + r) * N_QKV + h * D_ + ch * 8);
    }
    __syncthreads();

    // ---- Q fragments: 4 k16-chunks x 4 half2 regs (conflict-free LDS) ----
    uint32_t Qa[4][4];
    {
        const int row = w * 16;
        #pragma unroll
        for (int kc = 0; kc < 4; kc++) {
            const int k0 = kc * 16 + 2 * t4;
            Qa[kc][0] = *reinterpret_cast<const uint32_t*>(&Qh[row + g][k0]);
            Qa[kc][1] = *reinterpret_cast<const uint32_t*>(&Qh[row + g + 8][k0]);
            Qa[kc][2] = *reinterpret_cast<const uint32_t*>(&Qh[row + g][k0 + 8]);
            Qa[kc][3] = *reinterpret_cast<const uint32_t*>(&Qh[row + g + 8][k0 + 8]);
        }
    }

    float o[8][4];
    #pragma unroll
    for (int nt = 0; nt < 8; nt++)
        #pragma unroll
        for (int i = 0; i < 4; i++) o[nt][i] = 0.f;
    float m0 = -1e30f, m1 = -1e30f, l0 = 0.f, l1 = 0.f;

    const int q0g = qtile * 128 + w * 16 + g;   // own query row (second is +8)
    const int ntiles = 2 * qtile + 2;

    for (int kt = 0; kt < ntiles; kt++) {
        const int kbase = kt * 64;
        __syncthreads();    // previous tile's consumers done
        // ---- stage K/V tiles (pure copies) ----
        #pragma unroll
        for (int i = 0; i < 2; i++) {
            const int c = tid + i * 256;      // 0..511
            const int r = c >> 3;             // 0..63
            const int ch = c & 7;
            const __half* src =
                qkvh + (size_t)(b * T_ + kbase + r) * N_QKV + h * D_ + ch * 8;
            *reinterpret_cast<uint4*>(&Kh[r][ch * 8]) =
                *reinterpret_cast<const uint4*>(src + C_);
            *reinterpret_cast<uint4*>(&Vh[r][ch * 8]) =
                *reinterpret_cast<const uint4*>(src + 2 * C_);
        }
        __syncthreads();

        // ---- S = Q @ K^T (16x64 per warp); K frags via ldmatrix.x4 ----
        float s_[8][4];
        #pragma unroll
        for (int nt = 0; nt < 8; nt++)
            #pragma unroll
            for (int i = 0; i < 4; i++) s_[nt][i] = 0.f;
        #pragma unroll
        for (int kc = 0; kc < 4; kc++) {
            #pragma unroll
            for (int np = 0; np < 4; np++) {
                uint32_t r0, r1, r2, r3;
                ldsm_x4(r0, r1, r2, r3,
                        kfb + (uint32_t)(np * 16 * 72 + kc * 16) * 2);
                mma_f16(s_[2 * np],     Qa[kc], r0, r1);
                mma_f16(s_[2 * np + 1], Qa[kc], r2, r3);
            }
        }

        // ---- causal mask (tiles overlapping/above the diagonal) ----
        if (kbase + 63 > q0g) {
            #pragma unroll
            for (int nt = 0; nt < 8; nt++) {
                const int c0 = kbase + nt * 8 + 2 * t4;
                if (c0 > q0g)         s_[nt][0] = -1e30f;
                if (c0 + 1 > q0g)     s_[nt][1] = -1e30f;
                if (c0 > q0g + 8)     s_[nt][2] = -1e30f;
                if (c0 + 1 > q0g + 8) s_[nt][3] = -1e30f;
            }
        }

        // ---- online softmax (base-2) ----
        float mx0 = -1e30f, mx1 = -1e30f;
        #pragma unroll
        for (int nt = 0; nt < 8; nt++) {
            mx0 = fmaxf(mx0, fmaxf(s_[nt][0], s_[nt][1]));
            mx1 = fmaxf(mx1, fmaxf(s_[nt][2], s_[nt][3]));
        }
        mx0 = fmaxf(mx0, __shfl_xor_sync(0xffffffff, mx0, 1));
        mx0 = fmaxf(mx0, __shfl_xor_sync(0xffffffff, mx0, 2));
        mx1 = fmaxf(mx1, __shfl_xor_sync(0xffffffff, mx1, 1));
        mx1 = fmaxf(mx1, __shfl_xor_sync(0xffffffff, mx1, 2));
        const float nm0 = fmaxf(m0, mx0), nm1 = fmaxf(m1, mx1);
        const float sc0 = fast_exp2(m0 - nm0), sc1 = fast_exp2(m1 - nm1);
        m0 = nm0; m1 = nm1;

        float rs0 = 0.f, rs1 = 0.f;
        #pragma unroll
        for (int nt = 0; nt < 8; nt++) {
            s_[nt][0] = fast_exp2(s_[nt][0] - m0); rs0 += s_[nt][0];
            s_[nt][1] = fast_exp2(s_[nt][1] - m0); rs0 += s_[nt][1];
            s_[nt][2] = fast_exp2(s_[nt][2] - m1); rs1 += s_[nt][2];
            s_[nt][3] = fast_exp2(s_[nt][3] - m1); rs1 += s_[nt][3];
        }
        rs0 += __shfl_xor_sync(0xffffffff, rs0, 1);
        rs0 += __shfl_xor_sync(0xffffffff, rs0, 2);
        rs1 += __shfl_xor_sync(0xffffffff, rs1, 1);
        rs1 += __shfl_xor_sync(0xffffffff, rs1, 2);
        l0 = l0 * sc0 + rs0;
        l1 = l1 * sc1 + rs1;

        #pragma unroll
        for (int nt = 0; nt < 8; nt++) {
            o[nt][0] *= sc0; o[nt][1] *= sc0;
            o[nt][2] *= sc1; o[nt][3] *= sc1;
        }

        // ---- O += P @ V (V frags via ldmatrix.x4.trans) ----
        #pragma unroll
        for (int kc = 0; kc < 4; kc++) {
            uint32_t pa[4];
            pa[0] = pack_h2(s_[2 * kc][0], s_[2 * kc][1]);
            pa[1] = pack_h2(s_[2 * kc][2], s_[2 * kc][3]);
            pa[2] = pack_h2(s_[2 * kc + 1][0], s_[2 * kc + 1][1]);
            pa[3] = pack_h2(s_[2 * kc + 1][2], s_[2 * kc + 1][3]);
            #pragma unroll
            for (int p = 0; p < 4; p++) {
                uint32_t v0, v1, v2, v3;
                ldsm_x4_trans(v0, v1, v2, v3,
                              vfb + (uint32_t)(kc * 16 * 72 + p * 16) * 2);
                mma_f16(o[2 * p],     pa, v0, v1);
                mma_f16(o[2 * p + 1], pa, v2, v3);
            }
        }
    }

    // ---- normalize + store (fp16) ----
    const float inv0 = 1.f / l0, inv1 = 1.f / l1;
    const size_t row0 = (size_t)(b * T_ + qtile * 128 + w * 16 + g);
    const size_t row1 = row0 + 8;
    #pragma unroll
    for (int nt = 0; nt < 8; nt++) {
        const int col = h * D_ + nt * 8 + 2 * t4;
        uint32_t v0 = pack_h2(o[nt][0] * inv0, o[nt][1] * inv0);
        uint32_t v1 = pack_h2(o[nt][2] * inv1, o[nt][3] * inv1);
        *reinterpret_cast<uint32_t*>(&outh[row0 * C_ + col]) = v0;
        *reinterpret_cast<uint32_t*>(&outh[row1 * C_ + col]) = v1;
    }
}

// ---------------------------------------------------------------------------
// Launch
// ---------------------------------------------------------------------------
extern "C" void kernel_launch(void* const* d_in, const int* in_sizes, int n_in,
                              void* d_out, int out_size)
{
    const float* x    = (const float*)d_in[0];
    const float* Wqkv = (const float*)d_in[1];
    const float* bqkv = (const float*)d_in[2];
    const float* Wout = (const float*)d_in[3];
    const float* bout = (const float*)d_in[4];
    float* out = (float*)d_out;

    __half *xh, *wqkvh, *wouth, *qkvh, *attnh;
    cudaGetSymbolAddress((void**)&xh,    g_xh);
    cudaGetSymbolAddress((void**)&wqkvh, g_wqkvh);
    cudaGetSymbolAddress((void**)&wouth, g_wouth);
    cudaGetSymbolAddress((void**)&qkvh,  g_qkvh);
    cudaGetSymbolAddress((void**)&attnh, g_attnh);

    // 0) fp32 -> fp16 conversions (ceil-div grids; sizes divide evenly anyway)
    {
        const int n0 = M_ * C_ / 4;
        const int n1 = C_ * N_QKV / 4;
        const int n2 = C_ * C_ / 4;
        cvt_f32_f16<<<(n0 + 255) / 256, 256>>>(x, xh, n0);
        cvt_f32_f16<<<(n1 + 255) / 256, 256>>>(Wqkv, wqkvh, n1);
        cvt_f32_f16<<<(n2 + 255) / 256, 256>>>(Wout, wouth, n2);
    }

    // 1) QKV projection (fp16 out, Q columns pre-scaled by QSCALE)
    {
        dim3 grid(N_QKV / 128, M_ / 128);
        gemm_h_kernel<true><<<grid, 256>>>(xh, wqkvh, bqkv, qkvh,
                                           M_, N_QKV, C_, C_, (float)QSCALE);
    }
    // 2) Causal attention (flash, fp16 tensor cores, fp16 out)
    {
        dim3 grid(T_ / 128, B_ * H_);
        attn_mma_kernel<<<grid, 256>>>(qkvh, attnh);
    }
    // 3) Output projection (fp32 out)
    {
        dim3 grid(C_ / 128, M_ / 128);
        gemm_h_kernel<false><<<grid, 256>>>(attnh, wouth, bout, out,
                                            M_, C_, C_, 0, 1.f);
    }
}

// round 9
// speedup vs baseline: 3.1410x; 1.0539x over previous
#include <cuda_runtime.h>
#include <cuda_fp16.h>
#include <cstdint>
#include <cstddef>

#define B_ 2
#define T_ 4096
#define C_ 768
#define H_ 12
#define D_ 64
#define M_ (B_*T_)          // 8192
#define N_QKV (3*C_)        // 2304
// softmax scale folded with log2(e) so we can use ex2
#define QSCALE (0.125f * 1.4426950408889634f)

// fp16 scratch (allocation-free requirement -> __device__ globals)
__device__ __half g_xh[(size_t)M_ * C_];
__device__ __half g_wqkvh[(size_t)C_ * N_QKV];
__device__ __half g_wouth[(size_t)C_ * C_];
__device__ __half g_qkvh[(size_t)M_ * N_QKV];   // Q part pre-scaled by QSCALE
__device__ __half g_attnh[(size_t)M_ * C_];

// ---------------------------------------------------------------------------
// Helpers
// ---------------------------------------------------------------------------
__device__ __forceinline__ void mma_f16(float* c, const uint32_t* a,
                                        uint32_t b0, uint32_t b1) {
    asm volatile(
        "mma.sync.aligned.m16n8k16.row.col.f32.f16.f16.f32 "
        "{%0,%1,%2,%3},{%4,%5,%6,%7},{%8,%9},{%0,%1,%2,%3};"
        : "+f"(c[0]), "+f"(c[1]), "+f"(c[2]), "+f"(c[3])
        : "r"(a[0]), "r"(a[1]), "r"(a[2]), "r"(a[3]), "r"(b0), "r"(b1));
}

__device__ __forceinline__ void ldsm_x4(uint32_t& r0, uint32_t& r1,
                                        uint32_t& r2, uint32_t& r3,
                                        uint32_t addr) {
    asm volatile(
        "ldmatrix.sync.aligned.m8n8.x4.shared.b16 {%0,%1,%2,%3}, [%4];"
        : "=r"(r0), "=r"(r1), "=r"(r2), "=r"(r3) : "r"(addr));
}

__device__ __forceinline__ void ldsm_x4_trans(uint32_t& r0, uint32_t& r1,
                                              uint32_t& r2, uint32_t& r3,
                                              uint32_t addr) {
    asm volatile(
        "ldmatrix.sync.aligned.m8n8.x4.trans.shared.b16 {%0,%1,%2,%3}, [%4];"
        : "=r"(r0), "=r"(r1), "=r"(r2), "=r"(r3) : "r"(addr));
}

__device__ __forceinline__ uint32_t pack_h2(float lo, float hi) {
    __half2 h = __floats2half2_rn(lo, hi);
    return *reinterpret_cast<uint32_t*>(&h);
}

__device__ __forceinline__ float fast_exp2(float x) {
    float r;
    asm("ex2.approx.ftz.f32 %0, %1;" : "=f"(r) : "f"(x));
    return r;
}

__device__ __forceinline__ uint32_t smem_u32(const void* p) {
    return (uint32_t)__cvta_generic_to_shared(p);
}

// ---------------------------------------------------------------------------
// fp32 -> fp16 conversion (elementwise), n4 = numel/4
// ---------------------------------------------------------------------------
__global__ void __launch_bounds__(256)
cvt_f32_f16(const float* __restrict__ in, __half* __restrict__ out, int n4)
{
    int i = blockIdx.x * blockDim.x + threadIdx.x;
    if (i < n4) {
        float4 v = reinterpret_cast<const float4*>(in)[i];
        __half2 h0 = __floats2half2_rn(v.x, v.y);
        __half2 h1 = __floats2half2_rn(v.z, v.w);
        uint2 u;
        u.x = *reinterpret_cast<uint32_t*>(&h0);
        u.y = *reinterpret_cast<uint32_t*>(&h1);
        reinterpret_cast<uint2*>(out)[i] = u;
    }
}

// ---------------------------------------------------------------------------
// fp16-in tensor-core GEMM with bias: C[M,N] = A[M,K] @ B[K,N] + bias[N]
// BM=BN=128, BK=32, 256 threads (8 warps), warp tile 64x32 (m16n8k16).
// 2-stage smem double buffer + register prefetch (LDG kept on L1 path).
// One __syncthreads per slab. __launch_bounds__(256,2) for 2 blocks/SM.
// ---------------------------------------------------------------------------
template<bool HALF_OUT>
__global__ void __launch_bounds__(256, 2)
gemm_h_kernel(const __half* __restrict__ A, const __half* __restrict__ B,
              const float* __restrict__ bias, void* __restrict__ Cout,
              int M, int N, int K, int qcols, float qsc)
{
    __shared__ __half As[2][128][40];   // 20480 B
    __shared__ __half Bs[2][32][136];   // 17408 B

    const int tid = threadIdx.x;
    const int wid = tid >> 5;
    const int lane = tid & 31;
    const int g = lane >> 2;
    const int t4 = lane & 3;
    const int wm = wid >> 2;
    const int wn = wid & 3;
    const int bx = blockIdx.x, by = blockIdx.y;
    const int mrow = lane & 7;
    const int mid  = lane >> 3;

    const uint32_t abase = smem_u32(
        &As[0][wm * 64 + (mid & 1) * 8 + mrow][(mid >> 1) * 8]);
    const uint32_t bbase = smem_u32(
        &Bs[0][(mid & 1) * 8 + mrow][wn * 32 + (mid >> 1) * 8]);
    const uint32_t a_ststride = 128 * 40 * 2;   // bytes per A stage
    const uint32_t b_ststride = 32 * 136 * 2;   // bytes per B stage

    // staging coords
    const int ar = tid >> 2;            // rows ar, ar+64
    const int ach = tid & 3;
    const int br = tid >> 4;            // rows br, br+16
    const int bch = tid & 15;

    const __half* aG = A + (size_t)(by * 128 + ar) * K + ach * 8;
    const __half* bG = B + (size_t)br * N + bx * 128 + bch * 8;
    const size_t aRow64 = (size_t)64 * K;
    const size_t bRow16 = (size_t)16 * N;

    uint4 pa0, pa1, pb0, pb1;
    auto ldg_slab = [&](int k0) {
        pa0 = *reinterpret_cast<const uint4*>(aG + k0);
        pa1 = *reinterpret_cast<const uint4*>(aG + aRow64 + k0);
        pb0 = *reinterpret_cast<const uint4*>(bG + (size_t)k0 * N);
        pb1 = *reinterpret_cast<const uint4*>(bG + (size_t)k0 * N + bRow16);
    };
    auto sts_slab = [&](int st) {
        *reinterpret_cast<uint4*>(&As[st][ar][ach * 8])      = pa0;
        *reinterpret_cast<uint4*>(&As[st][ar + 64][ach * 8]) = pa1;
        *reinterpret_cast<uint4*>(&Bs[st][br][bch * 8])      = pb0;
        *reinterpret_cast<uint4*>(&Bs[st][br + 16][bch * 8]) = pb1;
    };

    float acc[4][4][4];
    #pragma unroll
    for (int mt = 0; mt < 4; mt++)
        #pragma unroll
        for (int nt = 0; nt < 4; nt++)
            #pragma unroll
            for (int i = 0; i < 4; i++) acc[mt][nt][i] = 0.f;

    const int steps = K >> 5;
    ldg_slab(0);
    sts_slab(0);
    __syncthreads();

    for (int s = 0; s < steps; s++) {
        if (s + 1 < steps) ldg_slab((s + 1) << 5);   // LDG issued before compute

        const uint32_t ab = abase + (uint32_t)(s & 1) * a_ststride;
        const uint32_t bb = bbase + (uint32_t)(s & 1) * b_ststride;
        #pragma unroll
        for (int kk = 0; kk < 32; kk += 16) {
            uint32_t afr[4][4], bfr[4][2];
            #pragma unroll
            for (int mt = 0; mt < 4; mt++)
                ldsm_x4(afr[mt][0], afr[mt][1], afr[mt][2], afr[mt][3],
                        ab + (uint32_t)(mt * 16 * 40 + kk) * 2);
            #pragma unroll
            for (int p = 0; p < 2; p++) {
                uint32_t r0, r1, r2, r3;
                ldsm_x4_trans(r0, r1, r2, r3,
                              bb + (uint32_t)(kk * 136 + p * 16) * 2);
                bfr[2 * p][0] = r0; bfr[2 * p][1] = r1;
                bfr[2 * p + 1][0] = r2; bfr[2 * p + 1][1] = r3;
            }
            #pragma unroll
            for (int mt = 0; mt < 4; mt++)
                #pragma unroll
                for (int nt = 0; nt < 4; nt++)
                    mma_f16(acc[mt][nt], afr[mt], bfr[nt][0], bfr[nt][1]);
        }

        if (s + 1 < steps) sts_slab((s + 1) & 1);
        __syncthreads();
    }

    // ---- epilogue ----
    float osc = 1.f;
    if (HALF_OUT) osc = (bx * 128 < qcols) ? qsc : 1.f;

    #pragma unroll
    for (int nt = 0; nt < 4; nt++) {
        const int col = bx * 128 + wn * 32 + nt * 8 + 2 * t4;
        const float b0 = bias[col], b1 = bias[col + 1];
        #pragma unroll
        for (int mt = 0; mt < 4; mt++) {
            const int row = by * 128 + wm * 64 + mt * 16 + g;
            if (HALF_OUT) {
                __half* Ch = (__half*)Cout;
                uint32_t v0 = pack_h2((acc[mt][nt][0] + b0) * osc,
                                      (acc[mt][nt][1] + b1) * osc);
                uint32_t v1 = pack_h2((acc[mt][nt][2] + b0) * osc,
                                      (acc[mt][nt][3] + b1) * osc);
                *reinterpret_cast<uint32_t*>(&Ch[(size_t)row * N + col]) = v0;
                *reinterpret_cast<uint32_t*>(&Ch[(size_t)(row + 8) * N + col]) = v1;
            } else {
                float* Cf = (float*)Cout;
                float2 o0 = make_float2(acc[mt][nt][0] + b0, acc[mt][nt][1] + b1);
                float2 o1 = make_float2(acc[mt][nt][2] + b0, acc[mt][nt][3] + b1);
                *reinterpret_cast<float2*>(Cf + (size_t)row * N + col) = o0;
                *reinterpret_cast<float2*>(Cf + (size_t)(row + 8) * N + col) = o1;
            }
        }
    }
}

// ---------------------------------------------------------------------------
// Flash attention (causal), fp16 end-to-end, double-buffered K/V.
// grid = (T/128, B*H), 256 threads (8 warps). Br=128, Bc=64, D=64.
// Dynamic smem: Q[128][72] + K[2][64][72] + V[2][64][72] = 55296 B.
// Register-prefetched K/V tiles, one __syncthreads per KV tile.
// ---------------------------------------------------------------------------
#define QH_HALFS (128 * 72)
#define KV_HALFS (64 * 72)
#define ATTN_SMEM ((QH_HALFS + 4 * KV_HALFS) * 2)

__global__ void __launch_bounds__(256)
attn_mma_kernel(const __half* __restrict__ qkvh, __half* __restrict__ outh)
{
    extern __shared__ __half smh[];
    __half* Qh = smh;                               // [128][72]
    __half* Kh = smh + QH_HALFS;                    // [2][64][72]
    __half* Vh = smh + QH_HALFS + 2 * KV_HALFS;     // [2][64][72]

    const int bh = blockIdx.y;
    const int b = bh / H_;
    const int h = bh % H_;
    const int qtile = gridDim.x - 1 - blockIdx.x;   // big tiles first
    const int tid = threadIdx.x;
    const int w = tid >> 5;
    const int lane = tid & 31;
    const int g = lane >> 2;
    const int t4 = lane & 3;
    const int mrow = lane & 7;
    const int mid  = lane >> 3;

    // ldmatrix bases (stage 0); stage stride in bytes
    const uint32_t kfb = smem_u32(&Kh[((mid >> 1) * 8 + mrow) * 72 + (mid & 1) * 8]);
    const uint32_t vfb = smem_u32(&Vh[((mid & 1) * 8 + mrow) * 72 + (mid >> 1) * 8]);
    const uint32_t kvstride = KV_HALFS * 2;

    // ---- stage Q tile (pure copy; already fp16 + pre-scaled) ----
    #pragma unroll
    for (int i = 0; i < 4; i++) {
        const int c = tid + i * 256;          // 0..1023
        const int r = c >> 3;                 // 0..127
        const int ch = c & 7;
        *reinterpret_cast<uint4*>(&Qh[r * 72 + ch * 8]) =
            *reinterpret_cast<const uint4*>(
                qkvh + (size_t)(b * T_ + qtile * 128 + r) * N_QKV + h * D_ + ch * 8);
    }

    // ---- K/V prefetch machinery ----
    const int kvr = tid >> 3;              // rows kvr, kvr+32
    const int kvch = tid & 7;
    const __half* kvG = qkvh + (size_t)(b * T_ + kvr) * N_QKV + h * D_ + kvch * 8;
    const size_t row32 = (size_t)32 * N_QKV;

    uint4 pk0, pk1, pv0, pv1;
    auto ldg_kv = [&](int kbase) {
        const __half* s0 = kvG + (size_t)kbase * N_QKV;
        pk0 = *reinterpret_cast<const uint4*>(s0 + C_);
        pv0 = *reinterpret_cast<const uint4*>(s0 + 2 * C_);
        pk1 = *reinterpret_cast<const uint4*>(s0 + row32 + C_);
        pv1 = *reinterpret_cast<const uint4*>(s0 + row32 + 2 * C_);
    };
    auto sts_kv = [&](int st) {
        *reinterpret_cast<uint4*>(&Kh[st * KV_HALFS + kvr * 72 + kvch * 8]) = pk0;
        *reinterpret_cast<uint4*>(&Kh[st * KV_HALFS + (kvr + 32) * 72 + kvch * 8]) = pk1;
        *reinterpret_cast<uint4*>(&Vh[st * KV_HALFS + kvr * 72 + kvch * 8]) = pv0;
        *reinterpret_cast<uint4*>(&Vh[st * KV_HALFS + (kvr + 32) * 72 + kvch * 8]) = pv1;
    };

    ldg_kv(0);
    sts_kv(0);
    __syncthreads();      // Q + stage-0 K/V visible

    // ---- Q fragments ----
    uint32_t Qa[4][4];
    {
        const int row = w * 16;
        #pragma unroll
        for (int kc = 0; kc < 4; kc++) {
            const int k0 = kc * 16 + 2 * t4;
            Qa[kc][0] = *reinterpret_cast<const uint32_t*>(&Qh[(row + g) * 72 + k0]);
            Qa[kc][1] = *reinterpret_cast<const uint32_t*>(&Qh[(row + g + 8) * 72 + k0]);
            Qa[kc][2] = *reinterpret_cast<const uint32_t*>(&Qh[(row + g) * 72 + k0 + 8]);
            Qa[kc][3] = *reinterpret_cast<const uint32_t*>(&Qh[(row + g + 8) * 72 + k0 + 8]);
        }
    }

    float o[8][4];
    #pragma unroll
    for (int nt = 0; nt < 8; nt++)
        #pragma unroll
        for (int i = 0; i < 4; i++) o[nt][i] = 0.f;
    float m0 = -1e30f, m1 = -1e30f, l0 = 0.f, l1 = 0.f;

    const int q0g = qtile * 128 + w * 16 + g;
    const int ntiles = 2 * qtile + 2;

    for (int kt = 0; kt < ntiles; kt++) {
        const int kbase = kt * 64;
        if (kt + 1 < ntiles) ldg_kv((kt + 1) * 64);   // LDG before compute

        const uint32_t kb = kfb + (uint32_t)(kt & 1) * kvstride;
        const uint32_t vb = vfb + (uint32_t)(kt & 1) * kvstride;

        // ---- S = Q @ K^T ----
        float s_[8][4];
        #pragma unroll
        for (int nt = 0; nt < 8; nt++)
            #pragma unroll
            for (int i = 0; i < 4; i++) s_[nt][i] = 0.f;
        #pragma unroll
        for (int kc = 0; kc < 4; kc++) {
            #pragma unroll
            for (int np = 0; np < 4; np++) {
                uint32_t r0, r1, r2, r3;
                ldsm_x4(r0, r1, r2, r3,
                        kb + (uint32_t)(np * 16 * 72 + kc * 16) * 2);
                mma_f16(s_[2 * np],     Qa[kc], r0, r1);
                mma_f16(s_[2 * np + 1], Qa[kc], r2, r3);
            }
        }

        // ---- causal mask ----
        if (kbase + 63 > q0g) {
            #pragma unroll
            for (int nt = 0; nt < 8; nt++) {
                const int c0 = kbase + nt * 8 + 2 * t4;
                if (c0 > q0g)         s_[nt][0] = -1e30f;
                if (c0 + 1 > q0g)     s_[nt][1] = -1e30f;
                if (c0 > q0g + 8)     s_[nt][2] = -1e30f;
                if (c0 + 1 > q0g + 8) s_[nt][3] = -1e30f;
            }
        }

        // ---- online softmax (base-2) ----
        float mx0 = -1e30f, mx1 = -1e30f;
        #pragma unroll
        for (int nt = 0; nt < 8; nt++) {
            mx0 = fmaxf(mx0, fmaxf(s_[nt][0], s_[nt][1]));
            mx1 = fmaxf(mx1, fmaxf(s_[nt][2], s_[nt][3]));
        }
        mx0 = fmaxf(mx0, __shfl_xor_sync(0xffffffff, mx0, 1));
        mx0 = fmaxf(mx0, __shfl_xor_sync(0xffffffff, mx0, 2));
        mx1 = fmaxf(mx1, __shfl_xor_sync(0xffffffff, mx1, 1));
        mx1 = fmaxf(mx1, __shfl_xor_sync(0xffffffff, mx1, 2));
        const float nm0 = fmaxf(m0, mx0), nm1 = fmaxf(m1, mx1);
        const float sc0 = fast_exp2(m0 - nm0), sc1 = fast_exp2(m1 - nm1);
        m0 = nm0; m1 = nm1;

        float rs0 = 0.f, rs1 = 0.f;
        #pragma unroll
        for (int nt = 0; nt < 8; nt++) {
            s_[nt][0] = fast_exp2(s_[nt][0] - m0); rs0 += s_[nt][0];
            s_[nt][1] = fast_exp2(s_[nt][1] - m0); rs0 += s_[nt][1];
            s_[nt][2] = fast_exp2(s_[nt][2] - m1); rs1 += s_[nt][2];
            s_[nt][3] = fast_exp2(s_[nt][3] - m1); rs1 += s_[nt][3];
        }
        rs0 += __shfl_xor_sync(0xffffffff, rs0, 1);
        rs0 += __shfl_xor_sync(0xffffffff, rs0, 2);
        rs1 += __shfl_xor_sync(0xffffffff, rs1, 1);
        rs1 += __shfl_xor_sync(0xffffffff, rs1, 2);
        l0 = l0 * sc0 + rs0;
        l1 = l1 * sc1 + rs1;

        #pragma unroll
        for (int nt = 0; nt < 8; nt++) {
            o[nt][0] *= sc0; o[nt][1] *= sc0;
            o[nt][2] *= sc1; o[nt][3] *= sc1;
        }

        // ---- O += P @ V ----
        #pragma unroll
        for (int kc = 0; kc < 4; kc++) {
            uint32_t pa[4];
            pa[0] = pack_h2(s_[2 * kc][0], s_[2 * kc][1]);
            pa[1] = pack_h2(s_[2 * kc][2], s_[2 * kc][3]);
            pa[2] = pack_h2(s_[2 * kc + 1][0], s_[2 * kc + 1][1]);
            pa[3] = pack_h2(s_[2 * kc + 1][2], s_[2 * kc + 1][3]);
            #pragma unroll
            for (int p = 0; p < 4; p++) {
                uint32_t v0, v1, v2, v3;
                ldsm_x4_trans(v0, v1, v2, v3,
                              vb + (uint32_t)(kc * 16 * 72 + p * 16) * 2);
                mma_f16(o[2 * p],     pa, v0, v1);
                mma_f16(o[2 * p + 1], pa, v2, v3);
            }
        }

        if (kt + 1 < ntiles) sts_kv((kt + 1) & 1);
        __syncthreads();
    }

    // ---- normalize + store (fp16) ----
    const float inv0 = 1.f / l0, inv1 = 1.f / l1;
    const size_t row0 = (size_t)(b * T_ + qtile * 128 + w * 16 + g);
    const size_t row1 = row0 + 8;
    #pragma unroll
    for (int nt = 0; nt < 8; nt++) {
        const int col = h * D_ + nt * 8 + 2 * t4;
        uint32_t v0 = pack_h2(o[nt][0] * inv0, o[nt][1] * inv0);
        uint32_t v1 = pack_h2(o[nt][2] * inv1, o[nt][3] * inv1);
        *reinterpret_cast<uint32_t*>(&outh[row0 * C_ + col]) = v0;
        *reinterpret_cast<uint32_t*>(&outh[row1 * C_ + col]) = v1;
    }
}

// ---------------------------------------------------------------------------
// Launch
// ---------------------------------------------------------------------------
extern "C" void kernel_launch(void* const* d_in, const int* in_sizes, int n_in,
                              void* d_out, int out_size)
{
    const float* x    = (const float*)d_in[0];
    const float* Wqkv = (const float*)d_in[1];
    const float* bqkv = (const float*)d_in[2];
    const float* Wout = (const float*)d_in[3];
    const float* bout = (const float*)d_in[4];
    float* out = (float*)d_out;

    __half *xh, *wqkvh, *wouth, *qkvh, *attnh;
    cudaGetSymbolAddress((void**)&xh,    g_xh);
    cudaGetSymbolAddress((void**)&wqkvh, g_wqkvh);
    cudaGetSymbolAddress((void**)&wouth, g_wouth);
    cudaGetSymbolAddress((void**)&qkvh,  g_qkvh);
    cudaGetSymbolAddress((void**)&attnh, g_attnh);

    cudaFuncSetAttribute(attn_mma_kernel,
                         cudaFuncAttributeMaxDynamicSharedMemorySize, ATTN_SMEM);

    // 0) fp32 -> fp16 conversions
    {
        const int n0 = M_ * C_ / 4;
        const int n1 = C_ * N_QKV / 4;
        const int n2 = C_ * C_ / 4;
        cvt_f32_f16<<<(n0 + 255) / 256, 256>>>(x, xh, n0);
        cvt_f32_f16<<<(n1 + 255) / 256, 256>>>(Wqkv, wqkvh, n1);
        cvt_f32_f16<<<(n2 + 255) / 256, 256>>>(Wout, wouth, n2);
    }

    // 1) QKV projection (fp16 out, Q columns pre-scaled by QSCALE)
    {
        dim3 grid(N_QKV / 128, M_ / 128);
        gemm_h_kernel<true><<<grid, 256>>>(xh, wqkvh, bqkv, qkvh,
                                           M_, N_QKV, C_, C_, (float)QSCALE);
    }
    // 2) Causal attention (flash, fp16 tensor cores, fp16 out)
    {
        dim3 grid(T_ / 128, B_ * H_);
        attn_mma_kernel<<<grid, 256, ATTN_SMEM>>>(qkvh, attnh);
    }
    // 3) Output projection (fp32 out)
    {
        dim3 grid(C_ / 128, M_ / 128);
        gemm_h_kernel<false><<<grid, 256>>>(attnh, wouth, bout, out,
                                            M_, C_, C_, 0, 1.f);
    }
}

// round 10
// speedup vs baseline: 3.2833x; 1.0453x over previous
#include <cuda_runtime.h>
#include <cuda_fp16.h>
#include <cstdint>
#include <cstddef>

#define B_ 2
#define T_ 4096
#define C_ 768
#define H_ 12
#define D_ 64
#define M_ (B_*T_)          // 8192
#define N_QKV (3*C_)        // 2304
// softmax scale folded with log2(e) so we can use ex2
#define QSCALE (0.125f * 1.4426950408889634f)

// fp16 scratch (allocation-free requirement -> __device__ globals)
__device__ __half g_xh[(size_t)M_ * C_];
__device__ __half g_wqkvh[(size_t)C_ * N_QKV];
__device__ __half g_wouth[(size_t)C_ * C_];
__device__ __half g_qkvh[(size_t)M_ * N_QKV];   // Q part pre-scaled by QSCALE
__device__ __half g_attnh[(size_t)M_ * C_];

// ---------------------------------------------------------------------------
// Helpers
// ---------------------------------------------------------------------------
__device__ __forceinline__ void mma_f16(float* c, const uint32_t* a,
                                        uint32_t b0, uint32_t b1) {
    asm volatile(
        "mma.sync.aligned.m16n8k16.row.col.f32.f16.f16.f32 "
        "{%0,%1,%2,%3},{%4,%5,%6,%7},{%8,%9},{%0,%1,%2,%3};"
        : "+f"(c[0]), "+f"(c[1]), "+f"(c[2]), "+f"(c[3])
        : "r"(a[0]), "r"(a[1]), "r"(a[2]), "r"(a[3]), "r"(b0), "r"(b1));
}

__device__ __forceinline__ void ldsm_x4(uint32_t& r0, uint32_t& r1,
                                        uint32_t& r2, uint32_t& r3,
                                        uint32_t addr) {
    asm volatile(
        "ldmatrix.sync.aligned.m8n8.x4.shared.b16 {%0,%1,%2,%3}, [%4];"
        : "=r"(r0), "=r"(r1), "=r"(r2), "=r"(r3) : "r"(addr));
}

__device__ __forceinline__ void ldsm_x4_trans(uint32_t& r0, uint32_t& r1,
                                              uint32_t& r2, uint32_t& r3,
                                              uint32_t addr) {
    asm volatile(
        "ldmatrix.sync.aligned.m8n8.x4.trans.shared.b16 {%0,%1,%2,%3}, [%4];"
        : "=r"(r0), "=r"(r1), "=r"(r2), "=r"(r3) : "r"(addr));
}

__device__ __forceinline__ uint32_t pack_h2(float lo, float hi) {
    __half2 h = __floats2half2_rn(lo, hi);
    return *reinterpret_cast<uint32_t*>(&h);
}

__device__ __forceinline__ float fast_exp2(float x) {
    float r;
    asm("ex2.approx.ftz.f32 %0, %1;" : "=f"(r) : "f"(x));
    return r;
}

__device__ __forceinline__ uint32_t smem_u32(const void* p) {
    return (uint32_t)__cvta_generic_to_shared(p);
}

// ---------------------------------------------------------------------------
// fp32 -> fp16 conversion (elementwise), n4 = numel/4
// ---------------------------------------------------------------------------
__global__ void __launch_bounds__(256)
cvt_f32_f16(const float* __restrict__ in, __half* __restrict__ out, int n4)
{
    int i = blockIdx.x * blockDim.x + threadIdx.x;
    if (i < n4) {
        float4 v = reinterpret_cast<const float4*>(in)[i];
        __half2 h0 = __floats2half2_rn(v.x, v.y);
        __half2 h1 = __floats2half2_rn(v.z, v.w);
        uint2 u;
        u.x = *reinterpret_cast<uint32_t*>(&h0);
        u.y = *reinterpret_cast<uint32_t*>(&h1);
        reinterpret_cast<uint2*>(out)[i] = u;
    }
}

// ---------------------------------------------------------------------------
// fp16-in tensor-core GEMM with bias (round-9 proven version):
// C[M,N] = A[M,K] @ B[K,N] + bias[N]
// BM=BN=128, BK=32, 256 threads (8 warps), warp tile 64x32 (m16n8k16).
// 2-stage smem double buffer + register prefetch, 2 CTAs/SM.
// ---------------------------------------------------------------------------
template<bool HALF_OUT>
__global__ void __launch_bounds__(256, 2)
gemm_h_kernel(const __half* __restrict__ A, const __half* __restrict__ B,
              const float* __restrict__ bias, void* __restrict__ Cout,
              int M, int N, int K, int qcols, float qsc)
{
    __shared__ __half As[2][128][40];   // 20480 B
    __shared__ __half Bs[2][32][136];   // 17408 B

    const int tid = threadIdx.x;
    const int wid = tid >> 5;
    const int lane = tid & 31;
    const int g = lane >> 2;
    const int t4 = lane & 3;
    const int wm = wid >> 2;
    const int wn = wid & 3;
    const int bx = blockIdx.x, by = blockIdx.y;
    const int mrow = lane & 7;
    const int mid  = lane >> 3;

    const uint32_t abase = smem_u32(
        &As[0][wm * 64 + (mid & 1) * 8 + mrow][(mid >> 1) * 8]);
    const uint32_t bbase = smem_u32(
        &Bs[0][(mid & 1) * 8 + mrow][wn * 32 + (mid >> 1) * 8]);
    const uint32_t a_ststride = 128 * 40 * 2;   // bytes per A stage
    const uint32_t b_ststride = 32 * 136 * 2;   // bytes per B stage

    // staging coords
    const int ar = tid >> 2;            // rows ar, ar+64
    const int ach = tid & 3;
    const int br = tid >> 4;            // rows br, br+16
    const int bch = tid & 15;

    const __half* aG = A + (size_t)(by * 128 + ar) * K + ach * 8;
    const __half* bG = B + (size_t)br * N + bx * 128 + bch * 8;
    const size_t aRow64 = (size_t)64 * K;
    const size_t bRow16 = (size_t)16 * N;

    uint4 pa0, pa1, pb0, pb1;
    auto ldg_slab = [&](int k0) {
        pa0 = *reinterpret_cast<const uint4*>(aG + k0);
        pa1 = *reinterpret_cast<const uint4*>(aG + aRow64 + k0);
        pb0 = *reinterpret_cast<const uint4*>(bG + (size_t)k0 * N);
        pb1 = *reinterpret_cast<const uint4*>(bG + (size_t)k0 * N + bRow16);
    };
    auto sts_slab = [&](int st) {
        *reinterpret_cast<uint4*>(&As[st][ar][ach * 8])      = pa0;
        *reinterpret_cast<uint4*>(&As[st][ar + 64][ach * 8]) = pa1;
        *reinterpret_cast<uint4*>(&Bs[st][br][bch * 8])      = pb0;
        *reinterpret_cast<uint4*>(&Bs[st][br + 16][bch * 8]) = pb1;
    };

    float acc[4][4][4];
    #pragma unroll
    for (int mt = 0; mt < 4; mt++)
        #pragma unroll
        for (int nt = 0; nt < 4; nt++)
            #pragma unroll
            for (int i = 0; i < 4; i++) acc[mt][nt][i] = 0.f;

    const int steps = K >> 5;
    ldg_slab(0);
    sts_slab(0);
    __syncthreads();

    for (int s = 0; s < steps; s++) {
        if (s + 1 < steps) ldg_slab((s + 1) << 5);   // LDG issued before compute

        const uint32_t ab = abase + (uint32_t)(s & 1) * a_ststride;
        const uint32_t bb = bbase + (uint32_t)(s & 1) * b_ststride;
        #pragma unroll
        for (int kk = 0; kk < 32; kk += 16) {
            uint32_t afr[4][4], bfr[4][2];
            #pragma unroll
            for (int mt = 0; mt < 4; mt++)
                ldsm_x4(afr[mt][0], afr[mt][1], afr[mt][2], afr[mt][3],
                        ab + (uint32_t)(mt * 16 * 40 + kk) * 2);
            #pragma unroll
            for (int p = 0; p < 2; p++) {
                uint32_t r0, r1, r2, r3;
                ldsm_x4_trans(r0, r1, r2, r3,
                              bb + (uint32_t)(kk * 136 + p * 16) * 2);
                bfr[2 * p][0] = r0; bfr[2 * p][1] = r1;
                bfr[2 * p + 1][0] = r2; bfr[2 * p + 1][1] = r3;
            }
            #pragma unroll
            for (int mt = 0; mt < 4; mt++)
                #pragma unroll
                for (int nt = 0; nt < 4; nt++)
                    mma_f16(acc[mt][nt], afr[mt], bfr[nt][0], bfr[nt][1]);
        }

        if (s + 1 < steps) sts_slab((s + 1) & 1);
        __syncthreads();
    }

    // ---- epilogue ----
    float osc = 1.f;
    if (HALF_OUT) osc = (bx * 128 < qcols) ? qsc : 1.f;

    #pragma unroll
    for (int nt = 0; nt < 4; nt++) {
        const int col = bx * 128 + wn * 32 + nt * 8 + 2 * t4;
        const float b0 = bias[col], b1 = bias[col + 1];
        #pragma unroll
        for (int mt = 0; mt < 4; mt++) {
            const int row = by * 128 + wm * 64 + mt * 16 + g;
            if (HALF_OUT) {
                __half* Ch = (__half*)Cout;
                uint32_t v0 = pack_h2((acc[mt][nt][0] + b0) * osc,
                                      (acc[mt][nt][1] + b1) * osc);
                uint32_t v1 = pack_h2((acc[mt][nt][2] + b0) * osc,
                                      (acc[mt][nt][3] + b1) * osc);
                *reinterpret_cast<uint32_t*>(&Ch[(size_t)row * N + col]) = v0;
                *reinterpret_cast<uint32_t*>(&Ch[(size_t)(row + 8) * N + col]) = v1;
            } else {
                float* Cf = (float*)Cout;
                float2 o0 = make_float2(acc[mt][nt][0] + b0, acc[mt][nt][1] + b1);
                float2 o1 = make_float2(acc[mt][nt][2] + b0, acc[mt][nt][3] + b1);
                *reinterpret_cast<float2*>(Cf + (size_t)row * N + col) = o0;
                *reinterpret_cast<float2*>(Cf + (size_t)(row + 8) * N + col) = o1;
            }
        }
    }
}

// ---------------------------------------------------------------------------
// Flash attention (causal), fp16 end-to-end (round-8 structure + 2 CTAs/SM).
// grid = (T/128, B*H), 256 threads (8 warps). Br=128, Bc=64, D=64.
// Static smem 36864 B -> 2 CTAs/SM fit; regs capped at 128.
// K frags: ldmatrix.x4 (non-trans), V frags: ldmatrix.x4.trans.
// ---------------------------------------------------------------------------
__global__ void __launch_bounds__(256, 2)
attn_mma_kernel(const __half* __restrict__ qkvh, __half* __restrict__ outh)
{
    __shared__ __half Qh[128][72];   // 18432 B
    __shared__ __half Kh[64][72];    //  9216 B
    __shared__ __half Vh[64][72];    //  9216 B

    const int bh = blockIdx.y;
    const int b = bh / H_;
    const int h = bh % H_;
    const int qtile = gridDim.x - 1 - blockIdx.x;   // big tiles first
    const int tid = threadIdx.x;
    const int w = tid >> 5;
    const int lane = tid & 31;
    const int g = lane >> 2;
    const int t4 = lane & 3;
    const int mrow = lane & 7;
    const int mid  = lane >> 3;

    // ldmatrix bases
    const uint32_t kfb = smem_u32(&Kh[(mid >> 1) * 8 + mrow][(mid & 1) * 8]);
    const uint32_t vfb = smem_u32(&Vh[(mid & 1) * 8 + mrow][(mid >> 1) * 8]);

    // ---- stage Q tile (pure copy; already fp16 + pre-scaled) ----
    #pragma unroll
    for (int i = 0; i < 4; i++) {
        const int c = tid + i * 256;          // 0..1023
        const int r = c >> 3;                 // 0..127
        const int ch = c & 7;
        *reinterpret_cast<uint4*>(&Qh[r][ch * 8]) =
            *reinterpret_cast<const uint4*>(
                qkvh + (size_t)(b * T_ + qtile * 128 + r) * N_QKV + h * D_ + ch * 8);
    }
    __syncthreads();

    // ---- Q fragments: 4 k16-chunks x 4 half2 regs (conflict-free LDS) ----
    uint32_t Qa[4][4];
    {
        const int row = w * 16;
        #pragma unroll
        for (int kc = 0; kc < 4; kc++) {
            const int k0 = kc * 16 + 2 * t4;
            Qa[kc][0] = *reinterpret_cast<const uint32_t*>(&Qh[row + g][k0]);
            Qa[kc][1] = *reinterpret_cast<const uint32_t*>(&Qh[row + g + 8][k0]);
            Qa[kc][2] = *reinterpret_cast<const uint32_t*>(&Qh[row + g][k0 + 8]);
            Qa[kc][3] = *reinterpret_cast<const uint32_t*>(&Qh[row + g + 8][k0 + 8]);
        }
    }

    float o[8][4];
    #pragma unroll
    for (int nt = 0; nt < 8; nt++)
        #pragma unroll
        for (int i = 0; i < 4; i++) o[nt][i] = 0.f;
    float m0 = -1e30f, m1 = -1e30f, l0 = 0.f, l1 = 0.f;

    const int q0g = qtile * 128 + w * 16 + g;   // own query row (second is +8)
    const int ntiles = 2 * qtile + 2;

    for (int kt = 0; kt < ntiles; kt++) {
        const int kbase = kt * 64;
        __syncthreads();    // previous tile's consumers done
        // ---- stage K/V tiles (pure copies) ----
        #pragma unroll
        for (int i = 0; i < 2; i++) {
            const int c = tid + i * 256;      // 0..511
            const int r = c >> 3;             // 0..63
            const int ch = c & 7;
            const __half* src =
                qkvh + (size_t)(b * T_ + kbase + r) * N_QKV + h * D_ + ch * 8;
            *reinterpret_cast<uint4*>(&Kh[r][ch * 8]) =
                *reinterpret_cast<const uint4*>(src + C_);
            *reinterpret_cast<uint4*>(&Vh[r][ch * 8]) =
                *reinterpret_cast<const uint4*>(src + 2 * C_);
        }
        __syncthreads();

        // ---- S = Q @ K^T (16x64 per warp); K frags via ldmatrix.x4 ----
        float s_[8][4];
        #pragma unroll
        for (int nt = 0; nt < 8; nt++)
            #pragma unroll
            for (int i = 0; i < 4; i++) s_[nt][i] = 0.f;
        #pragma unroll
        for (int kc = 0; kc < 4; kc++) {
            #pragma unroll
            for (int np = 0; np < 4; np++) {
                uint32_t r0, r1, r2, r3;
                ldsm_x4(r0, r1, r2, r3,
                        kfb + (uint32_t)(np * 16 * 72 + kc * 16) * 2);
                mma_f16(s_[2 * np],     Qa[kc], r0, r1);
                mma_f16(s_[2 * np + 1], Qa[kc], r2, r3);
            }
        }

        // ---- causal mask (tiles overlapping/above the diagonal) ----
        if (kbase + 63 > q0g) {
            #pragma unroll
            for (int nt = 0; nt < 8; nt++) {
                const int c0 = kbase + nt * 8 + 2 * t4;
                if (c0 > q0g)         s_[nt][0] = -1e30f;
                if (c0 + 1 > q0g)     s_[nt][1] = -1e30f;
                if (c0 > q0g + 8)     s_[nt][2] = -1e30f;
                if (c0 + 1 > q0g + 8) s_[nt][3] = -1e30f;
            }
        }

        // ---- online softmax (base-2) ----
        float mx0 = -1e30f, mx1 = -1e30f;
        #pragma unroll
        for (int nt = 0; nt < 8; nt++) {
            mx0 = fmaxf(mx0, fmaxf(s_[nt][0], s_[nt][1]));
            mx1 = fmaxf(mx1, fmaxf(s_[nt][2], s_[nt][3]));
        }
        mx0 = fmaxf(mx0, __shfl_xor_sync(0xffffffff, mx0, 1));
        mx0 = fmaxf(mx0, __shfl_xor_sync(0xffffffff, mx0, 2));
        mx1 = fmaxf(mx1, __shfl_xor_sync(0xffffffff, mx1, 1));
        mx1 = fmaxf(mx1, __shfl_xor_sync(0xffffffff, mx1, 2));
        const float nm0 = fmaxf(m0, mx0), nm1 = fmaxf(m1, mx1);
        const float sc0 = fast_exp2(m0 - nm0), sc1 = fast_exp2(m1 - nm1);
        m0 = nm0; m1 = nm1;

        float rs0 = 0.f, rs1 = 0.f;
        #pragma unroll
        for (int nt = 0; nt < 8; nt++) {
            s_[nt][0] = fast_exp2(s_[nt][0] - m0); rs0 += s_[nt][0];
            s_[nt][1] = fast_exp2(s_[nt][1] - m0); rs0 += s_[nt][1];
            s_[nt][2] = fast_exp2(s_[nt][2] - m1); rs1 += s_[nt][2];
            s_[nt][3] = fast_exp2(s_[nt][3] - m1); rs1 += s_[nt][3];
        }
        rs0 += __shfl_xor_sync(0xffffffff, rs0, 1);
        rs0 += __shfl_xor_sync(0xffffffff, rs0, 2);
        rs1 += __shfl_xor_sync(0xffffffff, rs1, 1);
        rs1 += __shfl_xor_sync(0xffffffff, rs1, 2);
        l0 = l0 * sc0 + rs0;
        l1 = l1 * sc1 + rs1;

        #pragma unroll
        for (int nt = 0; nt < 8; nt++) {
            o[nt][0] *= sc0; o[nt][1] *= sc0;
            o[nt][2] *= sc1; o[nt][3] *= sc1;
        }

        // ---- O += P @ V (V frags via ldmatrix.x4.trans) ----
        #pragma unroll
        for (int kc = 0; kc < 4; kc++) {
            uint32_t pa[4];
            pa[0] = pack_h2(s_[2 * kc][0], s_[2 * kc][1]);
            pa[1] = pack_h2(s_[2 * kc][2], s_[2 * kc][3]);
            pa[2] = pack_h2(s_[2 * kc + 1][0], s_[2 * kc + 1][1]);
            pa[3] = pack_h2(s_[2 * kc + 1][2], s_[2 * kc + 1][3]);
            #pragma unroll
            for (int p = 0; p < 4; p++) {
                uint32_t v0, v1, v2, v3;
                ldsm_x4_trans(v0, v1, v2, v3,
                              vfb + (uint32_t)(kc * 16 * 72 + p * 16) * 2);
                mma_f16(o[2 * p],     pa, v0, v1);
                mma_f16(o[2 * p + 1], pa, v2, v3);
            }
        }
    }

    // ---- normalize + store (fp16) ----
    const float inv0 = 1.f / l0, inv1 = 1.f / l1;
    const size_t row0 = (size_t)(b * T_ + qtile * 128 + w * 16 + g);
    const size_t row1 = row0 + 8;
    #pragma unroll
    for (int nt = 0; nt < 8; nt++) {
        const int col = h * D_ + nt * 8 + 2 * t4;
        uint32_t v0 = pack_h2(o[nt][0] * inv0, o[nt][1] * inv0);
        uint32_t v1 = pack_h2(o[nt][2] * inv1, o[nt][3] * inv1);
        *reinterpret_cast<uint32_t*>(&outh[row0 * C_ + col]) = v0;
        *reinterpret_cast<uint32_t*>(&outh[row1 * C_ + col]) = v1;
    }
}

// ---------------------------------------------------------------------------
// Launch
// ---------------------------------------------------------------------------
extern "C" void kernel_launch(void* const* d_in, const int* in_sizes, int n_in,
                              void* d_out, int out_size)
{
    const float* x    = (const float*)d_in[0];
    const float* Wqkv = (const float*)d_in[1];
    const float* bqkv = (const float*)d_in[2];
    const float* Wout = (const float*)d_in[3];
    const float* bout = (const float*)d_in[4];
    float* out = (float*)d_out;

    __half *xh, *wqkvh, *wouth, *qkvh, *attnh;
    cudaGetSymbolAddress((void**)&xh,    g_xh);
    cudaGetSymbolAddress((void**)&wqkvh, g_wqkvh);
    cudaGetSymbolAddress((void**)&wouth, g_wouth);
    cudaGetSymbolAddress((void**)&qkvh,  g_qkvh);
    cudaGetSymbolAddress((void**)&attnh, g_attnh);

    // 0) fp32 -> fp16 conversions
    {
        const int n0 = M_ * C_ / 4;
        const int n1 = C_ * N_QKV / 4;
        const int n2 = C_ * C_ / 4;
        cvt_f32_f16<<<(n0 + 255) / 256, 256>>>(x, xh, n0);
        cvt_f32_f16<<<(n1 + 255) / 256, 256>>>(Wqkv, wqkvh, n1);
        cvt_f32_f16<<<(n2 + 255) / 256, 256>>>(Wout, wouth, n2);
    }

    // 1) QKV projection (fp16 out, Q columns pre-scaled by QSCALE)
    {
        dim3 grid(N_QKV / 128, M_ / 128);
        gemm_h_kernel<true><<<grid, 256>>>(xh, wqkvh, bqkv, qkvh,
                                           M_, N_QKV, C_, C_, (float)QSCALE);
    }
    // 2) Causal attention (flash, fp16 tensor cores, fp16 out)
    {
        dim3 grid(T_ / 128, B_ * H_);
        attn_mma_kernel<<<grid, 256>>>(qkvh, attnh);
    }
    // 3) Output projection (fp32 out)
    {
        dim3 grid(C_ / 128, M_ / 128);
        gemm_h_kernel<false><<<grid, 256>>>(attnh, wouth, bout, out,
                                            M_, C_, C_, 0, 1.f);
    }
}

// round 12
// speedup vs baseline: 3.3510x; 1.0206x over previous
#include <cuda_runtime.h>
#include <cuda_fp16.h>
#include <cstdint>
#include <cstddef>

#define B_ 2
#define T_ 4096
#define C_ 768
#define H_ 12
#define D_ 64
#define M_ (B_*T_)          // 8192
#define N_QKV (3*C_)        // 2304
// softmax scale folded with log2(e) so we can use ex2
#define QSCALE (0.125f * 1.4426950408889634f)

// fp16 scratch (allocation-free requirement -> __device__ globals)
__device__ __half g_xh[(size_t)M_ * C_];
__device__ __half g_wqkvh[(size_t)C_ * N_QKV];
__device__ __half g_wouth[(size_t)C_ * C_];
__device__ __half g_qkvh[(size_t)M_ * N_QKV];   // Q part pre-scaled by QSCALE
__device__ __half g_attnh[(size_t)M_ * C_];

// ---------------------------------------------------------------------------
// Helpers
// ---------------------------------------------------------------------------
__device__ __forceinline__ void mma_f16(float* c, const uint32_t* a,
                                        uint32_t b0, uint32_t b1) {
    asm volatile(
        "mma.sync.aligned.m16n8k16.row.col.f32.f16.f16.f32 "
        "{%0,%1,%2,%3},{%4,%5,%6,%7},{%8,%9},{%0,%1,%2,%3};"
        : "+f"(c[0]), "+f"(c[1]), "+f"(c[2]), "+f"(c[3])
        : "r"(a[0]), "r"(a[1]), "r"(a[2]), "r"(a[3]), "r"(b0), "r"(b1));
}

__device__ __forceinline__ void ldsm_x4(uint32_t& r0, uint32_t& r1,
                                        uint32_t& r2, uint32_t& r3,
                                        uint32_t addr) {
    asm volatile(
        "ldmatrix.sync.aligned.m8n8.x4.shared.b16 {%0,%1,%2,%3}, [%4];"
        : "=r"(r0), "=r"(r1), "=r"(r2), "=r"(r3) : "r"(addr));
}

__device__ __forceinline__ void ldsm_x4_trans(uint32_t& r0, uint32_t& r1,
                                              uint32_t& r2, uint32_t& r3,
                                              uint32_t addr) {
    asm volatile(
        "ldmatrix.sync.aligned.m8n8.x4.trans.shared.b16 {%0,%1,%2,%3}, [%4];"
        : "=r"(r0), "=r"(r1), "=r"(r2), "=r"(r3) : "r"(addr));
}

__device__ __forceinline__ uint32_t pack_h2(float lo, float hi) {
    __half2 h = __floats2half2_rn(lo, hi);
    return *reinterpret_cast<uint32_t*>(&h);
}

__device__ __forceinline__ float fast_exp2(float x) {
    float r;
    asm("ex2.approx.ftz.f32 %0, %1;" : "=f"(r) : "f"(x));
    return r;
}

__device__ __forceinline__ uint32_t smem_u32(const void* p) {
    return (uint32_t)__cvta_generic_to_shared(p);
}

// ---------------------------------------------------------------------------
// fp32 -> fp16 conversion (elementwise), n4 = numel/4
// ---------------------------------------------------------------------------
__global__ void __launch_bounds__(256)
cvt_f32_f16(const float* __restrict__ in, __half* __restrict__ out, int n4)
{
    int i = blockIdx.x * blockDim.x + threadIdx.x;
    if (i < n4) {
        float4 v = reinterpret_cast<const float4*>(in)[i];
        __half2 h0 = __floats2half2_rn(v.x, v.y);
        __half2 h1 = __floats2half2_rn(v.z, v.w);
        uint2 u;
        u.x = *reinterpret_cast<uint32_t*>(&h0);
        u.y = *reinterpret_cast<uint32_t*>(&h1);
        reinterpret_cast<uint2*>(out)[i] = u;
    }
}

// ---------------------------------------------------------------------------
// fp16-in tensor-core GEMM with bias (round-9 proven version):
// C[M,N] = A[M,K] @ B[K,N] + bias[N]
// BM=BN=128, BK=32, 256 threads (8 warps), warp tile 64x32 (m16n8k16).
// 2-stage smem double buffer + register prefetch, 2 CTAs/SM.
// ---------------------------------------------------------------------------
template<bool HALF_OUT>
__global__ void __launch_bounds__(256, 2)
gemm_h_kernel(const __half* __restrict__ A, const __half* __restrict__ B,
              const float* __restrict__ bias, void* __restrict__ Cout,
              int M, int N, int K, int qcols, float qsc)
{
    __shared__ __half As[2][128][40];   // 20480 B
    __shared__ __half Bs[2][32][136];   // 17408 B

    const int tid = threadIdx.x;
    const int wid = tid >> 5;
    const int lane = tid & 31;
    const int g = lane >> 2;
    const int t4 = lane & 3;
    const int wm = wid >> 2;
    const int wn = wid & 3;
    const int bx = blockIdx.x, by = blockIdx.y;
    const int mrow = lane & 7;
    const int mid  = lane >> 3;

    const uint32_t abase = smem_u32(
        &As[0][wm * 64 + (mid & 1) * 8 + mrow][(mid >> 1) * 8]);
    const uint32_t bbase = smem_u32(
        &Bs[0][(mid & 1) * 8 + mrow][wn * 32 + (mid >> 1) * 8]);
    const uint32_t a_ststride = 128 * 40 * 2;   // bytes per A stage
    const uint32_t b_ststride = 32 * 136 * 2;   // bytes per B stage

    // staging coords
    const int ar = tid >> 2;            // rows ar, ar+64
    const int ach = tid & 3;
    const int br = tid >> 4;            // rows br, br+16
    const int bch = tid & 15;

    const __half* aG = A + (size_t)(by * 128 + ar) * K + ach * 8;
    const __half* bG = B + (size_t)br * N + bx * 128 + bch * 8;
    const size_t aRow64 = (size_t)64 * K;
    const size_t bRow16 = (size_t)16 * N;

    uint4 pa0, pa1, pb0, pb1;
    auto ldg_slab = [&](int k0) {
        pa0 = *reinterpret_cast<const uint4*>(aG + k0);
        pa1 = *reinterpret_cast<const uint4*>(aG + aRow64 + k0);
        pb0 = *reinterpret_cast<const uint4*>(bG + (size_t)k0 * N);
        pb1 = *reinterpret_cast<const uint4*>(bG + (size_t)k0 * N + bRow16);
    };
    auto sts_slab = [&](int st) {
        *reinterpret_cast<uint4*>(&As[st][ar][ach * 8])      = pa0;
        *reinterpret_cast<uint4*>(&As[st][ar + 64][ach * 8]) = pa1;
        *reinterpret_cast<uint4*>(&Bs[st][br][bch * 8])      = pb0;
        *reinterpret_cast<uint4*>(&Bs[st][br + 16][bch * 8]) = pb1;
    };

    float acc[4][4][4];
    #pragma unroll
    for (int mt = 0; mt < 4; mt++)
        #pragma unroll
        for (int nt = 0; nt < 4; nt++)
            #pragma unroll
            for (int i = 0; i < 4; i++) acc[mt][nt][i] = 0.f;

    const int steps = K >> 5;
    ldg_slab(0);
    sts_slab(0);
    __syncthreads();

    for (int s = 0; s < steps; s++) {
        if (s + 1 < steps) ldg_slab((s + 1) << 5);   // LDG issued before compute

        const uint32_t ab = abase + (uint32_t)(s & 1) * a_ststride;
        const uint32_t bb = bbase + (uint32_t)(s & 1) * b_ststride;
        #pragma unroll
        for (int kk = 0; kk < 32; kk += 16) {
            uint32_t afr[4][4], bfr[4][2];
            #pragma unroll
            for (int mt = 0; mt < 4; mt++)
                ldsm_x4(afr[mt][0], afr[mt][1], afr[mt][2], afr[mt][3],
                        ab + (uint32_t)(mt * 16 * 40 + kk) * 2);
            #pragma unroll
            for (int p = 0; p < 2; p++) {
                uint32_t r0, r1, r2, r3;
                ldsm_x4_trans(r0, r1, r2, r3,
                              bb + (uint32_t)(kk * 136 + p * 16) * 2);
                bfr[2 * p][0] = r0; bfr[2 * p][1] = r1;
                bfr[2 * p + 1][0] = r2; bfr[2 * p + 1][1] = r3;
            }
            #pragma unroll
            for (int mt = 0; mt < 4; mt++)
                #pragma unroll
                for (int nt = 0; nt < 4; nt++)
                    mma_f16(acc[mt][nt], afr[mt], bfr[nt][0], bfr[nt][1]);
        }

        if (s + 1 < steps) sts_slab((s + 1) & 1);
        __syncthreads();
    }

    // ---- epilogue ----
    float osc = 1.f;
    if (HALF_OUT) osc = (bx * 128 < qcols) ? qsc : 1.f;

    #pragma unroll
    for (int nt = 0; nt < 4; nt++) {
        const int col = bx * 128 + wn * 32 + nt * 8 + 2 * t4;
        const float b0 = bias[col], b1 = bias[col + 1];
        #pragma unroll
        for (int mt = 0; mt < 4; mt++) {
            const int row = by * 128 + wm * 64 + mt * 16 + g;
            if (HALF_OUT) {
                __half* Ch = (__half*)Cout;
                uint32_t v0 = pack_h2((acc[mt][nt][0] + b0) * osc,
                                      (acc[mt][nt][1] + b1) * osc);
                uint32_t v1 = pack_h2((acc[mt][nt][2] + b0) * osc,
                                      (acc[mt][nt][3] + b1) * osc);
                *reinterpret_cast<uint32_t*>(&Ch[(size_t)row * N + col]) = v0;
                *reinterpret_cast<uint32_t*>(&Ch[(size_t)(row + 8) * N + col]) = v1;
            } else {
                float* Cf = (float*)Cout;
                float2 o0 = make_float2(acc[mt][nt][0] + b0, acc[mt][nt][1] + b1);
                float2 o1 = make_float2(acc[mt][nt][2] + b0, acc[mt][nt][3] + b1);
                *reinterpret_cast<float2*>(Cf + (size_t)row * N + col) = o0;
                *reinterpret_cast<float2*>(Cf + (size_t)(row + 8) * N + col) = o1;
            }
        }
    }
}

// ---------------------------------------------------------------------------
// Flash attention (causal), fp16 end-to-end (round-8 proven version).
// grid = (T/128, B*H), 256 threads (8 warps). Br=128, Bc=64, D=64.
// Static smem 36864 B, no occupancy cap (register-rich variant).
// K frags: ldmatrix.x4 (non-trans), V frags: ldmatrix.x4.trans.
// ---------------------------------------------------------------------------
__global__ void __launch_bounds__(256)
attn_mma_kernel(const __half* __restrict__ qkvh, __half* __restrict__ outh)
{
    __shared__ __half Qh[128][72];   // 18432 B
    __shared__ __half Kh[64][72];    //  9216 B
    __shared__ __half Vh[64][72];    //  9216 B

    const int bh = blockIdx.y;
    const int b = bh / H_;
    const int h = bh % H_;
    const int qtile = gridDim.x - 1 - blockIdx.x;   // big tiles first
    const int tid = threadIdx.x;
    const int w = tid >> 5;
    const int lane = tid & 31;
    const int g = lane >> 2;
    const int t4 = lane & 3;
    const int mrow = lane & 7;
    const int mid  = lane >> 3;

    // ldmatrix bases
    const uint32_t kfb = smem_u32(&Kh[(mid >> 1) * 8 + mrow][(mid & 1) * 8]);
    const uint32_t vfb = smem_u32(&Vh[(mid & 1) * 8 + mrow][(mid >> 1) * 8]);

    // ---- stage Q tile (pure copy; already fp16 + pre-scaled) ----
    #pragma unroll
    for (int i = 0; i < 4; i++) {
        const int c = tid + i * 256;          // 0..1023
        const int r = c >> 3;                 // 0..127
        const int ch = c & 7;
        *reinterpret_cast<uint4*>(&Qh[r][ch * 8]) =
            *reinterpret_cast<const uint4*>(
                qkvh + (size_t)(b * T_ + qtile * 128 + r) * N_QKV + h * D_ + ch * 8);
    }
    __syncthreads();

    // ---- Q fragments: 4 k16-chunks x 4 half2 regs (conflict-free LDS) ----
    uint32_t Qa[4][4];
    {
        const int row = w * 16;
        #pragma unroll
        for (int kc = 0; kc < 4; kc++) {
            const int k0 = kc * 16 + 2 * t4;
            Qa[kc][0] = *reinterpret_cast<const uint32_t*>(&Qh[row + g][k0]);
            Qa[kc][1] = *reinterpret_cast<const uint32_t*>(&Qh[row + g + 8][k0]);
            Qa[kc][2] = *reinterpret_cast<const uint32_t*>(&Qh[row + g][k0 + 8]);
            Qa[kc][3] = *reinterpret_cast<const uint32_t*>(&Qh[row + g + 8][k0 + 8]);
        }
    }

    float o[8][4];
    #pragma unroll
    for (int nt = 0; nt < 8; nt++)
        #pragma unroll
        for (int i = 0; i < 4; i++) o[nt][i] = 0.f;
    float m0 = -1e30f, m1 = -1e30f, l0 = 0.f, l1 = 0.f;

    const int q0g = qtile * 128 + w * 16 + g;   // own query row (second is +8)
    const int ntiles = 2 * qtile + 2;

    for (int kt = 0; kt < ntiles; kt++) {
        const int kbase = kt * 64;
        __syncthreads();    // previous tile's consumers done
        // ---- stage K/V tiles (pure copies) ----
        #pragma unroll
        for (int i = 0; i < 2; i++) {
            const int c = tid + i * 256;      // 0..511
            const int r = c >> 3;             // 0..63
            const int ch = c & 7;
            const __half* src =
                qkvh + (size_t)(b * T_ + kbase + r) * N_QKV + h * D_ + ch * 8;
            *reinterpret_cast<uint4*>(&Kh[r][ch * 8]) =
                *reinterpret_cast<const uint4*>(src + C_);
            *reinterpret_cast<uint4*>(&Vh[r][ch * 8]) =
                *reinterpret_cast<const uint4*>(src + 2 * C_);
        }
        __syncthreads();

        // ---- S = Q @ K^T (16x64 per warp); K frags via ldmatrix.x4 ----
        float s_[8][4];
        #pragma unroll
        for (int nt = 0; nt < 8; nt++)
            #pragma unroll
            for (int i = 0; i < 4; i++) s_[nt][i] = 0.f;
        #pragma unroll
        for (int kc = 0; kc < 4; kc++) {
            #pragma unroll
            for (int np = 0; np < 4; np++) {
                uint32_t r0, r1, r2, r3;
                ldsm_x4(r0, r1, r2, r3,
                        kfb + (uint32_t)(np * 16 * 72 + kc * 16) * 2);
                mma_f16(s_[2 * np],     Qa[kc], r0, r1);
                mma_f16(s_[2 * np + 1], Qa[kc], r2, r3);
            }
        }

        // ---- causal mask (tiles overlapping/above the diagonal) ----
        if (kbase + 63 > q0g) {
            #pragma unroll
            for (int nt = 0; nt < 8; nt++) {
                const int c0 = kbase + nt * 8 + 2 * t4;
                if (c0 > q0g)         s_[nt][0] = -1e30f;
                if (c0 + 1 > q0g)     s_[nt][1] = -1e30f;
                if (c0 > q0g + 8)     s_[nt][2] = -1e30f;
                if (c0 + 1 > q0g + 8) s_[nt][3] = -1e30f;
            }
        }

        // ---- online softmax (base-2) ----
        float mx0 = -1e30f, mx1 = -1e30f;
        #pragma unroll
        for (int nt = 0; nt < 8; nt++) {
            mx0 = fmaxf(mx0, fmaxf(s_[nt][0], s_[nt][1]));
            mx1 = fmaxf(mx1, fmaxf(s_[nt][2], s_[nt][3]));
        }
        mx0 = fmaxf(mx0, __shfl_xor_sync(0xffffffff, mx0, 1));
        mx0 = fmaxf(mx0, __shfl_xor_sync(0xffffffff, mx0, 2));
        mx1 = fmaxf(mx1, __shfl_xor_sync(0xffffffff, mx1, 1));
        mx1 = fmaxf(mx1, __shfl_xor_sync(0xffffffff, mx1, 2));
        const float nm0 = fmaxf(m0, mx0), nm1 = fmaxf(m1, mx1);
        const float sc0 = fast_exp2(m0 - nm0), sc1 = fast_exp2(m1 - nm1);
        m0 = nm0; m1 = nm1;

        float rs0 = 0.f, rs1 = 0.f;
        #pragma unroll
        for (int nt = 0; nt < 8; nt++) {
            s_[nt][0] = fast_exp2(s_[nt][0] - m0); rs0 += s_[nt][0];
            s_[nt][1] = fast_exp2(s_[nt][1] - m0); rs0 += s_[nt][1];
            s_[nt][2] = fast_exp2(s_[nt][2] - m1); rs1 += s_[nt][2];
            s_[nt][3] = fast_exp2(s_[nt][3] - m1); rs1 += s_[nt][3];
        }
        rs0 += __shfl_xor_sync(0xffffffff, rs0, 1);
        rs0 += __shfl_xor_sync(0xffffffff, rs0, 2);
        rs1 += __shfl_xor_sync(0xffffffff, rs1, 1);
        rs1 += __shfl_xor_sync(0xffffffff, rs1, 2);
        l0 = l0 * sc0 + rs0;
        l1 = l1 * sc1 + rs1;

        #pragma unroll
        for (int nt = 0; nt < 8; nt++) {
            o[nt][0] *= sc0; o[nt][1] *= sc0;
            o[nt][2] *= sc1; o[nt][3] *= sc1;
        }

        // ---- O += P @ V (V frags via ldmatrix.x4.trans) ----
        #pragma unroll
        for (int kc = 0; kc < 4; kc++) {
            uint32_t pa[4];
            pa[0] = pack_h2(s_[2 * kc][0], s_[2 * kc][1]);
            pa[1] = pack_h2(s_[2 * kc][2], s_[2 * kc][3]);
            pa[2] = pack_h2(s_[2 * kc + 1][0], s_[2 * kc + 1][1]);
            pa[3] = pack_h2(s_[2 * kc + 1][2], s_[2 * kc + 1][3]);
            #pragma unroll
            for (int p = 0; p < 4; p++) {
                uint32_t v0, v1, v2, v3;
                ldsm_x4_trans(v0, v1, v2, v3,
                              vfb + (uint32_t)(kc * 16 * 72 + p * 16) * 2);
                mma_f16(o[2 * p],     pa, v0, v1);
                mma_f16(o[2 * p + 1], pa, v2, v3);
            }
        }
    }

    // ---- normalize + store (fp16) ----
    const float inv0 = 1.f / l0, inv1 = 1.f / l1;
    const size_t row0 = (size_t)(b * T_ + qtile * 128 + w * 16 + g);
    const size_t row1 = row0 + 8;
    #pragma unroll
    for (int nt = 0; nt < 8; nt++) {
        const int col = h * D_ + nt * 8 + 2 * t4;
        uint32_t v0 = pack_h2(o[nt][0] * inv0, o[nt][1] * inv0);
        uint32_t v1 = pack_h2(o[nt][2] * inv1, o[nt][3] * inv1);
        *reinterpret_cast<uint32_t*>(&outh[row0 * C_ + col]) = v0;
        *reinterpret_cast<uint32_t*>(&outh[row1 * C_ + col]) = v1;
    }
}

// ---------------------------------------------------------------------------
// Launch
// ---------------------------------------------------------------------------
extern "C" void kernel_launch(void* const* d_in, const int* in_sizes, int n_in,
                              void* d_out, int out_size)
{
    const float* x    = (const float*)d_in[0];
    const float* Wqkv = (const float*)d_in[1];
    const float* bqkv = (const float*)d_in[2];
    const float* Wout = (const float*)d_in[3];
    const float* bout = (const float*)d_in[4];
    float* out = (float*)d_out;

    __half *xh, *wqkvh, *wouth, *qkvh, *attnh;
    cudaGetSymbolAddress((void**)&xh,    g_xh);
    cudaGetSymbolAddress((void**)&wqkvh, g_wqkvh);
    cudaGetSymbolAddress((void**)&wouth, g_wouth);
    cudaGetSymbolAddress((void**)&qkvh,  g_qkvh);
    cudaGetSymbolAddress((void**)&attnh, g_attnh);

    // 0) fp32 -> fp16 conversions
    {
        const int n0 = M_ * C_ / 4;
        const int n1 = C_ * N_QKV / 4;
        const int n2 = C_ * C_ / 4;
        cvt_f32_f16<<<(n0 + 255) / 256, 256>>>(x, xh, n0);
        cvt_f32_f16<<<(n1 + 255) / 256, 256>>>(Wqkv, wqkvh, n1);
        cvt_f32_f16<<<(n2 + 255) / 256, 256>>>(Wout, wouth, n2);
    }

    // 1) QKV projection (fp16 out, Q columns pre-scaled by QSCALE)
    {
        dim3 grid(N_QKV / 128, M_ / 128);
        gemm_h_kernel<true><<<grid, 256>>>(xh, wqkvh, bqkv, qkvh,
                                           M_, N_QKV, C_, C_, (float)QSCALE);
    }
    // 2) Causal attention (flash, fp16 tensor cores, fp16 out)
    {
        dim3 grid(T_ / 128, B_ * H_);
        attn_mma_kernel<<<grid, 256>>>(qkvh, attnh);
    }
    // 3) Output projection (fp32 out)
    {
        dim3 grid(C_ / 128, M_ / 128);
        gemm_h_kernel<false><<<grid, 256>>>(attnh, wouth, bout, out,
                                            M_, C_, C_, 0, 1.f);
    }
}

// round 13
// speedup vs baseline: 3.4050x; 1.0161x over previous
#include <cuda_runtime.h>
#include <cuda_fp16.h>
#include <cstdint>
#include <cstddef>

#define B_ 2
#define T_ 4096
#define C_ 768
#define H_ 12
#define D_ 64
#define M_ (B_*T_)          // 8192
#define N_QKV (3*C_)        // 2304
// softmax scale folded with log2(e) so we can use ex2
#define QSCALE (0.125f * 1.4426950408889634f)

// fp16 scratch (allocation-free requirement -> __device__ globals)
__device__ __half g_xh[(size_t)M_ * C_];
__device__ __half g_wqkvh[(size_t)C_ * N_QKV];
__device__ __half g_wouth[(size_t)C_ * C_];
__device__ __half g_qkvh[(size_t)M_ * N_QKV];   // Q part pre-scaled by QSCALE
__device__ __half g_attnh[(size_t)M_ * C_];

// ---------------------------------------------------------------------------
// Helpers
// ---------------------------------------------------------------------------
__device__ __forceinline__ void mma_f16(float* c, const uint32_t* a,
                                        uint32_t b0, uint32_t b1) {
    asm volatile(
        "mma.sync.aligned.m16n8k16.row.col.f32.f16.f16.f32 "
        "{%0,%1,%2,%3},{%4,%5,%6,%7},{%8,%9},{%0,%1,%2,%3};"
        : "+f"(c[0]), "+f"(c[1]), "+f"(c[2]), "+f"(c[3])
        : "r"(a[0]), "r"(a[1]), "r"(a[2]), "r"(a[3]), "r"(b0), "r"(b1));
}

__device__ __forceinline__ void ldsm_x4(uint32_t& r0, uint32_t& r1,
                                        uint32_t& r2, uint32_t& r3,
                                        uint32_t addr) {
    asm volatile(
        "ldmatrix.sync.aligned.m8n8.x4.shared.b16 {%0,%1,%2,%3}, [%4];"
        : "=r"(r0), "=r"(r1), "=r"(r2), "=r"(r3) : "r"(addr));
}

__device__ __forceinline__ void ldsm_x4_trans(uint32_t& r0, uint32_t& r1,
                                              uint32_t& r2, uint32_t& r3,
                                              uint32_t addr) {
    asm volatile(
        "ldmatrix.sync.aligned.m8n8.x4.trans.shared.b16 {%0,%1,%2,%3}, [%4];"
        : "=r"(r0), "=r"(r1), "=r"(r2), "=r"(r3) : "r"(addr));
}

__device__ __forceinline__ uint32_t pack_h2(float lo, float hi) {
    __half2 h = __floats2half2_rn(lo, hi);
    return *reinterpret_cast<uint32_t*>(&h);
}

__device__ __forceinline__ float fast_exp2(float x) {
    float r;
    asm("ex2.approx.ftz.f32 %0, %1;" : "=f"(r) : "f"(x));
    return r;
}

// packed fp16 helpers (softmax fast path)
__device__ __forceinline__ uint32_t hsub2(uint32_t a, uint32_t b) {
    uint32_t r;
    asm("sub.f16x2 %0, %1, %2;" : "=r"(r) : "r"(a), "r"(b));
    return r;
}
__device__ __forceinline__ uint32_t hex2_h2(uint32_t x) {
    uint32_t r;
    asm("ex2.approx.f16x2 %0, %1;" : "=r"(r) : "r"(x));
    return r;
}

__device__ __forceinline__ uint32_t smem_u32(const void* p) {
    return (uint32_t)__cvta_generic_to_shared(p);
}

// ---------------------------------------------------------------------------
// fp32 -> fp16 conversion (elementwise), n4 = numel/4
// ---------------------------------------------------------------------------
__global__ void __launch_bounds__(256)
cvt_f32_f16(const float* __restrict__ in, __half* __restrict__ out, int n4)
{
    int i = blockIdx.x * blockDim.x + threadIdx.x;
    if (i < n4) {
        float4 v = reinterpret_cast<const float4*>(in)[i];
        __half2 h0 = __floats2half2_rn(v.x, v.y);
        __half2 h1 = __floats2half2_rn(v.z, v.w);
        uint2 u;
        u.x = *reinterpret_cast<uint32_t*>(&h0);
        u.y = *reinterpret_cast<uint32_t*>(&h1);
        reinterpret_cast<uint2*>(out)[i] = u;
    }
}

// ---------------------------------------------------------------------------
// fp16-in tensor-core GEMM with bias (round-9 proven version):
// C[M,N] = A[M,K] @ B[K,N] + bias[N]
// BM=BN=128, BK=32, 256 threads (8 warps), warp tile 64x32 (m16n8k16).
// 2-stage smem double buffer + register prefetch, 2 CTAs/SM.
// ---------------------------------------------------------------------------
template<bool HALF_OUT>
__global__ void __launch_bounds__(256, 2)
gemm_h_kernel(const __half* __restrict__ A, const __half* __restrict__ B,
              const float* __restrict__ bias, void* __restrict__ Cout,
              int M, int N, int K, int qcols, float qsc)
{
    __shared__ __half As[2][128][40];   // 20480 B
    __shared__ __half Bs[2][32][136];   // 17408 B

    const int tid = threadIdx.x;
    const int wid = tid >> 5;
    const int lane = tid & 31;
    const int g = lane >> 2;
    const int t4 = lane & 3;
    const int wm = wid >> 2;
    const int wn = wid & 3;
    const int bx = blockIdx.x, by = blockIdx.y;
    const int mrow = lane & 7;
    const int mid  = lane >> 3;

    const uint32_t abase = smem_u32(
        &As[0][wm * 64 + (mid & 1) * 8 + mrow][(mid >> 1) * 8]);
    const uint32_t bbase = smem_u32(
        &Bs[0][(mid & 1) * 8 + mrow][wn * 32 + (mid >> 1) * 8]);
    const uint32_t a_ststride = 128 * 40 * 2;   // bytes per A stage
    const uint32_t b_ststride = 32 * 136 * 2;   // bytes per B stage

    // staging coords
    const int ar = tid >> 2;            // rows ar, ar+64
    const int ach = tid & 3;
    const int br = tid >> 4;            // rows br, br+16
    const int bch = tid & 15;

    const __half* aG = A + (size_t)(by * 128 + ar) * K + ach * 8;
    const __half* bG = B + (size_t)br * N + bx * 128 + bch * 8;
    const size_t aRow64 = (size_t)64 * K;
    const size_t bRow16 = (size_t)16 * N;

    uint4 pa0, pa1, pb0, pb1;
    auto ldg_slab = [&](int k0) {
        pa0 = *reinterpret_cast<const uint4*>(aG + k0);
        pa1 = *reinterpret_cast<const uint4*>(aG + aRow64 + k0);
        pb0 = *reinterpret_cast<const uint4*>(bG + (size_t)k0 * N);
        pb1 = *reinterpret_cast<const uint4*>(bG + (size_t)k0 * N + bRow16);
    };
    auto sts_slab = [&](int st) {
        *reinterpret_cast<uint4*>(&As[st][ar][ach * 8])      = pa0;
        *reinterpret_cast<uint4*>(&As[st][ar + 64][ach * 8]) = pa1;
        *reinterpret_cast<uint4*>(&Bs[st][br][bch * 8])      = pb0;
        *reinterpret_cast<uint4*>(&Bs[st][br + 16][bch * 8]) = pb1;
    };

    float acc[4][4][4];
    #pragma unroll
    for (int mt = 0; mt < 4; mt++)
        #pragma unroll
        for (int nt = 0; nt < 4; nt++)
            #pragma unroll
            for (int i = 0; i < 4; i++) acc[mt][nt][i] = 0.f;

    const int steps = K >> 5;
    ldg_slab(0);
    sts_slab(0);
    __syncthreads();

    for (int s = 0; s < steps; s++) {
        if (s + 1 < steps) ldg_slab((s + 1) << 5);   // LDG issued before compute

        const uint32_t ab = abase + (uint32_t)(s & 1) * a_ststride;
        const uint32_t bb = bbase + (uint32_t)(s & 1) * b_ststride;
        #pragma unroll
        for (int kk = 0; kk < 32; kk += 16) {
            uint32_t afr[4][4], bfr[4][2];
            #pragma unroll
            for (int mt = 0; mt < 4; mt++)
                ldsm_x4(afr[mt][0], afr[mt][1], afr[mt][2], afr[mt][3],
                        ab + (uint32_t)(mt * 16 * 40 + kk) * 2);
            #pragma unroll
            for (int p = 0; p < 2; p++) {
                uint32_t r0, r1, r2, r3;
                ldsm_x4_trans(r0, r1, r2, r3,
                              bb + (uint32_t)(kk * 136 + p * 16) * 2);
                bfr[2 * p][0] = r0; bfr[2 * p][1] = r1;
                bfr[2 * p + 1][0] = r2; bfr[2 * p + 1][1] = r3;
            }
            #pragma unroll
            for (int mt = 0; mt < 4; mt++)
                #pragma unroll
                for (int nt = 0; nt < 4; nt++)
                    mma_f16(acc[mt][nt], afr[mt], bfr[nt][0], bfr[nt][1]);
        }

        if (s + 1 < steps) sts_slab((s + 1) & 1);
        __syncthreads();
    }

    // ---- epilogue ----
    float osc = 1.f;
    if (HALF_OUT) osc = (bx * 128 < qcols) ? qsc : 1.f;

    #pragma unroll
    for (int nt = 0; nt < 4; nt++) {
        const int col = bx * 128 + wn * 32 + nt * 8 + 2 * t4;
        const float b0 = bias[col], b1 = bias[col + 1];
        #pragma unroll
        for (int mt = 0; mt < 4; mt++) {
            const int row = by * 128 + wm * 64 + mt * 16 + g;
            if (HALF_OUT) {
                __half* Ch = (__half*)Cout;
                uint32_t v0 = pack_h2((acc[mt][nt][0] + b0) * osc,
                                      (acc[mt][nt][1] + b1) * osc);
                uint32_t v1 = pack_h2((acc[mt][nt][2] + b0) * osc,
                                      (acc[mt][nt][3] + b1) * osc);
                *reinterpret_cast<uint32_t*>(&Ch[(size_t)row * N + col]) = v0;
                *reinterpret_cast<uint32_t*>(&Ch[(size_t)(row + 8) * N + col]) = v1;
            } else {
                float* Cf = (float*)Cout;
                float2 o0 = make_float2(acc[mt][nt][0] + b0, acc[mt][nt][1] + b1);
                float2 o1 = make_float2(acc[mt][nt][2] + b0, acc[mt][nt][3] + b1);
                *reinterpret_cast<float2*>(Cf + (size_t)row * N + col) = o0;
                *reinterpret_cast<float2*>(Cf + (size_t)(row + 8) * N + col) = o1;
            }
        }
    }
}

// ---------------------------------------------------------------------------
// Flash attention (causal), fp16 end-to-end.
// grid = (T/128, B*H), 256 threads (8 warps). Br=128, Bc=64, D=64.
// Softmax fast path: exp via ex2.approx.f16x2, sub via sub.f16x2,
// row-sum l via mma ones-column (constant B fragment, no ldsm).
// ---------------------------------------------------------------------------
__global__ void __launch_bounds__(256)
attn_mma_kernel(const __half* __restrict__ qkvh, __half* __restrict__ outh)
{
    __shared__ __half Qh[128][72];   // 18432 B
    __shared__ __half Kh[64][72];    //  9216 B
    __shared__ __half Vh[64][72];    //  9216 B

    const int bh = blockIdx.y;
    const int b = bh / H_;
    const int h = bh % H_;
    const int qtile = gridDim.x - 1 - blockIdx.x;   // big tiles first
    const int tid = threadIdx.x;
    const int w = tid >> 5;
    const int lane = tid & 31;
    const int g = lane >> 2;
    const int t4 = lane & 3;
    const int mrow = lane & 7;
    const int mid  = lane >> 3;

    // ldmatrix bases
    const uint32_t kfb = smem_u32(&Kh[(mid >> 1) * 8 + mrow][(mid & 1) * 8]);
    const uint32_t vfb = smem_u32(&Vh[(mid & 1) * 8 + mrow][(mid >> 1) * 8]);

    // ones-column B fragment: B[k][n]=1 iff n==0 -> nonzero only for g==0
    const uint32_t onesb = (g == 0) ? 0x3C003C00u : 0u;

    // ---- stage Q tile (pure copy; already fp16 + pre-scaled) ----
    #pragma unroll
    for (int i = 0; i < 4; i++) {
        const int c = tid + i * 256;          // 0..1023
        const int r = c >> 3;                 // 0..127
        const int ch = c & 7;
        *reinterpret_cast<uint4*>(&Qh[r][ch * 8]) =
            *reinterpret_cast<const uint4*>(
                qkvh + (size_t)(b * T_ + qtile * 128 + r) * N_QKV + h * D_ + ch * 8);
    }
    __syncthreads();

    // ---- Q fragments: 4 k16-chunks x 4 half2 regs (conflict-free LDS) ----
    uint32_t Qa[4][4];
    {
        const int row = w * 16;
        #pragma unroll
        for (int kc = 0; kc < 4; kc++) {
            const int k0 = kc * 16 + 2 * t4;
            Qa[kc][0] = *reinterpret_cast<const uint32_t*>(&Qh[row + g][k0]);
            Qa[kc][1] = *reinterpret_cast<const uint32_t*>(&Qh[row + g + 8][k0]);
            Qa[kc][2] = *reinterpret_cast<const uint32_t*>(&Qh[row + g][k0 + 8]);
            Qa[kc][3] = *reinterpret_cast<const uint32_t*>(&Qh[row + g + 8][k0 + 8]);
        }
    }

    float o[8][4];
    #pragma unroll
    for (int nt = 0; nt < 8; nt++)
        #pragma unroll
        for (int i = 0; i < 4; i++) o[nt][i] = 0.f;
    float la[4] = {0.f, 0.f, 0.f, 0.f};     // ones-column accumulator (l sums)
    float m0 = -1e30f, m1 = -1e30f;

    const int q0g = qtile * 128 + w * 16 + g;   // own query row (second is +8)
    const int ntiles = 2 * qtile + 2;

    for (int kt = 0; kt < ntiles; kt++) {
        const int kbase = kt * 64;
        __syncthreads();    // previous tile's consumers done
        // ---- stage K/V tiles (pure copies) ----
        #pragma unroll
        for (int i = 0; i < 2; i++) {
            const int c = tid + i * 256;      // 0..511
            const int r = c >> 3;             // 0..63
            const int ch = c & 7;
            const __half* src =
                qkvh + (size_t)(b * T_ + kbase + r) * N_QKV + h * D_ + ch * 8;
            *reinterpret_cast<uint4*>(&Kh[r][ch * 8]) =
                *reinterpret_cast<const uint4*>(src + C_);
            *reinterpret_cast<uint4*>(&Vh[r][ch * 8]) =
                *reinterpret_cast<const uint4*>(src + 2 * C_);
        }
        __syncthreads();

        // ---- S = Q @ K^T (16x64 per warp); K frags via ldmatrix.x4 ----
        float s_[8][4];
        #pragma unroll
        for (int nt = 0; nt < 8; nt++)
            #pragma unroll
            for (int i = 0; i < 4; i++) s_[nt][i] = 0.f;
        #pragma unroll
        for (int kc = 0; kc < 4; kc++) {
            #pragma unroll
            for (int np = 0; np < 4; np++) {
                uint32_t r0, r1, r2, r3;
                ldsm_x4(r0, r1, r2, r3,
                        kfb + (uint32_t)(np * 16 * 72 + kc * 16) * 2);
                mma_f16(s_[2 * np],     Qa[kc], r0, r1);
                mma_f16(s_[2 * np + 1], Qa[kc], r2, r3);
            }
        }

        // ---- causal mask (tiles overlapping/above the diagonal) ----
        if (kbase + 63 > q0g) {
            #pragma unroll
            for (int nt = 0; nt < 8; nt++) {
                const int c0 = kbase + nt * 8 + 2 * t4;
                if (c0 > q0g)         s_[nt][0] = -1e30f;
                if (c0 + 1 > q0g)     s_[nt][1] = -1e30f;
                if (c0 > q0g + 8)     s_[nt][2] = -1e30f;
                if (c0 + 1 > q0g + 8) s_[nt][3] = -1e30f;
            }
        }

        // ---- online softmax (base-2) ----
        float mx0 = -1e30f, mx1 = -1e30f;
        #pragma unroll
        for (int nt = 0; nt < 8; nt++) {
            mx0 = fmaxf(mx0, fmaxf(s_[nt][0], s_[nt][1]));
            mx1 = fmaxf(mx1, fmaxf(s_[nt][2], s_[nt][3]));
        }
        mx0 = fmaxf(mx0, __shfl_xor_sync(0xffffffff, mx0, 1));
        mx0 = fmaxf(mx0, __shfl_xor_sync(0xffffffff, mx0, 2));
        mx1 = fmaxf(mx1, __shfl_xor_sync(0xffffffff, mx1, 1));
        mx1 = fmaxf(mx1, __shfl_xor_sync(0xffffffff, mx1, 2));
        const float nm0 = fmaxf(m0, mx0), nm1 = fmaxf(m1, mx1);
        const float sc0 = fast_exp2(m0 - nm0), sc1 = fast_exp2(m1 - nm1);
        m0 = nm0; m1 = nm1;

        // P = exp2(s - m) computed in packed fp16 (ready as mma A operand)
        const uint32_t mh0 = pack_h2(m0, m0);
        const uint32_t mh1 = pack_h2(m1, m1);
        uint32_t P0[8], P1[8];
        #pragma unroll
        for (int nt = 0; nt < 8; nt++) {
            P0[nt] = hex2_h2(hsub2(pack_h2(s_[nt][0], s_[nt][1]), mh0));
            P1[nt] = hex2_h2(hsub2(pack_h2(s_[nt][2], s_[nt][3]), mh1));
        }

        la[0] *= sc0; la[1] *= sc0; la[2] *= sc1; la[3] *= sc1;
        #pragma unroll
        for (int nt = 0; nt < 8; nt++) {
            o[nt][0] *= sc0; o[nt][1] *= sc0;
            o[nt][2] *= sc1; o[nt][3] *= sc1;
        }

        // ---- O += P @ V ; l += P @ ones (constant B fragment) ----
        #pragma unroll
        for (int kc = 0; kc < 4; kc++) {
            uint32_t pa[4];
            pa[0] = P0[2 * kc];
            pa[1] = P1[2 * kc];
            pa[2] = P0[2 * kc + 1];
            pa[3] = P1[2 * kc + 1];
            #pragma unroll
            for (int p = 0; p < 4; p++) {
                uint32_t v0, v1, v2, v3;
                ldsm_x4_trans(v0, v1, v2, v3,
                              vfb + (uint32_t)(kc * 16 * 72 + p * 16) * 2);
                mma_f16(o[2 * p],     pa, v0, v1);
                mma_f16(o[2 * p + 1], pa, v2, v3);
            }
            mma_f16(la, pa, onesb, onesb);
        }
    }

    // ---- broadcast l (column 0 lives in t4==0 lanes), normalize, store ----
    const int qlead = lane & 28;       // lane of t4==0 in this quad
    const float l0 = __shfl_sync(0xffffffff, la[0], qlead);
    const float l1 = __shfl_sync(0xffffffff, la[2], qlead);
    const float inv0 = 1.f / l0, inv1 = 1.f / l1;
    const size_t row0 = (size_t)(b * T_ + qtile * 128 + w * 16 + g);
    const size_t row1 = row0 + 8;
    #pragma unroll
    for (int nt = 0; nt < 8; nt++) {
        const int col = h * D_ + nt * 8 + 2 * t4;
        uint32_t v0 = pack_h2(o[nt][0] * inv0, o[nt][1] * inv0);
        uint32_t v1 = pack_h2(o[nt][2] * inv1, o[nt][3] * inv1);
        *reinterpret_cast<uint32_t*>(&outh[row0 * C_ + col]) = v0;
        *reinterpret_cast<uint32_t*>(&outh[row1 * C_ + col]) = v1;
    }
}

// ---------------------------------------------------------------------------
// Launch
// ---------------------------------------------------------------------------
extern "C" void kernel_launch(void* const* d_in, const int* in_sizes, int n_in,
                              void* d_out, int out_size)
{
    const float* x    = (const float*)d_in[0];
    const float* Wqkv = (const float*)d_in[1];
    const float* bqkv = (const float*)d_in[2];
    const float* Wout = (const float*)d_in[3];
    const float* bout = (const float*)d_in[4];
    float* out = (float*)d_out;

    __half *xh, *wqkvh, *wouth, *qkvh, *attnh;
    cudaGetSymbolAddress((void**)&xh,    g_xh);
    cudaGetSymbolAddress((void**)&wqkvh, g_wqkvh);
    cudaGetSymbolAddress((void**)&wouth, g_wouth);
    cudaGetSymbolAddress((void**)&qkvh,  g_qkvh);
    cudaGetSymbolAddress((void**)&attnh, g_attnh);

    // 0) fp32 -> fp16 conversions
    {
        const int n0 = M_ * C_ / 4;
        const int n1 = C_ * N_QKV / 4;
        const int n2 = C_ * C_ / 4;
        cvt_f32_f16<<<(n0 + 255) / 256, 256>>>(x, xh, n0);
        cvt_f32_f16<<<(n1 + 255) / 256, 256>>>(Wqkv, wqkvh, n1);
        cvt_f32_f16<<<(n2 + 255) / 256, 256>>>(Wout, wouth, n2);
    }

    // 1) QKV projection (fp16 out, Q columns pre-scaled by QSCALE)
    {
        dim3 grid(N_QKV / 128, M_ / 128);
        gemm_h_kernel<true><<<grid, 256>>>(xh, wqkvh, bqkv, qkvh,
                                           M_, N_QKV, C_, C_, (float)QSCALE);
    }
    // 2) Causal attention (flash, fp16 tensor cores, fp16 out)
    {
        dim3 grid(T_ / 128, B_ * H_);
        attn_mma_kernel<<<grid, 256>>>(qkvh, attnh);
    }
    // 3) Output projection (fp32 out)
    {
        dim3 grid(C_ / 128, M_ / 128);
        gemm_h_kernel<false><<<grid, 256>>>(attnh, wouth, bout, out,
                                            M_, C_, C_, 0, 1.f);
    }
}

// round 14
// speedup vs baseline: 3.4308x; 1.0076x over previous
#include <cuda_runtime.h>
#include <cuda_fp16.h>
#include <cstdint>
#include <cstddef>

#define B_ 2
#define T_ 4096
#define C_ 768
#define H_ 12
#define D_ 64
#define M_ (B_*T_)          // 8192
#define N_QKV (3*C_)        // 2304
// softmax scale folded with log2(e) so we can use ex2
#define QSCALE (0.125f * 1.4426950408889634f)

// fp16 scratch (allocation-free requirement -> __device__ globals)
__device__ __half g_xh[(size_t)M_ * C_];
__device__ __half g_wqkvh[(size_t)C_ * N_QKV];
__device__ __half g_wouth[(size_t)C_ * C_];
__device__ __half g_qkvh[(size_t)M_ * N_QKV];   // Q part pre-scaled by QSCALE
__device__ __half g_attnh[(size_t)M_ * C_];

// ---------------------------------------------------------------------------
// Helpers
// ---------------------------------------------------------------------------
__device__ __forceinline__ void mma_f16(float* c, const uint32_t* a,
                                        uint32_t b0, uint32_t b1) {
    asm volatile(
        "mma.sync.aligned.m16n8k16.row.col.f32.f16.f16.f32 "
        "{%0,%1,%2,%3},{%4,%5,%6,%7},{%8,%9},{%0,%1,%2,%3};"
        : "+f"(c[0]), "+f"(c[1]), "+f"(c[2]), "+f"(c[3])
        : "r"(a[0]), "r"(a[1]), "r"(a[2]), "r"(a[3]), "r"(b0), "r"(b1));
}

__device__ __forceinline__ void ldsm_x4(uint32_t& r0, uint32_t& r1,
                                        uint32_t& r2, uint32_t& r3,
                                        uint32_t addr) {
    asm volatile(
        "ldmatrix.sync.aligned.m8n8.x4.shared.b16 {%0,%1,%2,%3}, [%4];"
        : "=r"(r0), "=r"(r1), "=r"(r2), "=r"(r3) : "r"(addr));
}

__device__ __forceinline__ void ldsm_x4_trans(uint32_t& r0, uint32_t& r1,
                                              uint32_t& r2, uint32_t& r3,
                                              uint32_t addr) {
    asm volatile(
        "ldmatrix.sync.aligned.m8n8.x4.trans.shared.b16 {%0,%1,%2,%3}, [%4];"
        : "=r"(r0), "=r"(r1), "=r"(r2), "=r"(r3) : "r"(addr));
}

__device__ __forceinline__ uint32_t pack_h2(float lo, float hi) {
    __half2 h = __floats2half2_rn(lo, hi);
    return *reinterpret_cast<uint32_t*>(&h);
}

__device__ __forceinline__ float fast_exp2(float x) {
    float r;
    asm("ex2.approx.ftz.f32 %0, %1;" : "=f"(r) : "f"(x));
    return r;
}

// packed fp16 helpers (softmax fast path)
__device__ __forceinline__ uint32_t hsub2(uint32_t a, uint32_t b) {
    uint32_t r;
    asm("sub.f16x2 %0, %1, %2;" : "=r"(r) : "r"(a), "r"(b));
    return r;
}
__device__ __forceinline__ uint32_t hex2_h2(uint32_t x) {
    uint32_t r;
    asm("ex2.approx.f16x2 %0, %1;" : "=r"(r) : "r"(x));
    return r;
}

__device__ __forceinline__ uint32_t smem_u32(const void* p) {
    return (uint32_t)__cvta_generic_to_shared(p);
}
// L1-preserving async copy (NOT .cg — the round-4 lesson)
__device__ __forceinline__ void cp_async16_ca(uint32_t dst, const void* src) {
    asm volatile("cp.async.ca.shared.global [%0], [%1], 16;"
                 :: "r"(dst), "l"(src));
}
__device__ __forceinline__ void cp_commit() {
    asm volatile("cp.async.commit_group;");
}
__device__ __forceinline__ void cp_wait0() {
    asm volatile("cp.async.wait_group 0;");
}

// ---------------------------------------------------------------------------
// fp32 -> fp16 conversion (elementwise), n4 = numel/4
// ---------------------------------------------------------------------------
__global__ void __launch_bounds__(256)
cvt_f32_f16(const float* __restrict__ in, __half* __restrict__ out, int n4)
{
    int i = blockIdx.x * blockDim.x + threadIdx.x;
    if (i < n4) {
        float4 v = reinterpret_cast<const float4*>(in)[i];
        __half2 h0 = __floats2half2_rn(v.x, v.y);
        __half2 h1 = __floats2half2_rn(v.z, v.w);
        uint2 u;
        u.x = *reinterpret_cast<uint32_t*>(&h0);
        u.y = *reinterpret_cast<uint32_t*>(&h1);
        reinterpret_cast<uint2*>(out)[i] = u;
    }
}

// ---------------------------------------------------------------------------
// fp16-in tensor-core GEMM with bias (round-9 proven version):
// C[M,N] = A[M,K] @ B[K,N] + bias[N]
// BM=BN=128, BK=32, 256 threads (8 warps), warp tile 64x32 (m16n8k16).
// 2-stage smem double buffer + register prefetch, 2 CTAs/SM.
// ---------------------------------------------------------------------------
template<bool HALF_OUT>
__global__ void __launch_bounds__(256, 2)
gemm_h_kernel(const __half* __restrict__ A, const __half* __restrict__ B,
              const float* __restrict__ bias, void* __restrict__ Cout,
              int M, int N, int K, int qcols, float qsc)
{
    __shared__ __half As[2][128][40];   // 20480 B
    __shared__ __half Bs[2][32][136];   // 17408 B

    const int tid = threadIdx.x;
    const int wid = tid >> 5;
    const int lane = tid & 31;
    const int g = lane >> 2;
    const int t4 = lane & 3;
    const int wm = wid >> 2;
    const int wn = wid & 3;
    const int bx = blockIdx.x, by = blockIdx.y;
    const int mrow = lane & 7;
    const int mid  = lane >> 3;

    const uint32_t abase = smem_u32(
        &As[0][wm * 64 + (mid & 1) * 8 + mrow][(mid >> 1) * 8]);
    const uint32_t bbase = smem_u32(
        &Bs[0][(mid & 1) * 8 + mrow][wn * 32 + (mid >> 1) * 8]);
    const uint32_t a_ststride = 128 * 40 * 2;   // bytes per A stage
    const uint32_t b_ststride = 32 * 136 * 2;   // bytes per B stage

    // staging coords
    const int ar = tid >> 2;            // rows ar, ar+64
    const int ach = tid & 3;
    const int br = tid >> 4;            // rows br, br+16
    const int bch = tid & 15;

    const __half* aG = A + (size_t)(by * 128 + ar) * K + ach * 8;
    const __half* bG = B + (size_t)br * N + bx * 128 + bch * 8;
    const size_t aRow64 = (size_t)64 * K;
    const size_t bRow16 = (size_t)16 * N;

    uint4 pa0, pa1, pb0, pb1;
    auto ldg_slab = [&](int k0) {
        pa0 = *reinterpret_cast<const uint4*>(aG + k0);
        pa1 = *reinterpret_cast<const uint4*>(aG + aRow64 + k0);
        pb0 = *reinterpret_cast<const uint4*>(bG + (size_t)k0 * N);
        pb1 = *reinterpret_cast<const uint4*>(bG + (size_t)k0 * N + bRow16);
    };
    auto sts_slab = [&](int st) {
        *reinterpret_cast<uint4*>(&As[st][ar][ach * 8])      = pa0;
        *reinterpret_cast<uint4*>(&As[st][ar + 64][ach * 8]) = pa1;
        *reinterpret_cast<uint4*>(&Bs[st][br][bch * 8])      = pb0;
        *reinterpret_cast<uint4*>(&Bs[st][br + 16][bch * 8]) = pb1;
    };

    float acc[4][4][4];
    #pragma unroll
    for (int mt = 0; mt < 4; mt++)
        #pragma unroll
        for (int nt = 0; nt < 4; nt++)
            #pragma unroll
            for (int i = 0; i < 4; i++) acc[mt][nt][i] = 0.f;

    const int steps = K >> 5;
    ldg_slab(0);
    sts_slab(0);
    __syncthreads();

    for (int s = 0; s < steps; s++) {
        if (s + 1 < steps) ldg_slab((s + 1) << 5);   // LDG issued before compute

        const uint32_t ab = abase + (uint32_t)(s & 1) * a_ststride;
        const uint32_t bb = bbase + (uint32_t)(s & 1) * b_ststride;
        #pragma unroll
        for (int kk = 0; kk < 32; kk += 16) {
            uint32_t afr[4][4], bfr[4][2];
            #pragma unroll
            for (int mt = 0; mt < 4; mt++)
                ldsm_x4(afr[mt][0], afr[mt][1], afr[mt][2], afr[mt][3],
                        ab + (uint32_t)(mt * 16 * 40 + kk) * 2);
            #pragma unroll
            for (int p = 0; p < 2; p++) {
                uint32_t r0, r1, r2, r3;
                ldsm_x4_trans(r0, r1, r2, r3,
                              bb + (uint32_t)(kk * 136 + p * 16) * 2);
                bfr[2 * p][0] = r0; bfr[2 * p][1] = r1;
                bfr[2 * p + 1][0] = r2; bfr[2 * p + 1][1] = r3;
            }
            #pragma unroll
            for (int mt = 0; mt < 4; mt++)
                #pragma unroll
                for (int nt = 0; nt < 4; nt++)
                    mma_f16(acc[mt][nt], afr[mt], bfr[nt][0], bfr[nt][1]);
        }

        if (s + 1 < steps) sts_slab((s + 1) & 1);
        __syncthreads();
    }

    // ---- epilogue ----
    float osc = 1.f;
    if (HALF_OUT) osc = (bx * 128 < qcols) ? qsc : 1.f;

    #pragma unroll
    for (int nt = 0; nt < 4; nt++) {
        const int col = bx * 128 + wn * 32 + nt * 8 + 2 * t4;
        const float b0 = bias[col], b1 = bias[col + 1];
        #pragma unroll
        for (int mt = 0; mt < 4; mt++) {
            const int row = by * 128 + wm * 64 + mt * 16 + g;
            if (HALF_OUT) {
                __half* Ch = (__half*)Cout;
                uint32_t v0 = pack_h2((acc[mt][nt][0] + b0) * osc,
                                      (acc[mt][nt][1] + b1) * osc);
                uint32_t v1 = pack_h2((acc[mt][nt][2] + b0) * osc,
                                      (acc[mt][nt][3] + b1) * osc);
                *reinterpret_cast<uint32_t*>(&Ch[(size_t)row * N + col]) = v0;
                *reinterpret_cast<uint32_t*>(&Ch[(size_t)(row + 8) * N + col]) = v1;
            } else {
                float* Cf = (float*)Cout;
                float2 o0 = make_float2(acc[mt][nt][0] + b0, acc[mt][nt][1] + b1);
                float2 o1 = make_float2(acc[mt][nt][2] + b0, acc[mt][nt][3] + b1);
                *reinterpret_cast<float2*>(Cf + (size_t)row * N + col) = o0;
                *reinterpret_cast<float2*>(Cf + (size_t)(row + 8) * N + col) = o1;
            }
        }
    }
}

// ---------------------------------------------------------------------------
// Flash attention (causal), fp16 end-to-end, cp.async.ca double-buffered K/V.
// grid = (T/128, B*H), 256 threads (8 warps). Br=128, Bc=64, D=64.
// Dynamic smem: Q[128][72] + K[2][64][72] + V[2][64][72] = 55296 B.
// Softmax fast path: ex2.approx.f16x2 + ones-column l (round-13 proven).
// One __syncthreads per KV tile; copy of tile kt+1 overlaps compute of kt.
// ---------------------------------------------------------------------------
#define QH_HALFS (128 * 72)
#define KV_HALFS (64 * 72)
#define ATTN_SMEM ((QH_HALFS + 4 * KV_HALFS) * 2)

__global__ void __launch_bounds__(256)
attn_mma_kernel(const __half* __restrict__ qkvh, __half* __restrict__ outh)
{
    extern __shared__ __half smh[];
    __half* Qh = smh;                               // [128][72]
    __half* Kh = smh + QH_HALFS;                    // [2][64][72]
    __half* Vh = smh + QH_HALFS + 2 * KV_HALFS;     // [2][64][72]

    const int bh = blockIdx.y;
    const int b = bh / H_;
    const int h = bh % H_;
    const int qtile = gridDim.x - 1 - blockIdx.x;   // big tiles first
    const int tid = threadIdx.x;
    const int w = tid >> 5;
    const int lane = tid & 31;
    const int g = lane >> 2;
    const int t4 = lane & 3;
    const int mrow = lane & 7;
    const int mid  = lane >> 3;

    // ldmatrix bases (stage 0); stage stride in bytes
    const uint32_t kfb = smem_u32(&Kh[((mid >> 1) * 8 + mrow) * 72 + (mid & 1) * 8]);
    const uint32_t vfb = smem_u32(&Vh[((mid & 1) * 8 + mrow) * 72 + (mid >> 1) * 8]);
    const uint32_t kvstride = KV_HALFS * 2;

    // ones-column B fragment: B[k][n]=1 iff n==0 -> nonzero only for g==0
    const uint32_t onesb = (g == 0) ? 0x3C003C00u : 0u;

    // K/V cp.async coordinates (per thread: 2 chunks K + 2 chunks V)
    const int kvr = tid >> 3;              // rows kvr, kvr+32
    const int kvch = tid & 7;
    const __half* kvG = qkvh + (size_t)(b * T_ + kvr) * N_QKV + h * D_ + kvch * 8;
    const size_t row32 = (size_t)32 * N_QKV;

    auto stage_kv = [&](int kbase, int st) {
        const __half* s0 = kvG + (size_t)kbase * N_QKV;
        const uint32_t kd = smem_u32(&Kh[st * KV_HALFS + kvr * 72 + kvch * 8]);
        const uint32_t vd = smem_u32(&Vh[st * KV_HALFS + kvr * 72 + kvch * 8]);
        const uint32_t roff = 32 * 72 * 2;  // +32 rows in bytes
        cp_async16_ca(kd,        s0 + C_);
        cp_async16_ca(kd + roff, s0 + row32 + C_);
        cp_async16_ca(vd,        s0 + 2 * C_);
        cp_async16_ca(vd + roff, s0 + row32 + 2 * C_);
        cp_commit();
    };

    // ---- prologue: issue K/V tile 0, stage Q (plain stores) ----
    stage_kv(0, 0);
    #pragma unroll
    for (int i = 0; i < 4; i++) {
        const int c = tid + i * 256;          // 0..1023
        const int r = c >> 3;                 // 0..127
        const int ch = c & 7;
        *reinterpret_cast<uint4*>(&Qh[r * 72 + ch * 8]) =
            *reinterpret_cast<const uint4*>(
                qkvh + (size_t)(b * T_ + qtile * 128 + r) * N_QKV + h * D_ + ch * 8);
    }
    __syncthreads();

    // ---- Q fragments: 4 k16-chunks x 4 half2 regs (conflict-free LDS) ----
    uint32_t Qa[4][4];
    {
        const int row = w * 16;
        #pragma unroll
        for (int kc = 0; kc < 4; kc++) {
            const int k0 = kc * 16 + 2 * t4;
            Qa[kc][0] = *reinterpret_cast<const uint32_t*>(&Qh[(row + g) * 72 + k0]);
            Qa[kc][1] = *reinterpret_cast<const uint32_t*>(&Qh[(row + g + 8) * 72 + k0]);
            Qa[kc][2] = *reinterpret_cast<const uint32_t*>(&Qh[(row + g) * 72 + k0 + 8]);
            Qa[kc][3] = *reinterpret_cast<const uint32_t*>(&Qh[(row + g + 8) * 72 + k0 + 8]);
        }
    }

    float o[8][4];
    #pragma unroll
    for (int nt = 0; nt < 8; nt++)
        #pragma unroll
        for (int i = 0; i < 4; i++) o[nt][i] = 0.f;
    float la[4] = {0.f, 0.f, 0.f, 0.f};     // ones-column accumulator (l sums)
    float m0 = -1e30f, m1 = -1e30f;

    const int q0g = qtile * 128 + w * 16 + g;   // own query row (second is +8)
    const int ntiles = 2 * qtile + 2;

    for (int kt = 0; kt < ntiles; kt++) {
        const int kbase = kt * 64;
        cp_wait0();         // K/V tile kt landed
        __syncthreads();    // visible to all warps; all warps done with kt-1
        if (kt + 1 < ntiles)
            stage_kv((kt + 1) * 64, (kt + 1) & 1);   // overlaps compute of kt

        const uint32_t kb = kfb + (uint32_t)(kt & 1) * kvstride;
        const uint32_t vb = vfb + (uint32_t)(kt & 1) * kvstride;

        // ---- S = Q @ K^T (16x64 per warp); K frags via ldmatrix.x4 ----
        float s_[8][4];
        #pragma unroll
        for (int nt = 0; nt < 8; nt++)
            #pragma unroll
            for (int i = 0; i < 4; i++) s_[nt][i] = 0.f;
        #pragma unroll
        for (int kc = 0; kc < 4; kc++) {
            #pragma unroll
            for (int np = 0; np < 4; np++) {
                uint32_t r0, r1, r2, r3;
                ldsm_x4(r0, r1, r2, r3,
                        kb + (uint32_t)(np * 16 * 72 + kc * 16) * 2);
                mma_f16(s_[2 * np],     Qa[kc], r0, r1);
                mma_f16(s_[2 * np + 1], Qa[kc], r2, r3);
            }
        }

        // ---- causal mask (tiles overlapping/above the diagonal) ----
        if (kbase + 63 > q0g) {
            #pragma unroll
            for (int nt = 0; nt < 8; nt++) {
                const int c0 = kbase + nt * 8 + 2 * t4;
                if (c0 > q0g)         s_[nt][0] = -1e30f;
                if (c0 + 1 > q0g)     s_[nt][1] = -1e30f;
                if (c0 > q0g + 8)     s_[nt][2] = -1e30f;
                if (c0 + 1 > q0g + 8) s_[nt][3] = -1e30f;
            }
        }

        // ---- online softmax (base-2) ----
        float mx0 = -1e30f, mx1 = -1e30f;
        #pragma unroll
        for (int nt = 0; nt < 8; nt++) {
            mx0 = fmaxf(mx0, fmaxf(s_[nt][0], s_[nt][1]));
            mx1 = fmaxf(mx1, fmaxf(s_[nt][2], s_[nt][3]));
        }
        mx0 = fmaxf(mx0, __shfl_xor_sync(0xffffffff, mx0, 1));
        mx0 = fmaxf(mx0, __shfl_xor_sync(0xffffffff, mx0, 2));
        mx1 = fmaxf(mx1, __shfl_xor_sync(0xffffffff, mx1, 1));
        mx1 = fmaxf(mx1, __shfl_xor_sync(0xffffffff, mx1, 2));
        const float nm0 = fmaxf(m0, mx0), nm1 = fmaxf(m1, mx1);
        const float sc0 = fast_exp2(m0 - nm0), sc1 = fast_exp2(m1 - nm1);
        m0 = nm0; m1 = nm1;

        // P = exp2(s - m) computed in packed fp16 (ready as mma A operand)
        const uint32_t mh0 = pack_h2(m0, m0);
        const uint32_t mh1 = pack_h2(m1, m1);
        uint32_t P0[8], P1[8];
        #pragma unroll
        for (int nt = 0; nt < 8; nt++) {
            P0[nt] = hex2_h2(hsub2(pack_h2(s_[nt][0], s_[nt][1]), mh0));
            P1[nt] = hex2_h2(hsub2(pack_h2(s_[nt][2], s_[nt][3]), mh1));
        }

        la[0] *= sc0; la[1] *= sc0; la[2] *= sc1; la[3] *= sc1;
        #pragma unroll
        for (int nt = 0; nt < 8; nt++) {
            o[nt][0] *= sc0; o[nt][1] *= sc0;
            o[nt][2] *= sc1; o[nt][3] *= sc1;
        }

        // ---- O += P @ V ; l += P @ ones (constant B fragment) ----
        #pragma unroll
        for (int kc = 0; kc < 4; kc++) {
            uint32_t pa[4];
            pa[0] = P0[2 * kc];
            pa[1] = P1[2 * kc];
            pa[2] = P0[2 * kc + 1];
            pa[3] = P1[2 * kc + 1];
            #pragma unroll
            for (int p = 0; p < 4; p++) {
                uint32_t v0, v1, v2, v3;
                ldsm_x4_trans(v0, v1, v2, v3,
                              vb + (uint32_t)(kc * 16 * 72 + p * 16) * 2);
                mma_f16(o[2 * p],     pa, v0, v1);
                mma_f16(o[2 * p + 1], pa, v2, v3);
            }
            mma_f16(la, pa, onesb, onesb);
        }
    }

    // ---- broadcast l (column 0 lives in t4==0 lanes), normalize, store ----
    const int qlead = lane & 28;       // lane of t4==0 in this quad
    const float l0 = __shfl_sync(0xffffffff, la[0], qlead);
    const float l1 = __shfl_sync(0xffffffff, la[2], qlead);
    const float inv0 = 1.f / l0, inv1 = 1.f / l1;
    const size_t row0 = (size_t)(b * T_ + qtile * 128 + w * 16 + g);
    const size_t row1 = row0 + 8;
    #pragma unroll
    for (int nt = 0; nt < 8; nt++) {
        const int col = h * D_ + nt * 8 + 2 * t4;
        uint32_t v0 = pack_h2(o[nt][0] * inv0, o[nt][1] * inv0);
        uint32_t v1 = pack_h2(o[nt][2] * inv1, o[nt][3] * inv1);
        *reinterpret_cast<uint32_t*>(&outh[row0 * C_ + col]) = v0;
        *reinterpret_cast<uint32_t*>(&outh[row1 * C_ + col]) = v1;
    }
}

// ---------------------------------------------------------------------------
// Launch
// ---------------------------------------------------------------------------
extern "C" void kernel_launch(void* const* d_in, const int* in_sizes, int n_in,
                              void* d_out, int out_size)
{
    const float* x    = (const float*)d_in[0];
    const float* Wqkv = (const float*)d_in[1];
    const float* bqkv = (const float*)d_in[2];
    const float* Wout = (const float*)d_in[3];
    const float* bout = (const float*)d_in[4];
    float* out = (float*)d_out;

    __half *xh, *wqkvh, *wouth, *qkvh, *attnh;
    cudaGetSymbolAddress((void**)&xh,    g_xh);
    cudaGetSymbolAddress((void**)&wqkvh, g_wqkvh);
    cudaGetSymbolAddress((void**)&wouth, g_wouth);
    cudaGetSymbolAddress((void**)&qkvh,  g_qkvh);
    cudaGetSymbolAddress((void**)&attnh, g_attnh);

    cudaFuncSetAttribute(attn_mma_kernel,
                         cudaFuncAttributeMaxDynamicSharedMemorySize, ATTN_SMEM);

    // 0) fp32 -> fp16 conversions
    {
        const int n0 = M_ * C_ / 4;
        const int n1 = C_ * N_QKV / 4;
        const int n2 = C_ * C_ / 4;
        cvt_f32_f16<<<(n0 + 255) / 256, 256>>>(x, xh, n0);
        cvt_f32_f16<<<(n1 + 255) / 256, 256>>>(Wqkv, wqkvh, n1);
        cvt_f32_f16<<<(n2 + 255) / 256, 256>>>(Wout, wouth, n2);
    }

    // 1) QKV projection (fp16 out, Q columns pre-scaled by QSCALE)
    {
        dim3 grid(N_QKV / 128, M_ / 128);
        gemm_h_kernel<true><<<grid, 256>>>(xh, wqkvh, bqkv, qkvh,
                                           M_, N_QKV, C_, C_, (float)QSCALE);
    }
    // 2) Causal attention (flash, fp16 tensor cores, fp16 out)
    {
        dim3 grid(T_ / 128, B_ * H_);
        attn_mma_kernel<<<grid, 256, ATTN_SMEM>>>(qkvh, attnh);
    }
    // 3) Output projection (fp32 out)
    {
        dim3 grid(C_ / 128, M_ / 128);
        gemm_h_kernel<false><<<grid, 256>>>(attnh, wouth, bout, out,
                                            M_, C_, C_, 0, 1.f);
    }
}

// round 15
// speedup vs baseline: 3.4545x; 1.0069x over previous
#include <cuda_runtime.h>
#include <cuda_fp16.h>
#include <cstdint>
#include <cstddef>

#define B_ 2
#define T_ 4096
#define C_ 768
#define H_ 12
#define D_ 64
#define M_ (B_*T_)          // 8192
#define N_QKV (3*C_)        // 2304
// softmax scale folded with log2(e) so we can use ex2
#define QSCALE (0.125f * 1.4426950408889634f)

// fp16 scratch (allocation-free requirement -> __device__ globals)
__device__ __half g_xh[(size_t)M_ * C_];
__device__ __half g_wqkvh[(size_t)C_ * N_QKV];
__device__ __half g_wouth[(size_t)C_ * C_];
__device__ __half g_qkvh[(size_t)M_ * N_QKV];   // Q part pre-scaled by QSCALE
__device__ __half g_attnh[(size_t)M_ * C_];

// ---------------------------------------------------------------------------
// Helpers
// ---------------------------------------------------------------------------
__device__ __forceinline__ void mma_f16(float* c, const uint32_t* a,
                                        uint32_t b0, uint32_t b1) {
    asm volatile(
        "mma.sync.aligned.m16n8k16.row.col.f32.f16.f16.f32 "
        "{%0,%1,%2,%3},{%4,%5,%6,%7},{%8,%9},{%0,%1,%2,%3};"
        : "+f"(c[0]), "+f"(c[1]), "+f"(c[2]), "+f"(c[3])
        : "r"(a[0]), "r"(a[1]), "r"(a[2]), "r"(a[3]), "r"(b0), "r"(b1));
}

__device__ __forceinline__ void ldsm_x4(uint32_t& r0, uint32_t& r1,
                                        uint32_t& r2, uint32_t& r3,
                                        uint32_t addr) {
    asm volatile(
        "ldmatrix.sync.aligned.m8n8.x4.shared.b16 {%0,%1,%2,%3}, [%4];"
        : "=r"(r0), "=r"(r1), "=r"(r2), "=r"(r3) : "r"(addr));
}

__device__ __forceinline__ void ldsm_x4_trans(uint32_t& r0, uint32_t& r1,
                                              uint32_t& r2, uint32_t& r3,
                                              uint32_t addr) {
    asm volatile(
        "ldmatrix.sync.aligned.m8n8.x4.trans.shared.b16 {%0,%1,%2,%3}, [%4];"
        : "=r"(r0), "=r"(r1), "=r"(r2), "=r"(r3) : "r"(addr));
}

__device__ __forceinline__ uint32_t pack_h2(float lo, float hi) {
    __half2 h = __floats2half2_rn(lo, hi);
    return *reinterpret_cast<uint32_t*>(&h);
}

__device__ __forceinline__ float fast_exp2(float x) {
    float r;
    asm("ex2.approx.ftz.f32 %0, %1;" : "=f"(r) : "f"(x));
    return r;
}

// packed fp16 helpers (softmax fast path)
__device__ __forceinline__ uint32_t hsub2(uint32_t a, uint32_t b) {
    uint32_t r;
    asm("sub.f16x2 %0, %1, %2;" : "=r"(r) : "r"(a), "r"(b));
    return r;
}
__device__ __forceinline__ uint32_t hex2_h2(uint32_t x) {
    uint32_t r;
    asm("ex2.approx.f16x2 %0, %1;" : "=r"(r) : "r"(x));
    return r;
}

__device__ __forceinline__ uint32_t smem_u32(const void* p) {
    return (uint32_t)__cvta_generic_to_shared(p);
}
// L1-preserving async copy (NOT .cg — the round-4 lesson)
__device__ __forceinline__ void cp_async16_ca(uint32_t dst, const void* src) {
    asm volatile("cp.async.ca.shared.global [%0], [%1], 16;"
                 :: "r"(dst), "l"(src));
}
__device__ __forceinline__ void cp_commit() {
    asm volatile("cp.async.commit_group;");
}
__device__ __forceinline__ void cp_wait0() {
    asm volatile("cp.async.wait_group 0;");
}

// ---------------------------------------------------------------------------
// Fused fp32 -> fp16 conversion for all three tensors (one launch)
// ---------------------------------------------------------------------------
__global__ void __launch_bounds__(256)
cvt3_f32_f16(const float* __restrict__ a, __half* __restrict__ oa, int na4,
             const float* __restrict__ b, __half* __restrict__ ob, int nb4,
             const float* __restrict__ c, __half* __restrict__ oc, int nc4)
{
    int i = blockIdx.x * blockDim.x + threadIdx.x;
    const float* in;
    __half* out;
    int off;
    if (i < na4)                  { in = a; out = oa; off = i; }
    else if (i < na4 + nb4)       { in = b; out = ob; off = i - na4; }
    else if (i < na4 + nb4 + nc4) { in = c; out = oc; off = i - na4 - nb4; }
    else return;

    float4 v = reinterpret_cast<const float4*>(in)[off];
    __half2 h0 = __floats2half2_rn(v.x, v.y);
    __half2 h1 = __floats2half2_rn(v.z, v.w);
    uint2 u;
    u.x = *reinterpret_cast<uint32_t*>(&h0);
    u.y = *reinterpret_cast<uint32_t*>(&h1);
    reinterpret_cast<uint2*>(out)[off] = u;
}

// ---------------------------------------------------------------------------
// Wide-tile fp16 GEMM (QKV): C[M,N] = A[M,K] @ B[K,N] + bias, fp16 out with
// Q-column pre-scale. CTA tile 256x128, BK=32, 8 warps, warp tile 64x64.
// 2-stage double buffer + register prefetch. ~200 regs -> 1 CTA/SM.
// ldsm bytes/MAC drop 33%, staging bytes/MAC drop 2x vs the 128-tile kernel.
// ---------------------------------------------------------------------------
__global__ void __launch_bounds__(256)
gemm_h256_kernel(const __half* __restrict__ A, const __half* __restrict__ B,
                 const float* __restrict__ bias, __half* __restrict__ Cout,
                 int M, int N, int K, int qcols, float qsc)
{
    __shared__ __half As[2][256][40];   // 40960 B
    __shared__ __half Bs[2][32][136];   // 17408 B

    const int tid = threadIdx.x;
    const int wid = tid >> 5;
    const int lane = tid & 31;
    const int g = lane >> 2;
    const int t4 = lane & 3;
    const int wm = wid >> 1;            // 0..3 -> m offset wm*64
    const int wn = wid & 1;             // 0..1 -> n offset wn*64
    const int bx = blockIdx.x, by = blockIdx.y;
    const int mrow = lane & 7;
    const int mid  = lane >> 3;

    const uint32_t abase = smem_u32(
        &As[0][wm * 64 + (mid & 1) * 8 + mrow][(mid >> 1) * 8]);
    const uint32_t bbase = smem_u32(
        &Bs[0][(mid & 1) * 8 + mrow][wn * 64 + (mid >> 1) * 8]);
    const uint32_t a_ststride = 256 * 40 * 2;
    const uint32_t b_ststride = 32 * 136 * 2;

    // staging coords: A 4 uint4/thread (rows ar0+64i), B 2 uint4/thread
    const int ar0 = tid >> 2;           // 0..63
    const int ach = tid & 3;            // uint4 chunk within row
    const int br = tid >> 4;            // rows br, br+16
    const int bch = tid & 15;

    const __half* aG = A + (size_t)(by * 256 + ar0) * K + ach * 8;
    const __half* bG = B + (size_t)br * N + bx * 128 + bch * 8;
    const size_t aRow64 = (size_t)64 * K;
    const size_t bRow16 = (size_t)16 * N;

    uint4 pa[4], pb0, pb1;
    auto ldg_slab = [&](int k0) {
        #pragma unroll
        for (int i = 0; i < 4; i++)
            pa[i] = *reinterpret_cast<const uint4*>(aG + (size_t)i * aRow64 + k0);
        pb0 = *reinterpret_cast<const uint4*>(bG + (size_t)k0 * N);
        pb1 = *reinterpret_cast<const uint4*>(bG + (size_t)k0 * N + bRow16);
    };
    auto sts_slab = [&](int st) {
        #pragma unroll
        for (int i = 0; i < 4; i++)
            *reinterpret_cast<uint4*>(&As[st][ar0 + i * 64][ach * 8]) = pa[i];
        *reinterpret_cast<uint4*>(&Bs[st][br][bch * 8])      = pb0;
        *reinterpret_cast<uint4*>(&Bs[st][br + 16][bch * 8]) = pb1;
    };

    float acc[4][8][4];
    #pragma unroll
    for (int mt = 0; mt < 4; mt++)
        #pragma unroll
        for (int nt = 0; nt < 8; nt++)
            #pragma unroll
            for (int i = 0; i < 4; i++) acc[mt][nt][i] = 0.f;

    const int steps = K >> 5;
    ldg_slab(0);
    sts_slab(0);
    __syncthreads();

    for (int s = 0; s < steps; s++) {
        if (s + 1 < steps) ldg_slab((s + 1) << 5);

        const uint32_t ab = abase + (uint32_t)(s & 1) * a_ststride;
        const uint32_t bb = bbase + (uint32_t)(s & 1) * b_ststride;
        #pragma unroll
        for (int kk = 0; kk < 32; kk += 16) {
            uint32_t afr[4][4], bfr[8][2];
            #pragma unroll
            for (int mt = 0; mt < 4; mt++)
                ldsm_x4(afr[mt][0], afr[mt][1], afr[mt][2], afr[mt][3],
                        ab + (uint32_t)(mt * 16 * 40 + kk) * 2);
            #pragma unroll
            for (int p = 0; p < 4; p++) {
                uint32_t r0, r1, r2, r3;
                ldsm_x4_trans(r0, r1, r2, r3,
                              bb + (uint32_t)(kk * 136 + p * 16) * 2);
                bfr[2 * p][0] = r0; bfr[2 * p][1] = r1;
                bfr[2 * p + 1][0] = r2; bfr[2 * p + 1][1] = r3;
            }
            #pragma unroll
            for (int mt = 0; mt < 4; mt++)
                #pragma unroll
                for (int nt = 0; nt < 8; nt++)
                    mma_f16(acc[mt][nt], afr[mt], bfr[nt][0], bfr[nt][1]);
        }

        if (s + 1 < steps) sts_slab((s + 1) & 1);
        __syncthreads();
    }

    // ---- epilogue (fp16 out, Q pre-scale on columns < qcols) ----
    const float osc = (bx * 128 < qcols) ? qsc : 1.f;
    #pragma unroll
    for (int nt = 0; nt < 8; nt++) {
        const int col = bx * 128 + wn * 64 + nt * 8 + 2 * t4;
        const float b0 = bias[col], b1 = bias[col + 1];
        #pragma unroll
        for (int mt = 0; mt < 4; mt++) {
            const int row = by * 256 + wm * 64 + mt * 16 + g;
            uint32_t v0 = pack_h2((acc[mt][nt][0] + b0) * osc,
                                  (acc[mt][nt][1] + b1) * osc);
            uint32_t v1 = pack_h2((acc[mt][nt][2] + b0) * osc,
                                  (acc[mt][nt][3] + b1) * osc);
            *reinterpret_cast<uint32_t*>(&Cout[(size_t)row * N + col]) = v0;
            *reinterpret_cast<uint32_t*>(&Cout[(size_t)(row + 8) * N + col]) = v1;
        }
    }
}

// ---------------------------------------------------------------------------
// fp16-in tensor-core GEMM with bias (round-9 proven version, out-proj):
// BM=BN=128, BK=32, 256 threads (8 warps), warp tile 64x32 (m16n8k16).
// 2-stage smem double buffer + register prefetch, 2 CTAs/SM. fp32 out.
// ---------------------------------------------------------------------------
__global__ void __launch_bounds__(256, 2)
gemm_h_kernel(const __half* __restrict__ A, const __half* __restrict__ B,
              const float* __restrict__ bias, float* __restrict__ Cout,
              int M, int N, int K)
{
    __shared__ __half As[2][128][40];   // 20480 B
    __shared__ __half Bs[2][32][136];   // 17408 B

    const int tid = threadIdx.x;
    const int wid = tid >> 5;
    const int lane = tid & 31;
    const int g = lane >> 2;
    const int t4 = lane & 3;
    const int wm = wid >> 2;
    const int wn = wid & 3;
    const int bx = blockIdx.x, by = blockIdx.y;
    const int mrow = lane & 7;
    const int mid  = lane >> 3;

    const uint32_t abase = smem_u32(
        &As[0][wm * 64 + (mid & 1) * 8 + mrow][(mid >> 1) * 8]);
    const uint32_t bbase = smem_u32(
        &Bs[0][(mid & 1) * 8 + mrow][wn * 32 + (mid >> 1) * 8]);
    const uint32_t a_ststride = 128 * 40 * 2;
    const uint32_t b_ststride = 32 * 136 * 2;

    const int ar = tid >> 2;            // rows ar, ar+64
    const int ach = tid & 3;
    const int br = tid >> 4;            // rows br, br+16
    const int bch = tid & 15;

    const __half* aG = A + (size_t)(by * 128 + ar) * K + ach * 8;
    const __half* bG = B + (size_t)br * N + bx * 128 + bch * 8;
    const size_t aRow64 = (size_t)64 * K;
    const size_t bRow16 = (size_t)16 * N;

    uint4 pa0, pa1, pb0, pb1;
    auto ldg_slab = [&](int k0) {
        pa0 = *reinterpret_cast<const uint4*>(aG + k0);
        pa1 = *reinterpret_cast<const uint4*>(aG + aRow64 + k0);
        pb0 = *reinterpret_cast<const uint4*>(bG + (size_t)k0 * N);
        pb1 = *reinterpret_cast<const uint4*>(bG + (size_t)k0 * N + bRow16);
    };
    auto sts_slab = [&](int st) {
        *reinterpret_cast<uint4*>(&As[st][ar][ach * 8])      = pa0;
        *reinterpret_cast<uint4*>(&As[st][ar + 64][ach * 8]) = pa1;
        *reinterpret_cast<uint4*>(&Bs[st][br][bch * 8])      = pb0;
        *reinterpret_cast<uint4*>(&Bs[st][br + 16][bch * 8]) = pb1;
    };

    float acc[4][4][4];
    #pragma unroll
    for (int mt = 0; mt < 4; mt++)
        #pragma unroll
        for (int nt = 0; nt < 4; nt++)
            #pragma unroll
            for (int i = 0; i < 4; i++) acc[mt][nt][i] = 0.f;

    const int steps = K >> 5;
    ldg_slab(0);
    sts_slab(0);
    __syncthreads();

    for (int s = 0; s < steps; s++) {
        if (s + 1 < steps) ldg_slab((s + 1) << 5);

        const uint32_t ab = abase + (uint32_t)(s & 1) * a_ststride;
        const uint32_t bb = bbase + (uint32_t)(s & 1) * b_ststride;
        #pragma unroll
        for (int kk = 0; kk < 32; kk += 16) {
            uint32_t afr[4][4], bfr[4][2];
            #pragma unroll
            for (int mt = 0; mt < 4; mt++)
                ldsm_x4(afr[mt][0], afr[mt][1], afr[mt][2], afr[mt][3],
                        ab + (uint32_t)(mt * 16 * 40 + kk) * 2);
            #pragma unroll
            for (int p = 0; p < 2; p++) {
                uint32_t r0, r1, r2, r3;
                ldsm_x4_trans(r0, r1, r2, r3,
                              bb + (uint32_t)(kk * 136 + p * 16) * 2);
                bfr[2 * p][0] = r0; bfr[2 * p][1] = r1;
                bfr[2 * p + 1][0] = r2; bfr[2 * p + 1][1] = r3;
            }
            #pragma unroll
            for (int mt = 0; mt < 4; mt++)
                #pragma unroll
                for (int nt = 0; nt < 4; nt++)
                    mma_f16(acc[mt][nt], afr[mt], bfr[nt][0], bfr[nt][1]);
        }

        if (s + 1 < steps) sts_slab((s + 1) & 1);
        __syncthreads();
    }

    #pragma unroll
    for (int nt = 0; nt < 4; nt++) {
        const int col = bx * 128 + wn * 32 + nt * 8 + 2 * t4;
        const float b0 = bias[col], b1 = bias[col + 1];
        #pragma unroll
        for (int mt = 0; mt < 4; mt++) {
            const int row = by * 128 + wm * 64 + mt * 16 + g;
            float2 o0 = make_float2(acc[mt][nt][0] + b0, acc[mt][nt][1] + b1);
            float2 o1 = make_float2(acc[mt][nt][2] + b0, acc[mt][nt][3] + b1);
            *reinterpret_cast<float2*>(Cout + (size_t)row * N + col) = o0;
            *reinterpret_cast<float2*>(Cout + (size_t)(row + 8) * N + col) = o1;
        }
    }
}

// ---------------------------------------------------------------------------
// Flash attention (causal), fp16 end-to-end, cp.async.ca double-buffered K/V.
// grid = (T/128, B*H), 256 threads (8 warps). Br=128, Bc=64, D=64.
// Round-14 proven version (current best).
// ---------------------------------------------------------------------------
#define QH_HALFS (128 * 72)
#define KV_HALFS (64 * 72)
#define ATTN_SMEM ((QH_HALFS + 4 * KV_HALFS) * 2)

__global__ void __launch_bounds__(256)
attn_mma_kernel(const __half* __restrict__ qkvh, __half* __restrict__ outh)
{
    extern __shared__ __half smh[];
    __half* Qh = smh;                               // [128][72]
    __half* Kh = smh + QH_HALFS;                    // [2][64][72]
    __half* Vh = smh + QH_HALFS + 2 * KV_HALFS;     // [2][64][72]

    const int bh = blockIdx.y;
    const int b = bh / H_;
    const int h = bh % H_;
    const int qtile = gridDim.x - 1 - blockIdx.x;   // big tiles first
    const int tid = threadIdx.x;
    const int w = tid >> 5;
    const int lane = tid & 31;
    const int g = lane >> 2;
    const int t4 = lane & 3;
    const int mrow = lane & 7;
    const int mid  = lane >> 3;

    const uint32_t kfb = smem_u32(&Kh[((mid >> 1) * 8 + mrow) * 72 + (mid & 1) * 8]);
    const uint32_t vfb = smem_u32(&Vh[((mid & 1) * 8 + mrow) * 72 + (mid >> 1) * 8]);
    const uint32_t kvstride = KV_HALFS * 2;

    const uint32_t onesb = (g == 0) ? 0x3C003C00u : 0u;

    const int kvr = tid >> 3;
    const int kvch = tid & 7;
    const __half* kvG = qkvh + (size_t)(b * T_ + kvr) * N_QKV + h * D_ + kvch * 8;
    const size_t row32 = (size_t)32 * N_QKV;

    auto stage_kv = [&](int kbase, int st) {
        const __half* s0 = kvG + (size_t)kbase * N_QKV;
        const uint32_t kd = smem_u32(&Kh[st * KV_HALFS + kvr * 72 + kvch * 8]);
        const uint32_t vd = smem_u32(&Vh[st * KV_HALFS + kvr * 72 + kvch * 8]);
        const uint32_t roff = 32 * 72 * 2;
        cp_async16_ca(kd,        s0 + C_);
        cp_async16_ca(kd + roff, s0 + row32 + C_);
        cp_async16_ca(vd,        s0 + 2 * C_);
        cp_async16_ca(vd + roff, s0 + row32 + 2 * C_);
        cp_commit();
    };

    stage_kv(0, 0);
    #pragma unroll
    for (int i = 0; i < 4; i++) {
        const int c = tid + i * 256;
        const int r = c >> 3;
        const int ch = c & 7;
        *reinterpret_cast<uint4*>(&Qh[r * 72 + ch * 8]) =
            *reinterpret_cast<const uint4*>(
                qkvh + (size_t)(b * T_ + qtile * 128 + r) * N_QKV + h * D_ + ch * 8);
    }
    __syncthreads();

    uint32_t Qa[4][4];
    {
        const int row = w * 16;
        #pragma unroll
        for (int kc = 0; kc < 4; kc++) {
            const int k0 = kc * 16 + 2 * t4;
            Qa[kc][0] = *reinterpret_cast<const uint32_t*>(&Qh[(row + g) * 72 + k0]);
            Qa[kc][1] = *reinterpret_cast<const uint32_t*>(&Qh[(row + g + 8) * 72 + k0]);
            Qa[kc][2] = *reinterpret_cast<const uint32_t*>(&Qh[(row + g) * 72 + k0 + 8]);
            Qa[kc][3] = *reinterpret_cast<const uint32_t*>(&Qh[(row + g + 8) * 72 + k0 + 8]);
        }
    }

    float o[8][4];
    #pragma unroll
    for (int nt = 0; nt < 8; nt++)
        #pragma unroll
        for (int i = 0; i < 4; i++) o[nt][i] = 0.f;
    float la[4] = {0.f, 0.f, 0.f, 0.f};
    float m0 = -1e30f, m1 = -1e30f;

    const int q0g = qtile * 128 + w * 16 + g;
    const int ntiles = 2 * qtile + 2;

    for (int kt = 0; kt < ntiles; kt++) {
        const int kbase = kt * 64;
        cp_wait0();
        __syncthreads();
        if (kt + 1 < ntiles)
            stage_kv((kt + 1) * 64, (kt + 1) & 1);

        const uint32_t kb = kfb + (uint32_t)(kt & 1) * kvstride;
        const uint32_t vb = vfb + (uint32_t)(kt & 1) * kvstride;

        float s_[8][4];
        #pragma unroll
        for (int nt = 0; nt < 8; nt++)
            #pragma unroll
            for (int i = 0; i < 4; i++) s_[nt][i] = 0.f;
        #pragma unroll
        for (int kc = 0; kc < 4; kc++) {
            #pragma unroll
            for (int np = 0; np < 4; np++) {
                uint32_t r0, r1, r2, r3;
                ldsm_x4(r0, r1, r2, r3,
                        kb + (uint32_t)(np * 16 * 72 + kc * 16) * 2);
                mma_f16(s_[2 * np],     Qa[kc], r0, r1);
                mma_f16(s_[2 * np + 1], Qa[kc], r2, r3);
            }
        }

        if (kbase + 63 > q0g) {
            #pragma unroll
            for (int nt = 0; nt < 8; nt++) {
                const int c0 = kbase + nt * 8 + 2 * t4;
                if (c0 > q0g)         s_[nt][0] = -1e30f;
                if (c0 + 1 > q0g)     s_[nt][1] = -1e30f;
                if (c0 > q0g + 8)     s_[nt][2] = -1e30f;
                if (c0 + 1 > q0g + 8) s_[nt][3] = -1e30f;
            }
        }

        float mx0 = -1e30f, mx1 = -1e30f;
        #pragma unroll
        for (int nt = 0; nt < 8; nt++) {
            mx0 = fmaxf(mx0, fmaxf(s_[nt][0], s_[nt][1]));
            mx1 = fmaxf(mx1, fmaxf(s_[nt][2], s_[nt][3]));
        }
        mx0 = fmaxf(mx0, __shfl_xor_sync(0xffffffff, mx0, 1));
        mx0 = fmaxf(mx0, __shfl_xor_sync(0xffffffff, mx0, 2));
        mx1 = fmaxf(mx1, __shfl_xor_sync(0xffffffff, mx1, 1));
        mx1 = fmaxf(mx1, __shfl_xor_sync(0xffffffff, mx1, 2));
        const float nm0 = fmaxf(m0, mx0), nm1 = fmaxf(m1, mx1);
        const float sc0 = fast_exp2(m0 - nm0), sc1 = fast_exp2(m1 - nm1);
        m0 = nm0; m1 = nm1;

        const uint32_t mh0 = pack_h2(m0, m0);
        const uint32_t mh1 = pack_h2(m1, m1);
        uint32_t P0[8], P1[8];
        #pragma unroll
        for (int nt = 0; nt < 8; nt++) {
            P0[nt] = hex2_h2(hsub2(pack_h2(s_[nt][0], s_[nt][1]), mh0));
            P1[nt] = hex2_h2(hsub2(pack_h2(s_[nt][2], s_[nt][3]), mh1));
        }

        la[0] *= sc0; la[1] *= sc0; la[2] *= sc1; la[3] *= sc1;
        #pragma unroll
        for (int nt = 0; nt < 8; nt++) {
            o[nt][0] *= sc0; o[nt][1] *= sc0;
            o[nt][2] *= sc1; o[nt][3] *= sc1;
        }

        #pragma unroll
        for (int kc = 0; kc < 4; kc++) {
            uint32_t pa[4];
            pa[0] = P0[2 * kc];
            pa[1] = P1[2 * kc];
            pa[2] = P0[2 * kc + 1];
            pa[3] = P1[2 * kc + 1];
            #pragma unroll
            for (int p = 0; p < 4; p++) {
                uint32_t v0, v1, v2, v3;
                ldsm_x4_trans(v0, v1, v2, v3,
                              vb + (uint32_t)(kc * 16 * 72 + p * 16) * 2);
                mma_f16(o[2 * p],     pa, v0, v1);
                mma_f16(o[2 * p + 1], pa, v2, v3);
            }
            mma_f16(la, pa, onesb, onesb);
        }
    }

    const int qlead = lane & 28;
    const float l0 = __shfl_sync(0xffffffff, la[0], qlead);
    const float l1 = __shfl_sync(0xffffffff, la[2], qlead);
    const float inv0 = 1.f / l0, inv1 = 1.f / l1;
    const size_t row0 = (size_t)(b * T_ + qtile * 128 + w * 16 + g);
    const size_t row1 = row0 + 8;
    #pragma unroll
    for (int nt = 0; nt < 8; nt++) {
        const int col = h * D_ + nt * 8 + 2 * t4;
        uint32_t v0 = pack_h2(o[nt][0] * inv0, o[nt][1] * inv0);
        uint32_t v1 = pack_h2(o[nt][2] * inv1, o[nt][3] * inv1);
        *reinterpret_cast<uint32_t*>(&outh[row0 * C_ + col]) = v0;
        *reinterpret_cast<uint32_t*>(&outh[row1 * C_ + col]) = v1;
    }
}

// ---------------------------------------------------------------------------
// Launch
// ---------------------------------------------------------------------------
extern "C" void kernel_launch(void* const* d_in, const int* in_sizes, int n_in,
                              void* d_out, int out_size)
{
    const float* x    = (const float*)d_in[0];
    const float* Wqkv = (const float*)d_in[1];
    const float* bqkv = (const float*)d_in[2];
    const float* Wout = (const float*)d_in[3];
    const float* bout = (const float*)d_in[4];
    float* out = (float*)d_out;

    __half *xh, *wqkvh, *wouth, *qkvh, *attnh;
    cudaGetSymbolAddress((void**)&xh,    g_xh);
    cudaGetSymbolAddress((void**)&wqkvh, g_wqkvh);
    cudaGetSymbolAddress((void**)&wouth, g_wouth);
    cudaGetSymbolAddress((void**)&qkvh,  g_qkvh);
    cudaGetSymbolAddress((void**)&attnh, g_attnh);

    cudaFuncSetAttribute(attn_mma_kernel,
                         cudaFuncAttributeMaxDynamicSharedMemorySize, ATTN_SMEM);

    // 0) fp32 -> fp16 conversions (single fused launch)
    {
        const int n0 = M_ * C_ / 4;
        const int n1 = C_ * N_QKV / 4;
        const int n2 = C_ * C_ / 4;
        const int ntot = n0 + n1 + n2;
        cvt3_f32_f16<<<(ntot + 255) / 256, 256>>>(x, xh, n0,
                                                  Wqkv, wqkvh, n1,
                                                  Wout, wouth, n2);
    }

    // 1) QKV projection (wide-tile kernel; fp16 out, Q pre-scaled by QSCALE)
    {
        dim3 grid(N_QKV / 128, M_ / 256);
        gemm_h256_kernel<<<grid, 256>>>(xh, wqkvh, bqkv, qkvh,
                                        M_, N_QKV, C_, C_, (float)QSCALE);
    }
    // 2) Causal attention (flash, fp16 tensor cores, fp16 out)
    {
        dim3 grid(T_ / 128, B_ * H_);
        attn_mma_kernel<<<grid, 256, ATTN_SMEM>>>(qkvh, attnh);
    }
    // 3) Output projection (proven 128-tile kernel, fp32 out)
    {
        dim3 grid(C_ / 128, M_ / 128);
        gemm_h_kernel<<<grid, 256>>>(attnh, wouth, bout, out, M_, C_, C_);
    }
}